// round 2
// baseline (speedup 1.0000x reference)
#include <cuda_runtime.h>
#include <math.h>

// ---------------- problem constants ----------------
#define B_    2
#define NIN   4096
#define NOUT  484
#define D_    384
#define H_    12
#define HD_   32
#define QG    22
#define GW_   64
#define MOUT  (B_*NOUT)   // 968
#define MIN_  (B_*NIN)    // 8192
#define BH_   (B_*H_)     // 24
#define NROT_ 16
#define LNEPS 1e-5f
#define EPSV  1.1920929e-07f

#define XOUT_SZ  (MOUT*D_)                       // 371712
#define ATTN_SZ  ((size_t)BH_*NOUT*NIN)          // 47579136

// ---------------- scratch (device globals; no alloc allowed) ----------------
__device__ float g_wt[49*D_*D_];
__device__ float g_xo[MOUT*D_];
__device__ float g_xout[MOUT*D_];
__device__ float g_kv[MIN_*2*D_];
__device__ float g_k[BH_*NIN*HD_];
__device__ float g_v[BH_*NIN*HD_];
__device__ float g_qlin[MOUT*D_];
__device__ float g_q[BH_*NOUT*HD_];
__device__ float g_attn[(size_t)BH_*NOUT*NIN];   // fallback if out_size is small
__device__ float g_colinv[BH_*NIN];
__device__ float g_h1[MOUT*4*D_];

__device__ __forceinline__ float gelu_f(float x){
    return 0.5f * x * (1.0f + erff(x * 0.70710678118654752f));
}

// dst[khw][ci][co] = w[co][ci][kh][kw]
__global__ void wt_kernel(const float* __restrict__ w, float* __restrict__ dst){
    int idx = blockIdx.x*blockDim.x + threadIdx.x;
    if (idx >= 49*D_*D_) return;
    int co  = idx % D_;
    int ci  = (idx / D_) % D_;
    int khw = idx / (D_*D_);
    dst[idx] = w[((size_t)co*D_ + ci)*49 + khw];
}

__global__ void initbias_kernel(const float* __restrict__ b, float* __restrict__ o){
    int idx = blockIdx.x*blockDim.x + threadIdx.x;
    if (idx < MOUT*D_) o[idx] = b[idx % D_];
}

// ---------------- generic fp32 tiled GEMM: C = A(MxK) @ B(KxN) + bias, opt gelu ----
__global__ void gemm_kernel(const float* __restrict__ A, const float* __restrict__ Bm,
                            const float* __restrict__ bias, float* __restrict__ C,
                            int M, int N, int K, int act){
    __shared__ float  As[16][68];
    __shared__ float4 Bs[16][16];
    int tid = threadIdx.x;
    int tx = tid & 15, ty = tid >> 4;
    int m0 = blockIdx.y * 64, n0 = blockIdx.x * 64;
    float acc[4][4] = {};
    int lm = tid >> 2;
    int lk = (tid & 3) * 4;
    int am = m0 + lm;
    int bk = tid >> 4;
    int bn = n0 + (tid & 15) * 4;
    for (int k0 = 0; k0 < K; k0 += 16){
        float4 av = make_float4(0.f,0.f,0.f,0.f);
        if (am < M) av = *(const float4*)(A + (size_t)am*K + k0 + lk);
        As[lk  ][lm] = av.x; As[lk+1][lm] = av.y;
        As[lk+2][lm] = av.z; As[lk+3][lm] = av.w;
        Bs[bk][tid & 15] = *(const float4*)(Bm + (size_t)(k0+bk)*N + bn);
        __syncthreads();
        #pragma unroll
        for (int kk = 0; kk < 16; kk++){
            float a0 = As[kk][ty*4+0], a1 = As[kk][ty*4+1];
            float a2 = As[kk][ty*4+2], a3 = As[kk][ty*4+3];
            float4 b4 = Bs[kk][tx];
            acc[0][0]+=a0*b4.x; acc[0][1]+=a0*b4.y; acc[0][2]+=a0*b4.z; acc[0][3]+=a0*b4.w;
            acc[1][0]+=a1*b4.x; acc[1][1]+=a1*b4.y; acc[1][2]+=a1*b4.z; acc[1][3]+=a1*b4.w;
            acc[2][0]+=a2*b4.x; acc[2][1]+=a2*b4.y; acc[2][2]+=a2*b4.z; acc[2][3]+=a2*b4.w;
            acc[3][0]+=a3*b4.x; acc[3][1]+=a3*b4.y; acc[3][2]+=a3*b4.z; acc[3][3]+=a3*b4.w;
        }
        __syncthreads();
    }
    #pragma unroll
    for (int i = 0; i < 4; i++){
        int r = m0 + ty*4 + i;
        if (r >= M) break;
        #pragma unroll
        for (int j = 0; j < 4; j++){
            int c = n0 + tx*4 + j;
            float v = acc[i][j] + bias[c];
            if (act) v = gelu_f(v);
            C[(size_t)r*N + c] = v;
        }
    }
}

// ---------------- conv as implicit GEMM, K split over kh (grid.z = 7 slices) -------
__global__ void conv_kernel(const float* __restrict__ x, const float* __restrict__ wt,
                            float* __restrict__ C){
    __shared__ float  As[16][68];
    __shared__ float4 Bs[16][16];
    int tid = threadIdx.x;
    int tx = tid & 15, ty = tid >> 4;
    int m0 = blockIdx.y * 64, n0 = blockIdx.x * 64;
    int slice = blockIdx.z;
    float acc[4][4] = {};
    int lm = tid >> 2;
    int lk = (tid & 3) * 4;
    int am = m0 + lm;
    bool mok = am < MOUT;
    int bb = mok ? am / NOUT : 0;
    int rr = mok ? am % NOUT : 0;
    int oh = rr / QG, ow = rr % QG;
    int bkr = tid >> 4;
    int bnc = n0 + (tid & 15) * 4;
    for (int k0 = 0; k0 < 7*D_; k0 += 16){
        int khw = slice*7 + k0/D_;
        int kh = khw/7, kw = khw%7;
        int ih = oh*3 - 3 + kh, iw = ow*3 - 3 + kw;
        int cib = k0 % D_;
        float4 av = make_float4(0.f,0.f,0.f,0.f);
        if (mok && (unsigned)ih < 64u && (unsigned)iw < 64u)
            av = *(const float4*)(x + ((size_t)bb*NIN + ih*GW_ + iw)*D_ + cib + lk);
        As[lk  ][lm] = av.x; As[lk+1][lm] = av.y;
        As[lk+2][lm] = av.z; As[lk+3][lm] = av.w;
        Bs[bkr][tid & 15] = *(const float4*)(wt + ((size_t)khw*D_ + cib + bkr)*D_ + bnc);
        __syncthreads();
        #pragma unroll
        for (int kk = 0; kk < 16; kk++){
            float a0 = As[kk][ty*4+0], a1 = As[kk][ty*4+1];
            float a2 = As[kk][ty*4+2], a3 = As[kk][ty*4+3];
            float4 b4 = Bs[kk][tx];
            acc[0][0]+=a0*b4.x; acc[0][1]+=a0*b4.y; acc[0][2]+=a0*b4.z; acc[0][3]+=a0*b4.w;
            acc[1][0]+=a1*b4.x; acc[1][1]+=a1*b4.y; acc[1][2]+=a1*b4.z; acc[1][3]+=a1*b4.w;
            acc[2][0]+=a2*b4.x; acc[2][1]+=a2*b4.y; acc[2][2]+=a2*b4.z; acc[2][3]+=a2*b4.w;
            acc[3][0]+=a3*b4.x; acc[3][1]+=a3*b4.y; acc[3][2]+=a3*b4.z; acc[3][3]+=a3*b4.w;
        }
        __syncthreads();
    }
    #pragma unroll
    for (int i = 0; i < 4; i++){
        int r = m0 + ty*4 + i;
        if (r >= MOUT) break;
        #pragma unroll
        for (int j = 0; j < 4; j++){
            int c = n0 + tx*4 + j;
            atomicAdd(&C[(size_t)r*D_ + c], acc[i][j]);
        }
    }
}

// ---------------- layernorm over D=384, optional residual-add into out -------------
__global__ void ln_kernel(const float* __restrict__ X, const float* __restrict__ g,
                          const float* __restrict__ bt, float* __restrict__ out, int add){
    int row = blockIdx.x, tid = threadIdx.x;
    float x = X[(size_t)row*D_ + tid];
    __shared__ float ws[12];
    float s = x;
    #pragma unroll
    for (int o = 16; o > 0; o >>= 1) s += __shfl_down_sync(0xffffffffu, s, o);
    if ((tid & 31) == 0) ws[tid >> 5] = s;
    __syncthreads();
    if (tid == 0){ float t = 0.f; for (int i = 0; i < 12; i++) t += ws[i]; ws[0] = t; }
    __syncthreads();
    float mu = ws[0] * (1.0f/D_);
    __syncthreads();
    float d = x - mu;
    s = d*d;
    #pragma unroll
    for (int o = 16; o > 0; o >>= 1) s += __shfl_down_sync(0xffffffffu, s, o);
    if ((tid & 31) == 0) ws[tid >> 5] = s;
    __syncthreads();
    if (tid == 0){ float t = 0.f; for (int i = 0; i < 12; i++) t += ws[i]; ws[0] = t; }
    __syncthreads();
    float var = ws[0] * (1.0f/D_);
    float y = d * rsqrtf(var + LNEPS) * g[tid] + bt[tid];
    size_t o_ = (size_t)row*D_ + tid;
    out[o_] = add ? (out[o_] + y) : y;
}

// ---------------- rotary spatial embedding: (B,N,D[off:]) -> (B,H,N,HD) ------------
__global__ void rose_kernel(const float* __restrict__ src, int stride, int off,
                            float* __restrict__ dst, int N, int Gw, float sp0, float sp1,
                            const float* __restrict__ fr, const float* __restrict__ temp,
                            int doRot, int applyTemp){
    int idx = blockIdx.x*blockDim.x + threadIdx.x;
    int total = BH_ * N * HD_;
    if (idx >= total) return;
    int hd = idx & 31;
    int n  = (idx >> 5) % N;
    int bh = idx / (N*32);
    int h = bh % H_, b = bh / H_;
    const float* sp = src + ((size_t)b*N + n)*stride + off + h*HD_;
    float val;
    if (doRot && hd < NROT_){
        int m = hd >> 1, s = m >> 2, p = m & 3;
        float coord = (s == 0) ? (float)(n / Gw) * sp0 : (float)(n % Gw) * sp1;
        float ang = coord * fr[(h*2 + s)*4 + p];
        float cs, sn; sincosf(ang, &sn, &cs);
        float x1 = sp[2*m], x2 = sp[2*m+1];
        val = (hd & 1) ? (x1*sn + x2*cs) : (x1*cs - x2*sn);
    } else {
        val = sp[hd];
    }
    if (applyTemp) val *= temp[0];
    dst[idx] = val;
}

// ---------------- attention scores + row softmax ----------------------------------
// block = one (bh, qi) row of 4096 logits; 128 threads x 32 cols each
__global__ void attn_kernel(const float* __restrict__ q, const float* __restrict__ kmat,
                            float* __restrict__ attn){
    int qi = blockIdx.x, bh = blockIdx.y;
    int tid = threadIdx.x;
    __shared__ float qs[32];
    __shared__ float red[128];
    if (tid < 32) qs[tid] = q[((size_t)bh*NOUT + qi)*HD_ + tid];
    __syncthreads();
    const float* kb = kmat + (size_t)bh*NIN*HD_;
    float lg[32];
    #pragma unroll
    for (int j = 0; j < 32; j++){
        int col = j*128 + tid;
        const float4* kr = (const float4*)(kb + (size_t)col*HD_);
        float s = 0.f;
        #pragma unroll
        for (int d = 0; d < 8; d++){
            float4 kv = kr[d];
            s += kv.x*qs[4*d] + kv.y*qs[4*d+1] + kv.z*qs[4*d+2] + kv.w*qs[4*d+3];
        }
        lg[j] = s;
    }
    float mx = -3.4e38f;
    #pragma unroll
    for (int j = 0; j < 32; j++) mx = fmaxf(mx, lg[j]);
    red[tid] = mx; __syncthreads();
    for (int s2 = 64; s2 > 0; s2 >>= 1){
        if (tid < s2) red[tid] = fmaxf(red[tid], red[tid+s2]);
        __syncthreads();
    }
    mx = red[0];
    __syncthreads();
    float sum = 0.f;
    #pragma unroll
    for (int j = 0; j < 32; j++){ lg[j] = expf(lg[j] - mx); sum += lg[j]; }
    red[tid] = sum; __syncthreads();
    for (int s2 = 64; s2 > 0; s2 >>= 1){
        if (tid < s2) red[tid] += red[tid+s2];
        __syncthreads();
    }
    float inv = 1.f / red[0];
    float* arow = attn + ((size_t)bh*NOUT + qi)*NIN;
    #pragma unroll
    for (int j = 0; j < 32; j++) arow[j*128 + tid] = lg[j]*inv;
}

// colinv[bh][col] = 1 / (sum_q attn[bh][q][col] + EPS)
__global__ void colsum_kernel(const float* __restrict__ attn, float* __restrict__ colinv){
    int bh = blockIdx.x;
    int col = blockIdx.y*256 + threadIdx.x;
    const float* a = attn + (size_t)bh*NOUT*NIN + col;
    float s = 0.f;
    for (int qi = 0; qi < NOUT; qi++) s += a[(size_t)qi*NIN];
    colinv[bh*NIN + col] = 1.f / (s + EPSV);
}

__global__ void attnq_kernel(const float* __restrict__ attnk, const float* __restrict__ colinv,
                             float* __restrict__ out){
    size_t idx = (size_t)blockIdx.x*blockDim.x + threadIdx.x;
    if (idx >= ATTN_SZ) return;
    size_t row = idx >> 12;          // NIN = 4096
    int col = (int)(idx & 4095);
    int bh = (int)(row / NOUT);
    out[idx] = attnk[idx] * colinv[bh*NIN + col];
}

// upd[b,qi,h*32+hd] = sum_k attn_q * v ; one warp per (bh, qi), lane = hd
__global__ void upd_kernel(const float* __restrict__ attn, const float* __restrict__ colinv,
                           const float* __restrict__ v, float* __restrict__ out){
    int bh = blockIdx.x;
    int warp = threadIdx.x >> 5, lane = threadIdx.x & 31;
    int qi = blockIdx.y*4 + warp;
    const float* arow = attn + ((size_t)bh*NOUT + qi)*NIN;
    const float* ci = colinv + bh*NIN;
    const float* vb = v + (size_t)bh*NIN*HD_;
    float acc = 0.f;
    #pragma unroll 4
    for (int c = 0; c < NIN; c++){
        float a = arow[c] * ci[c];
        acc += a * vb[(size_t)c*HD_ + lane];
    }
    int b = bh / H_, h = bh % H_;
    out[((size_t)b*NOUT + qi)*D_ + h*HD_ + lane] = acc;
}

__global__ void copy_kernel(const float* __restrict__ src, float* __restrict__ dst, int n){
    int idx = blockIdx.x*blockDim.x + threadIdx.x;
    if (idx < n) dst[idx] = src[idx];
}

// ---------------- host orchestration ----------------------------------------------
extern "C" void kernel_launch(void* const* d_in, const int* in_sizes, int n_in,
                              void* d_out, int out_size){
    const float* x      = (const float*)d_in[0];
    const float* conv_w = (const float*)d_in[1];
    const float* conv_b = (const float*)d_in[2];
    const float* kv_w   = (const float*)d_in[3];
    const float* kv_b   = (const float*)d_in[4];
    const float* q_w    = (const float*)d_in[5];
    const float* q_b    = (const float*)d_in[6];
    const float* w1     = (const float*)d_in[7];
    const float* b1m    = (const float*)d_in[8];
    const float* w2     = (const float*)d_in[9];
    const float* b2m    = (const float*)d_in[10];
    const float* g1     = (const float*)d_in[11];
    const float* b1_    = (const float*)d_in[12];
    const float* g2     = (const float*)d_in[13];
    const float* b2_    = (const float*)d_in[14];
    const float* g3     = (const float*)d_in[15];
    const float* b3_    = (const float*)d_in[16];
    const float* temp   = (const float*)d_in[17];
    const float* freqs  = (const float*)d_in[18];

    float *wt, *xo, *xout, *kv, *k, *v, *qlin, *q, *attn_s, *colinv, *h1;
    cudaGetSymbolAddress((void**)&wt,     g_wt);
    cudaGetSymbolAddress((void**)&xo,     g_xo);
    cudaGetSymbolAddress((void**)&xout,   g_xout);
    cudaGetSymbolAddress((void**)&kv,     g_kv);
    cudaGetSymbolAddress((void**)&k,      g_k);
    cudaGetSymbolAddress((void**)&v,      g_v);
    cudaGetSymbolAddress((void**)&qlin,   g_qlin);
    cudaGetSymbolAddress((void**)&q,      g_q);
    cudaGetSymbolAddress((void**)&attn_s, g_attn);
    cudaGetSymbolAddress((void**)&colinv, g_colinv);
    cudaGetSymbolAddress((void**)&h1,     g_h1);

    float* out = (float*)d_out;
    bool full = (size_t)out_size >= (size_t)XOUT_SZ + 2*ATTN_SZ;
    float* out_attnq = full ? out + XOUT_SZ : attn_s;                 // fallback-safe
    float* out_attnk = full ? out + XOUT_SZ + ATTN_SZ : attn_s;

    // ---- prologue (loop-invariant) ----
    wt_kernel<<<(49*D_*D_ + 255)/256, 256>>>(conv_w, wt);
    initbias_kernel<<<(MOUT*D_ + 255)/256, 256>>>(conv_b, xo);
    conv_kernel<<<dim3(D_/64, (MOUT+63)/64, 7), 256>>>(x, wt, xo);
    ln_kernel<<<MOUT, D_>>>(xo, g1, b1_, xout, 0);
    gemm_kernel<<<dim3(2*D_/64, MIN_/64), 256>>>(x, kv_w, kv_b, kv, MIN_, 2*D_, D_, 0);
    int totk = BH_*NIN*HD_;
    rose_kernel<<<(totk+255)/256, 256>>>(kv, 2*D_, 0,  k, NIN, GW_, 1.f, 1.f, freqs, temp, 1, 1);
    rose_kernel<<<(totk+255)/256, 256>>>(kv, 2*D_, D_, v, NIN, GW_, 1.f, 1.f, freqs, temp, 0, 0);

    int totq = BH_*NOUT*HD_;
    for (int it = 0; it < 3; it++){
        gemm_kernel<<<dim3(D_/64, (MOUT+63)/64), 256>>>(xout, q_w, q_b, qlin, MOUT, D_, D_, 0);
        rose_kernel<<<(totq+255)/256, 256>>>(qlin, D_, 0, q, NOUT, QG, 3.f, 3.f, freqs, temp, 1, 0);

        float* attnT = full ? out_attnk : attn_s;   // last write wins => iter 2 values remain
        attn_kernel<<<dim3(NOUT, BH_), 128>>>(q, k, attnT);
        colsum_kernel<<<dim3(BH_, NIN/256), 256>>>(attnT, colinv);
        if (it == 2 && full)
            attnq_kernel<<<(int)((ATTN_SZ + 255)/256), 256>>>(attnT, colinv, out_attnq);
        upd_kernel<<<dim3(BH_, NOUT/4), 128>>>(attnT, colinv, v, xo);
        ln_kernel<<<MOUT, D_>>>(xo, g2, b2_, xout, 1);

        gemm_kernel<<<dim3(4*D_/64, (MOUT+63)/64), 256>>>(xout, w1, b1m, h1, MOUT, 4*D_, D_, 1);
        gemm_kernel<<<dim3(D_/64, (MOUT+63)/64), 256>>>(h1, w2, b2m, xo, MOUT, D_, 4*D_, 0);
        ln_kernel<<<MOUT, D_>>>(xo, g3, b3_, xout, 1);
    }
    copy_kernel<<<(XOUT_SZ + 255)/256, 256>>>(xout, out, XOUT_SZ);
}

// round 3
// speedup vs baseline: 3.0463x; 3.0463x over previous
#include <cuda_runtime.h>
#include <math.h>

// ---------------- problem constants ----------------
#define B_    2
#define NIN   4096
#define NOUT  484
#define D_    384
#define H_    12
#define HD_   32
#define QG    22
#define GW_   64
#define MOUT  (B_*NOUT)   // 968
#define MIN_  (B_*NIN)    // 8192
#define BH_   (B_*H_)     // 24
#define NROT_ 16
#define LNEPS 1e-5f
#define EPSV  1.1920929e-07f

#define XOUT_SZ  (MOUT*D_)                       // 371712
#define ATTN_SZ  ((size_t)BH_*NOUT*NIN)          // 47579136

// ---------------- scratch (device globals; no alloc allowed) ----------------
__device__ float g_wt[49*D_*D_];
__device__ float g_xo[MOUT*D_];
__device__ float g_xout[MOUT*D_];
__device__ float g_kv[MIN_*2*D_];
__device__ float g_k[BH_*NIN*HD_];
__device__ float g_v[BH_*NIN*HD_];
__device__ float g_qlin[MOUT*D_];
__device__ float g_q[BH_*NOUT*HD_];
__device__ float g_attn[(size_t)BH_*NOUT*NIN];   // fallback if out_size is small
__device__ float g_rowsum[BH_*NOUT];
__device__ float g_colinv[BH_*NIN];
__device__ float g_h1[MOUT*4*D_];

__device__ __forceinline__ float gelu_f(float x){
    return 0.5f * x * (1.0f + erff(x * 0.70710678118654752f));
}

// dst[khw][ci][co] = w[co][ci][kh][kw]
__global__ void wt_kernel(const float* __restrict__ w, float* __restrict__ dst){
    int idx = blockIdx.x*blockDim.x + threadIdx.x;
    if (idx >= 49*D_*D_) return;
    int co  = idx % D_;
    int ci  = (idx / D_) % D_;
    int khw = idx / (D_*D_);
    dst[idx] = w[((size_t)co*D_ + ci)*49 + khw];
}

__global__ void initbias_kernel(const float* __restrict__ b, float* __restrict__ o){
    int idx = blockIdx.x*blockDim.x + threadIdx.x;
    if (idx < MOUT*D_) o[idx] = b[idx % D_];
}

__global__ void zero2_kernel(float* __restrict__ a, int na, float* __restrict__ b, int nb){
    int i = blockIdx.x*blockDim.x + threadIdx.x;
    if (i < na) a[i] = 0.f;
    if (i < nb) b[i] = 0.f;
}

// ======== 128x64 tiled fp32 GEMM: C = A(MxK) @ B(KxN) + bias, opt gelu ========
// 256 threads; thread computes 8 rows x 4 cols. 32 FMA : 3 LDS.128 per k-step.
__global__ void gemm128_kernel(const float* __restrict__ A, const float* __restrict__ Bm,
                               const float* __restrict__ bias, float* __restrict__ C,
                               int M, int N, int K, int act){
    __shared__ float  As[16][132];
    __shared__ float4 Bs[16][16];
    int tid = threadIdx.x;
    int tx = tid & 15;          // 4 cols each -> 64
    int ty = tid >> 4;          // 8 rows each -> 128
    int m0 = blockIdx.y * 128, n0 = blockIdx.x * 64;
    float acc[8][4] = {};
    int la_m  = tid & 127;
    int la_kg = (tid >> 7) * 8;     // 0 or 8
    int lb_k  = tid >> 4;
    int lb_n  = tid & 15;
    int am = m0 + la_m;
    bool mok = am < M;
    for (int k0 = 0; k0 < K; k0 += 16){
        float4 a0 = make_float4(0.f,0.f,0.f,0.f), a1 = a0;
        if (mok){
            a0 = *(const float4*)(A + (size_t)am*K + k0 + la_kg);
            a1 = *(const float4*)(A + (size_t)am*K + k0 + la_kg + 4);
        }
        As[la_kg+0][la_m]=a0.x; As[la_kg+1][la_m]=a0.y; As[la_kg+2][la_m]=a0.z; As[la_kg+3][la_m]=a0.w;
        As[la_kg+4][la_m]=a1.x; As[la_kg+5][la_m]=a1.y; As[la_kg+6][la_m]=a1.z; As[la_kg+7][la_m]=a1.w;
        Bs[lb_k][lb_n] = *(const float4*)(Bm + (size_t)(k0+lb_k)*N + n0 + lb_n*4);
        __syncthreads();
        #pragma unroll
        for (int kk = 0; kk < 16; kk++){
            float4 b4  = Bs[kk][tx];
            float4 av0 = *(float4*)&As[kk][ty*8];
            float4 av1 = *(float4*)&As[kk][ty*8+4];
            acc[0][0]+=av0.x*b4.x; acc[0][1]+=av0.x*b4.y; acc[0][2]+=av0.x*b4.z; acc[0][3]+=av0.x*b4.w;
            acc[1][0]+=av0.y*b4.x; acc[1][1]+=av0.y*b4.y; acc[1][2]+=av0.y*b4.z; acc[1][3]+=av0.y*b4.w;
            acc[2][0]+=av0.z*b4.x; acc[2][1]+=av0.z*b4.y; acc[2][2]+=av0.z*b4.z; acc[2][3]+=av0.z*b4.w;
            acc[3][0]+=av0.w*b4.x; acc[3][1]+=av0.w*b4.y; acc[3][2]+=av0.w*b4.z; acc[3][3]+=av0.w*b4.w;
            acc[4][0]+=av1.x*b4.x; acc[4][1]+=av1.x*b4.y; acc[4][2]+=av1.x*b4.z; acc[4][3]+=av1.x*b4.w;
            acc[5][0]+=av1.y*b4.x; acc[5][1]+=av1.y*b4.y; acc[5][2]+=av1.y*b4.z; acc[5][3]+=av1.y*b4.w;
            acc[6][0]+=av1.z*b4.x; acc[6][1]+=av1.z*b4.y; acc[6][2]+=av1.z*b4.z; acc[6][3]+=av1.z*b4.w;
            acc[7][0]+=av1.w*b4.x; acc[7][1]+=av1.w*b4.y; acc[7][2]+=av1.w*b4.z; acc[7][3]+=av1.w*b4.w;
        }
        __syncthreads();
    }
    float4 bi = *(const float4*)(bias + n0 + tx*4);
    #pragma unroll
    for (int i = 0; i < 8; i++){
        int r = m0 + ty*8 + i;
        if (r >= M) break;
        float4 o;
        o.x = acc[i][0] + bi.x; o.y = acc[i][1] + bi.y;
        o.z = acc[i][2] + bi.z; o.w = acc[i][3] + bi.w;
        if (act){ o.x=gelu_f(o.x); o.y=gelu_f(o.y); o.z=gelu_f(o.z); o.w=gelu_f(o.w); }
        *(float4*)(C + (size_t)r*N + n0 + tx*4) = o;
    }
}

// ======== conv as implicit 128x64 GEMM, K split over kh (grid.z = 7 slices) ========
__global__ void conv128_kernel(const float* __restrict__ x, const float* __restrict__ wt,
                               float* __restrict__ C){
    __shared__ float  As[16][132];
    __shared__ float4 Bs[16][16];
    int tid = threadIdx.x;
    int tx = tid & 15, ty = tid >> 4;
    int m0 = blockIdx.y * 128, n0 = blockIdx.x * 64;
    int slice = blockIdx.z;
    float acc[8][4] = {};
    int la_m  = tid & 127;
    int la_kg = (tid >> 7) * 8;
    int lb_k  = tid >> 4;
    int lb_n  = tid & 15;
    int am = m0 + la_m;
    bool mok = am < MOUT;
    int bb = mok ? am / NOUT : 0;
    int rr = mok ? am % NOUT : 0;
    int oh = rr / QG, ow = rr % QG;
    for (int k0 = 0; k0 < 7*D_; k0 += 16){
        int khw = slice*7 + k0/D_;
        int kh = khw/7, kw = khw%7;
        int ih = oh*3 - 3 + kh, iw = ow*3 - 3 + kw;
        int cib = k0 % D_;
        float4 a0 = make_float4(0.f,0.f,0.f,0.f), a1 = a0;
        if (mok && (unsigned)ih < 64u && (unsigned)iw < 64u){
            const float* src = x + ((size_t)bb*NIN + ih*GW_ + iw)*D_ + cib + la_kg;
            a0 = *(const float4*)src;
            a1 = *(const float4*)(src + 4);
        }
        As[la_kg+0][la_m]=a0.x; As[la_kg+1][la_m]=a0.y; As[la_kg+2][la_m]=a0.z; As[la_kg+3][la_m]=a0.w;
        As[la_kg+4][la_m]=a1.x; As[la_kg+5][la_m]=a1.y; As[la_kg+6][la_m]=a1.z; As[la_kg+7][la_m]=a1.w;
        Bs[lb_k][lb_n] = *(const float4*)(wt + ((size_t)khw*D_ + cib + lb_k)*D_ + n0 + lb_n*4);
        __syncthreads();
        #pragma unroll
        for (int kk = 0; kk < 16; kk++){
            float4 b4  = Bs[kk][tx];
            float4 av0 = *(float4*)&As[kk][ty*8];
            float4 av1 = *(float4*)&As[kk][ty*8+4];
            acc[0][0]+=av0.x*b4.x; acc[0][1]+=av0.x*b4.y; acc[0][2]+=av0.x*b4.z; acc[0][3]+=av0.x*b4.w;
            acc[1][0]+=av0.y*b4.x; acc[1][1]+=av0.y*b4.y; acc[1][2]+=av0.y*b4.z; acc[1][3]+=av0.y*b4.w;
            acc[2][0]+=av0.z*b4.x; acc[2][1]+=av0.z*b4.y; acc[2][2]+=av0.z*b4.z; acc[2][3]+=av0.z*b4.w;
            acc[3][0]+=av0.w*b4.x; acc[3][1]+=av0.w*b4.y; acc[3][2]+=av0.w*b4.z; acc[3][3]+=av0.w*b4.w;
            acc[4][0]+=av1.x*b4.x; acc[4][1]+=av1.x*b4.y; acc[4][2]+=av1.x*b4.z; acc[4][3]+=av1.x*b4.w;
            acc[5][0]+=av1.y*b4.x; acc[5][1]+=av1.y*b4.y; acc[5][2]+=av1.y*b4.z; acc[5][3]+=av1.y*b4.w;
            acc[6][0]+=av1.z*b4.x; acc[6][1]+=av1.z*b4.y; acc[6][2]+=av1.z*b4.z; acc[6][3]+=av1.z*b4.w;
            acc[7][0]+=av1.w*b4.x; acc[7][1]+=av1.w*b4.y; acc[7][2]+=av1.w*b4.z; acc[7][3]+=av1.w*b4.w;
        }
        __syncthreads();
    }
    #pragma unroll
    for (int i = 0; i < 8; i++){
        int r = m0 + ty*8 + i;
        if (r >= MOUT) break;
        #pragma unroll
        for (int j = 0; j < 4; j++)
            atomicAdd(&C[(size_t)r*D_ + n0 + tx*4 + j], acc[i][j]);
    }
}

// ---------------- layernorm over D=384, optional residual-add into out -------------
__global__ void ln_kernel(const float* __restrict__ X, const float* __restrict__ g,
                          const float* __restrict__ bt, float* __restrict__ out, int add){
    int row = blockIdx.x, tid = threadIdx.x;
    float x = X[(size_t)row*D_ + tid];
    __shared__ float ws[12];
    float s = x;
    #pragma unroll
    for (int o = 16; o > 0; o >>= 1) s += __shfl_down_sync(0xffffffffu, s, o);
    if ((tid & 31) == 0) ws[tid >> 5] = s;
    __syncthreads();
    if (tid == 0){ float t = 0.f; for (int i = 0; i < 12; i++) t += ws[i]; ws[0] = t; }
    __syncthreads();
    float mu = ws[0] * (1.0f/D_);
    __syncthreads();
    float d = x - mu;
    s = d*d;
    #pragma unroll
    for (int o = 16; o > 0; o >>= 1) s += __shfl_down_sync(0xffffffffu, s, o);
    if ((tid & 31) == 0) ws[tid >> 5] = s;
    __syncthreads();
    if (tid == 0){ float t = 0.f; for (int i = 0; i < 12; i++) t += ws[i]; ws[0] = t; }
    __syncthreads();
    float var = ws[0] * (1.0f/D_);
    float y = d * rsqrtf(var + LNEPS) * g[tid] + bt[tid];
    size_t o_ = (size_t)row*D_ + tid;
    out[o_] = add ? (out[o_] + y) : y;
}

// ---------------- rotary spatial embedding: (B,N,D[off:]) -> (B,H,N,HD) ------------
__global__ void rose_kernel(const float* __restrict__ src, int stride, int off,
                            float* __restrict__ dst, int N, int Gw, float sp0, float sp1,
                            const float* __restrict__ fr, const float* __restrict__ temp,
                            int doRot, int applyTemp){
    int idx = blockIdx.x*blockDim.x + threadIdx.x;
    int total = BH_ * N * HD_;
    if (idx >= total) return;
    int hd = idx & 31;
    int n  = (idx >> 5) % N;
    int bh = idx / (N*32);
    int h = bh % H_, b = bh / H_;
    const float* sp = src + ((size_t)b*N + n)*stride + off + h*HD_;
    float val;
    if (doRot && hd < NROT_){
        int m = hd >> 1, s = m >> 2, p = m & 3;
        float coord = (s == 0) ? (float)(n / Gw) * sp0 : (float)(n % Gw) * sp1;
        float ang = coord * fr[(h*2 + s)*4 + p];
        float cs, sn; sincosf(ang, &sn, &cs);
        float x1 = sp[2*m], x2 = sp[2*m+1];
        val = (hd & 1) ? (x1*sn + x2*cs) : (x1*cs - x2*sn);
    } else {
        val = sp[hd];
    }
    if (applyTemp) val *= temp[0];
    dst[idx] = val;
}

// ======== scores: E = exp(Q K^T) tile GEMM + fused row-sum atomics ========
// grid (NIN/64, 8, BH), 256 threads, thread = 4q x 4k.
__global__ void score_kernel(const float* __restrict__ q, const float* __restrict__ kmat,
                             float* __restrict__ E, float* __restrict__ rowsum){
    __shared__ float Qs[32][68];
    __shared__ float Ks[32][68];
    int tid = threadIdx.x;
    int tx = tid & 15, ty = tid >> 4;
    int kt = blockIdx.x * 64, q0 = blockIdx.y * 64, bh = blockIdx.z;
    int m  = tid & 63;
    int dg = (tid >> 6) * 8;
    // load Q tile (guard rows) and K tile, k-major in smem
    {
        float4 a0 = make_float4(0.f,0.f,0.f,0.f), a1 = a0;
        if (q0 + m < NOUT){
            const float* src = q + ((size_t)bh*NOUT + q0 + m)*HD_ + dg;
            a0 = *(const float4*)src; a1 = *(const float4*)(src + 4);
        }
        Qs[dg+0][m]=a0.x; Qs[dg+1][m]=a0.y; Qs[dg+2][m]=a0.z; Qs[dg+3][m]=a0.w;
        Qs[dg+4][m]=a1.x; Qs[dg+5][m]=a1.y; Qs[dg+6][m]=a1.z; Qs[dg+7][m]=a1.w;
        const float* ks = kmat + ((size_t)bh*NIN + kt + m)*HD_ + dg;
        float4 b0 = *(const float4*)ks, b1 = *(const float4*)(ks + 4);
        Ks[dg+0][m]=b0.x; Ks[dg+1][m]=b0.y; Ks[dg+2][m]=b0.z; Ks[dg+3][m]=b0.w;
        Ks[dg+4][m]=b1.x; Ks[dg+5][m]=b1.y; Ks[dg+6][m]=b1.z; Ks[dg+7][m]=b1.w;
    }
    __syncthreads();
    float acc[4][4] = {};
    #pragma unroll
    for (int d = 0; d < 32; d++){
        float4 av = *(float4*)&Qs[d][ty*4];
        float4 bv = *(float4*)&Ks[d][tx*4];
        acc[0][0]+=av.x*bv.x; acc[0][1]+=av.x*bv.y; acc[0][2]+=av.x*bv.z; acc[0][3]+=av.x*bv.w;
        acc[1][0]+=av.y*bv.x; acc[1][1]+=av.y*bv.y; acc[1][2]+=av.y*bv.z; acc[1][3]+=av.y*bv.w;
        acc[2][0]+=av.z*bv.x; acc[2][1]+=av.z*bv.y; acc[2][2]+=av.z*bv.z; acc[2][3]+=av.z*bv.w;
        acc[3][0]+=av.w*bv.x; acc[3][1]+=av.w*bv.y; acc[3][2]+=av.w*bv.z; acc[3][3]+=av.w*bv.w;
    }
    #pragma unroll
    for (int i = 0; i < 4; i++){
        int r = q0 + ty*4 + i;
        float4 e;
        e.x = expf(acc[i][0]); e.y = expf(acc[i][1]);
        e.z = expf(acc[i][2]); e.w = expf(acc[i][3]);
        float rs = e.x + e.y + e.z + e.w;
        if (r < NOUT)
            *(float4*)(E + ((size_t)bh*NOUT + r)*NIN + kt + tx*4) = e;
        #pragma unroll
        for (int o = 8; o > 0; o >>= 1) rs += __shfl_down_sync(0xffffffffu, rs, o, 16);
        if ((tid & 15) == 0 && r < NOUT)
            atomicAdd(rowsum + bh*NOUT + r, rs);
    }
}

// in-place: rowsum -> 1/rowsum
__global__ void rowinv_kernel(float* __restrict__ rowsum){
    int i = blockIdx.x*blockDim.x + threadIdx.x;
    if (i < BH_*NOUT) rowsum[i] = 1.f / rowsum[i];
}

// colinv[bh][c] = 1 / (sum_q E[q,c]*rowinv[q] + eps)
__global__ void colsum_kernel(const float* __restrict__ E, const float* __restrict__ rinv,
                              float* __restrict__ colinv){
    int bh = blockIdx.y;
    int col = blockIdx.x*256 + threadIdx.x;
    const float* a = E + (size_t)bh*NOUT*NIN + col;
    const float* ri = rinv + bh*NOUT;
    float s = 0.f;
    #pragma unroll 4
    for (int qi = 0; qi < NOUT; qi++) s += a[(size_t)qi*NIN] * __ldg(ri + qi);
    colinv[bh*NIN + col] = 1.f / (s + EPSV);
}

// ======== PV GEMM: upd += (E*rowinv*colinv) @ V, split-K, atomic epilogue ========
// grid (4 qtiles, BH, 4 ksplits), 256 threads, thread = 4q x 4n. M-tile 128, N=32.
__global__ void pv_kernel(const float* __restrict__ E, const float* __restrict__ rinv,
                          const float* __restrict__ colinv, const float* __restrict__ v,
                          float* __restrict__ out){
    __shared__ float  Es[16][132];
    __shared__ float4 Vs[16][8];
    int tid = threadIdx.x;
    int tx = tid & 7;          // 4 cols -> 32
    int ty = tid >> 3;         // 4 rows -> 128
    int q0 = blockIdx.x * 128, bh = blockIdx.y;
    int ks0 = blockIdx.z * 1024;
    float acc[4][4] = {};
    int la_m  = tid & 127;
    int la_kg = (tid >> 7) * 8;
    int am = q0 + la_m;
    bool mok = am < NOUT;
    float rowv = mok ? rinv[bh*NOUT + am] : 0.f;
    const float* Erow = E + ((size_t)bh*NOUT + (mok ? am : 0))*NIN;
    const float* ci   = colinv + bh*NIN;
    const float* vb   = v + (size_t)bh*NIN*HD_;
    for (int k0 = ks0; k0 < ks0 + 1024; k0 += 16){
        float4 a0 = make_float4(0.f,0.f,0.f,0.f), a1 = a0;
        if (mok){
            a0 = *(const float4*)(Erow + k0 + la_kg);
            a1 = *(const float4*)(Erow + k0 + la_kg + 4);
        }
        float4 c0 = *(const float4*)(ci + k0 + la_kg);
        float4 c1 = *(const float4*)(ci + k0 + la_kg + 4);
        Es[la_kg+0][la_m]=a0.x*rowv*c0.x; Es[la_kg+1][la_m]=a0.y*rowv*c0.y;
        Es[la_kg+2][la_m]=a0.z*rowv*c0.z; Es[la_kg+3][la_m]=a0.w*rowv*c0.w;
        Es[la_kg+4][la_m]=a1.x*rowv*c1.x; Es[la_kg+5][la_m]=a1.y*rowv*c1.y;
        Es[la_kg+6][la_m]=a1.z*rowv*c1.z; Es[la_kg+7][la_m]=a1.w*rowv*c1.w;
        if (tid < 128){
            int kk = tid >> 3, n4 = tid & 7;
            Vs[kk][n4] = *(const float4*)(vb + (size_t)(k0+kk)*HD_ + n4*4);
        }
        __syncthreads();
        #pragma unroll
        for (int kk = 0; kk < 16; kk++){
            float4 av = *(float4*)&Es[kk][ty*4];
            float4 bv = Vs[kk][tx];
            acc[0][0]+=av.x*bv.x; acc[0][1]+=av.x*bv.y; acc[0][2]+=av.x*bv.z; acc[0][3]+=av.x*bv.w;
            acc[1][0]+=av.y*bv.x; acc[1][1]+=av.y*bv.y; acc[1][2]+=av.y*bv.z; acc[1][3]+=av.y*bv.w;
            acc[2][0]+=av.z*bv.x; acc[2][1]+=av.z*bv.y; acc[2][2]+=av.z*bv.z; acc[2][3]+=av.z*bv.w;
            acc[3][0]+=av.w*bv.x; acc[3][1]+=av.w*bv.y; acc[3][2]+=av.w*bv.z; acc[3][3]+=av.w*bv.w;
        }
        __syncthreads();
    }
    int b = bh / H_, h = bh % H_;
    #pragma unroll
    for (int i = 0; i < 4; i++){
        int r = q0 + ty*4 + i;
        if (r >= NOUT) break;
        float* dst = out + ((size_t)b*NOUT + r)*D_ + h*HD_ + tx*4;
        #pragma unroll
        for (int j = 0; j < 4; j++) atomicAdd(dst + j, acc[i][j]);
    }
}

// last iter: attn_k = E*rowinv (in place), attn_q = attn_k*colinv
__global__ void final_kernel(float* __restrict__ E, const float* __restrict__ rinv,
                             const float* __restrict__ colinv, float* __restrict__ outq){
    size_t idx = ((size_t)blockIdx.x*blockDim.x + threadIdx.x) * 4;
    if (idx >= ATTN_SZ) return;
    size_t row = idx >> 12;          // NIN = 4096
    int col = (int)(idx & 4095);
    int bh = (int)(row / NOUT);
    float rv = rinv[row];
    float4 e = *(float4*)(E + idx);
    float4 cv = *(const float4*)(colinv + bh*NIN + col);
    float4 ak, aq;
    ak.x = e.x*rv; ak.y = e.y*rv; ak.z = e.z*rv; ak.w = e.w*rv;
    aq.x = ak.x*cv.x; aq.y = ak.y*cv.y; aq.z = ak.z*cv.z; aq.w = ak.w*cv.w;
    *(float4*)(E + idx) = ak;
    *(float4*)(outq + idx) = aq;
}

__global__ void copy_kernel(const float* __restrict__ src, float* __restrict__ dst, int n){
    int idx = blockIdx.x*blockDim.x + threadIdx.x;
    if (idx < n) dst[idx] = src[idx];
}

// ---------------- host orchestration ----------------------------------------------
extern "C" void kernel_launch(void* const* d_in, const int* in_sizes, int n_in,
                              void* d_out, int out_size){
    const float* x      = (const float*)d_in[0];
    const float* conv_w = (const float*)d_in[1];
    const float* conv_b = (const float*)d_in[2];
    const float* kv_w   = (const float*)d_in[3];
    const float* kv_b   = (const float*)d_in[4];
    const float* q_w    = (const float*)d_in[5];
    const float* q_b    = (const float*)d_in[6];
    const float* w1     = (const float*)d_in[7];
    const float* b1m    = (const float*)d_in[8];
    const float* w2     = (const float*)d_in[9];
    const float* b2m    = (const float*)d_in[10];
    const float* g1     = (const float*)d_in[11];
    const float* b1_    = (const float*)d_in[12];
    const float* g2     = (const float*)d_in[13];
    const float* b2_    = (const float*)d_in[14];
    const float* g3     = (const float*)d_in[15];
    const float* b3_    = (const float*)d_in[16];
    const float* temp   = (const float*)d_in[17];
    const float* freqs  = (const float*)d_in[18];

    float *wt, *xo, *xout, *kv, *k, *v, *qlin, *q, *attn_s, *rowsum, *colinv, *h1;
    cudaGetSymbolAddress((void**)&wt,     g_wt);
    cudaGetSymbolAddress((void**)&xo,     g_xo);
    cudaGetSymbolAddress((void**)&xout,   g_xout);
    cudaGetSymbolAddress((void**)&kv,     g_kv);
    cudaGetSymbolAddress((void**)&k,      g_k);
    cudaGetSymbolAddress((void**)&v,      g_v);
    cudaGetSymbolAddress((void**)&qlin,   g_qlin);
    cudaGetSymbolAddress((void**)&q,      g_q);
    cudaGetSymbolAddress((void**)&attn_s, g_attn);
    cudaGetSymbolAddress((void**)&rowsum, g_rowsum);
    cudaGetSymbolAddress((void**)&colinv, g_colinv);
    cudaGetSymbolAddress((void**)&h1,     g_h1);

    float* out = (float*)d_out;
    bool full = (size_t)out_size >= (size_t)XOUT_SZ + 2*ATTN_SZ;
    float* out_attnq = full ? out + XOUT_SZ : attn_s;
    float* Ebuf      = full ? out + XOUT_SZ + ATTN_SZ : attn_s;  // attn_k slot holds E

    // ---- prologue (loop-invariant) ----
    wt_kernel<<<(49*D_*D_ + 255)/256, 256>>>(conv_w, wt);
    initbias_kernel<<<(MOUT*D_ + 255)/256, 256>>>(conv_b, xo);
    conv128_kernel<<<dim3(D_/64, (MOUT+127)/128, 7), 256>>>(x, wt, xo);
    ln_kernel<<<MOUT, D_>>>(xo, g1, b1_, xout, 0);
    gemm128_kernel<<<dim3(2*D_/64, MIN_/128), 256>>>(x, kv_w, kv_b, kv, MIN_, 2*D_, D_, 0);
    int totk = BH_*NIN*HD_;
    rose_kernel<<<(totk+255)/256, 256>>>(kv, 2*D_, 0,  k, NIN, GW_, 1.f, 1.f, freqs, temp, 1, 1);
    rose_kernel<<<(totk+255)/256, 256>>>(kv, 2*D_, D_, v, NIN, GW_, 1.f, 1.f, freqs, temp, 0, 0);

    int totq = BH_*NOUT*HD_;
    for (int it = 0; it < 3; it++){
        gemm128_kernel<<<dim3(D_/64, (MOUT+127)/128), 256>>>(xout, q_w, q_b, qlin, MOUT, D_, D_, 0);
        rose_kernel<<<(totq+255)/256, 256>>>(qlin, D_, 0, q, NOUT, QG, 3.f, 3.f, freqs, temp, 1, 0);

        zero2_kernel<<<(MOUT*D_ + 255)/256, 256>>>(rowsum, BH_*NOUT, xo, MOUT*D_);
        score_kernel<<<dim3(NIN/64, (NOUT+63)/64, BH_), 256>>>(q, k, Ebuf, rowsum);
        rowinv_kernel<<<(BH_*NOUT + 255)/256, 256>>>(rowsum);
        colsum_kernel<<<dim3(NIN/256, BH_), 256>>>(Ebuf, rowsum, colinv);
        pv_kernel<<<dim3((NOUT+127)/128, BH_, 4), 256>>>(Ebuf, rowsum, colinv, v, xo);
        if (it == 2 && full)
            final_kernel<<<(int)((ATTN_SZ/4 + 255)/256), 256>>>(Ebuf, rowsum, colinv, out_attnq);
        ln_kernel<<<MOUT, D_>>>(xo, g2, b2_, xout, 1);

        gemm128_kernel<<<dim3(4*D_/64, (MOUT+127)/128), 256>>>(xout, w1, b1m, h1, MOUT, 4*D_, D_, 1);
        gemm128_kernel<<<dim3(D_/64, (MOUT+127)/128), 256>>>(h1, w2, b2m, xo, MOUT, D_, 4*D_, 0);
        ln_kernel<<<MOUT, D_>>>(xo, g3, b3_, xout, 1);
    }
    copy_kernel<<<(XOUT_SZ + 255)/256, 256>>>(xout, out, XOUT_SZ);
}

// round 7
// speedup vs baseline: 3.8202x; 1.2540x over previous
#include <cuda_runtime.h>
#include <cuda_bf16.h>
#include <math.h>
#include <stdint.h>

// ---------------- problem constants ----------------
#define B_    2
#define NIN   4096
#define NOUT  484
#define D_    384
#define H_    12
#define HD_   32
#define QG    22
#define GW_   64
#define MOUT  (B_*NOUT)   // 968
#define MIN_  (B_*NIN)    // 8192
#define BH_   (B_*H_)     // 24
#define NROT_ 16
#define LNEPS 1e-5f
#define EPSV  1.1920929e-07f

#define XOUT_SZ  (MOUT*D_)                       // 371712
#define ATTN_SZ  ((size_t)BH_*NOUT*NIN)          // 47579136

// ---------------- scratch (device globals; no alloc allowed) ----------------
__device__ unsigned g_wtp[49*D_*D_];     // conv weight, [khw][ci][co], packed bf16 hi/lo
__device__ unsigned g_kvwp[D_*2*D_];
__device__ unsigned g_qwp[D_*D_];
__device__ unsigned g_w1p[D_*4*D_];
__device__ unsigned g_w2p[4*D_*D_];
__device__ float g_xo[MOUT*D_];
__device__ float g_xout[MOUT*D_];
__device__ float g_kv[MIN_*2*D_];
__device__ float g_k[BH_*NIN*HD_];
__device__ float g_v[BH_*NIN*HD_];
__device__ float g_qlin[MOUT*D_];
__device__ float g_q[BH_*NOUT*HD_];
__device__ float g_attn[(size_t)BH_*NOUT*NIN];   // fallback if out_size is small
__device__ float g_rowsum[BH_*NOUT];
__device__ float g_colinv[BH_*NIN];
__device__ float g_h1[MOUT*4*D_];

__device__ __forceinline__ float gelu_f(float x){
    return 0.5f * x * (1.0f + erff(x * 0.70710678118654752f));
}
__device__ __forceinline__ void split1(float v, __nv_bfloat16& h, __nv_bfloat16& l){
    h = __float2bfloat16(v);
    l = __float2bfloat16(v - __bfloat162float(h));
}
__device__ __forceinline__ unsigned pack_hl(float v){
    __nv_bfloat16 h, l; split1(v, h, l);
    return ((unsigned)__bfloat16_as_ushort(h)<<16) | (unsigned)__bfloat16_as_ushort(l);
}

// D += A(16x16) * B(16x8), bf16 inputs, f32 accum
__device__ __forceinline__ void mma16816(float* c, const unsigned* a, const unsigned* b){
    asm volatile("mma.sync.aligned.m16n8k16.row.col.f32.bf16.bf16.f32 "
        "{%0,%1,%2,%3},{%4,%5,%6,%7},{%8,%9},{%0,%1,%2,%3};"
        : "+f"(c[0]), "+f"(c[1]), "+f"(c[2]), "+f"(c[3])
        : "r"(a[0]), "r"(a[1]), "r"(a[2]), "r"(a[3]), "r"(b[0]), "r"(b[1]));
}

// ---------------- prologue pack kernels ----------------
__global__ void packw_kernel(const float* __restrict__ src, unsigned* __restrict__ dst, int n){
    int i = blockIdx.x*blockDim.x + threadIdx.x;
    if (i < n) dst[i] = pack_hl(src[i]);
}
// dst[khw][ci][co] = pack(w[co][ci][kh][kw])
__global__ void packconv_kernel(const float* __restrict__ w, unsigned* __restrict__ dst){
    int idx = blockIdx.x*blockDim.x + threadIdx.x;
    if (idx >= 49*D_*D_) return;
    int co  = idx % D_;
    int ci  = (idx / D_) % D_;
    int khw = idx / (D_*D_);
    dst[idx] = pack_hl(w[((size_t)co*D_ + ci)*49 + khw]);
}
__global__ void seed_kernel(const float* __restrict__ b, float* __restrict__ o, int M, int N){
    int idx = blockIdx.x*blockDim.x + threadIdx.x;
    if (idx < M*N) o[idx] = b[idx % N];
}
__global__ void zero2_kernel(float* __restrict__ a, int na, float* __restrict__ b, int nb){
    int i = blockIdx.x*blockDim.x + threadIdx.x;
    if (i < na) a[i] = 0.f;
    if (i < nb) b[i] = 0.f;
}

// ================= HMMA (mma.sync) bf16-split GEMM =================
// C[M,N] = A[M,K](fp32) @ Bp[K,N](packed bf16 hi|lo). Tile 128x64, BK=32.
// 8 warps as 4(M)x2(N); warp tile 32x32 = 2x4 m16n8 frags. 3-term hi/lo split.
#define ASTR 40   // bf16 elements per smem row (80B) -> conflict-free frag loads

struct Frag { unsigned ah[2][4], al[2][4], bh[4][2], bl[4][2]; };

__device__ __forceinline__ void load_frags(Frag& f, const __nv_bfloat16* Ah, const __nv_bfloat16* Al,
                                           const __nv_bfloat16* Bh, const __nv_bfloat16* Bl,
                                           int wm, int wn, int ks, int g, int c2){
    #pragma unroll
    for (int t = 0; t < 2; t++){
        int rb = (wm*32 + t*16 + g)*ASTR + ks + c2;
        f.ah[t][0] = *(const unsigned*)(Ah + rb);
        f.ah[t][1] = *(const unsigned*)(Ah + rb + 8*ASTR);
        f.ah[t][2] = *(const unsigned*)(Ah + rb + 8);
        f.ah[t][3] = *(const unsigned*)(Ah + rb + 8*ASTR + 8);
        f.al[t][0] = *(const unsigned*)(Al + rb);
        f.al[t][1] = *(const unsigned*)(Al + rb + 8*ASTR);
        f.al[t][2] = *(const unsigned*)(Al + rb + 8);
        f.al[t][3] = *(const unsigned*)(Al + rb + 8*ASTR + 8);
    }
    #pragma unroll
    for (int u = 0; u < 4; u++){
        int nb = (wn*32 + u*8 + g)*ASTR + ks + c2;
        f.bh[u][0] = *(const unsigned*)(Bh + nb);
        f.bh[u][1] = *(const unsigned*)(Bh + nb + 8);
        f.bl[u][0] = *(const unsigned*)(Bl + nb);
        f.bl[u][1] = *(const unsigned*)(Bl + nb + 8);
    }
}
__device__ __forceinline__ void do_mmas(float (*acc)[4], const Frag& f){
    #pragma unroll
    for (int t = 0; t < 2; t++)
        #pragma unroll
        for (int u = 0; u < 4; u++){
            mma16816(acc[t*4+u], f.ah[t], f.bh[u]);
            mma16816(acc[t*4+u], f.ah[t], f.bl[u]);
            mma16816(acc[t*4+u], f.al[t], f.bh[u]);
        }
}
__device__ __forceinline__ void epi(float (*acc)[4], const float* __restrict__ bias,
                                    float* __restrict__ C, int M, int N, int m0, int n0,
                                    int wm, int wn, int g, int c2, int act, int atom){
    #pragma unroll
    for (int t = 0; t < 2; t++){
        int r0 = m0 + wm*32 + t*16 + g;
        #pragma unroll
        for (int u = 0; u < 4; u++){
            int cb = n0 + wn*32 + u*8 + c2;
            float* ac = acc[t*4+u];
            if (atom){
                if (r0 < M){
                    atomicAdd(&C[(size_t)r0*N + cb],     ac[0]);
                    atomicAdd(&C[(size_t)r0*N + cb + 1], ac[1]);
                }
                if (r0 + 8 < M){
                    atomicAdd(&C[(size_t)(r0+8)*N + cb],     ac[2]);
                    atomicAdd(&C[(size_t)(r0+8)*N + cb + 1], ac[3]);
                }
            } else {
                float b0 = bias[cb], b1 = bias[cb+1];
                float o0 = ac[0]+b0, o1 = ac[1]+b1, o2 = ac[2]+b0, o3 = ac[3]+b1;
                if (act){ o0=gelu_f(o0); o1=gelu_f(o1); o2=gelu_f(o2); o3=gelu_f(o3); }
                if (r0 < M){ C[(size_t)r0*N + cb] = o0; C[(size_t)r0*N + cb + 1] = o1; }
                if (r0 + 8 < M){ C[(size_t)(r0+8)*N + cb] = o2; C[(size_t)(r0+8)*N + cb + 1] = o3; }
            }
        }
    }
}

__global__ __launch_bounds__(256, 2)
void mgemm_kernel(const float* __restrict__ A, const unsigned* __restrict__ Bp,
                  const float* __restrict__ bias, float* __restrict__ C,
                  int M, int N, int K, int kSlice, int act, int atom){
    __shared__ __align__(16) __nv_bfloat16 Ah[128*ASTR], Al[128*ASTR];
    __shared__ __align__(16) __nv_bfloat16 Bh[64*ASTR],  Bl[64*ASTR];
    int tid = threadIdx.x, lane = tid & 31, wid = tid >> 5;
    int wm = wid >> 1, wn = wid & 1;
    int g = lane >> 2, c2 = (lane & 3)*2;
    int m0 = blockIdx.y*128, n0 = blockIdx.x*64;
    int kb0 = blockIdx.z*kSlice, kend = kb0 + kSlice;
    float acc[8][4] = {};
    for (int k0 = kb0; k0 < kend; k0 += 32){
        #pragma unroll
        for (int i = 0; i < 4; i++){
            int e = tid + i*256;
            int row = e >> 3, kg = (e & 7)*4;
            float4 v = (m0+row < M) ? *(const float4*)(A + (size_t)(m0+row)*K + k0 + kg)
                                    : make_float4(0.f,0.f,0.f,0.f);
            __nv_bfloat16 h, l; int o = row*ASTR + kg;
            split1(v.x, h, l); Ah[o+0]=h; Al[o+0]=l;
            split1(v.y, h, l); Ah[o+1]=h; Al[o+1]=l;
            split1(v.z, h, l); Ah[o+2]=h; Al[o+2]=l;
            split1(v.w, h, l); Ah[o+3]=h; Al[o+3]=l;
        }
        #pragma unroll
        for (int i = 0; i < 8; i++){
            int e = i*256 + tid;
            int kk = e >> 6, n = e & 63;
            unsigned wv = Bp[(size_t)(k0+kk)*N + n0 + n];
            Bh[n*ASTR+kk] = __ushort_as_bfloat16((unsigned short)(wv >> 16));
            Bl[n*ASTR+kk] = __ushort_as_bfloat16((unsigned short)(wv & 0xffffu));
        }
        __syncthreads();
        #pragma unroll
        for (int ks = 0; ks < 32; ks += 16){
            Frag f;
            load_frags(f, Ah, Al, Bh, Bl, wm, wn, ks, g, c2);
            do_mmas(acc, f);
        }
        __syncthreads();
    }
    epi(acc, bias, C, M, N, m0, n0, wm, wn, g, c2, act, atom);
}

// conv as implicit GEMM: K = 7*384 per slice (grid.z = 7), atomic epilogue
__global__ __launch_bounds__(256, 2)
void mconv_kernel(const float* __restrict__ x, const unsigned* __restrict__ Bp,
                  float* __restrict__ C){
    __shared__ __align__(16) __nv_bfloat16 Ah[128*ASTR], Al[128*ASTR];
    __shared__ __align__(16) __nv_bfloat16 Bh[64*ASTR],  Bl[64*ASTR];
    int tid = threadIdx.x, lane = tid & 31, wid = tid >> 5;
    int wm = wid >> 1, wn = wid & 1;
    int g = lane >> 2, c2 = (lane & 3)*2;
    int m0 = blockIdx.y*128, n0 = blockIdx.x*64;
    int slice = blockIdx.z;
    float acc[8][4] = {};
    for (int kc = 0; kc < 7*D_; kc += 32){
        int khw = slice*7 + kc/D_;
        int cib = kc % D_;
        int kh = khw/7, kw = khw%7;
        #pragma unroll
        for (int i = 0; i < 4; i++){
            int e = tid + i*256;
            int row = e >> 3, kg = (e & 7)*4;
            int m = m0 + row;
            float4 v = make_float4(0.f,0.f,0.f,0.f);
            if (m < MOUT){
                int bb = m / NOUT, rr = m % NOUT;
                int oh = rr / QG, ow = rr % QG;
                int ih = oh*3 - 3 + kh, iw = ow*3 - 3 + kw;
                if ((unsigned)ih < 64u && (unsigned)iw < 64u)
                    v = *(const float4*)(x + ((size_t)(bb*NIN + ih*GW_ + iw))*D_ + cib + kg);
            }
            __nv_bfloat16 h, l; int o = row*ASTR + kg;
            split1(v.x, h, l); Ah[o+0]=h; Al[o+0]=l;
            split1(v.y, h, l); Ah[o+1]=h; Al[o+1]=l;
            split1(v.z, h, l); Ah[o+2]=h; Al[o+2]=l;
            split1(v.w, h, l); Ah[o+3]=h; Al[o+3]=l;
        }
        #pragma unroll
        for (int i = 0; i < 8; i++){
            int e = i*256 + tid;
            int kk = e >> 6, n = e & 63;
            unsigned wv = Bp[(size_t)(khw*D_ + cib + kk)*D_ + n0 + n];
            Bh[n*ASTR+kk] = __ushort_as_bfloat16((unsigned short)(wv >> 16));
            Bl[n*ASTR+kk] = __ushort_as_bfloat16((unsigned short)(wv & 0xffffu));
        }
        __syncthreads();
        #pragma unroll
        for (int ks = 0; ks < 32; ks += 16){
            Frag f;
            load_frags(f, Ah, Al, Bh, Bl, wm, wn, ks, g, c2);
            do_mmas(acc, f);
        }
        __syncthreads();
    }
    epi(acc, (const float*)0, C, MOUT, D_, m0, n0, wm, wn, g, c2, 0, 1);
}

// ---------------- layernorm over D=384, optional residual-add into out -------------
__global__ void ln_kernel(const float* __restrict__ X, const float* __restrict__ g,
                          const float* __restrict__ bt, float* __restrict__ out, int add){
    int row = blockIdx.x, tid = threadIdx.x;
    float x = X[(size_t)row*D_ + tid];
    __shared__ float ws[12];
    float s = x;
    #pragma unroll
    for (int o = 16; o > 0; o >>= 1) s += __shfl_down_sync(0xffffffffu, s, o);
    if ((tid & 31) == 0) ws[tid >> 5] = s;
    __syncthreads();
    if (tid == 0){ float t = 0.f; for (int i = 0; i < 12; i++) t += ws[i]; ws[0] = t; }
    __syncthreads();
    float mu = ws[0] * (1.0f/D_);
    __syncthreads();
    float d = x - mu;
    s = d*d;
    #pragma unroll
    for (int o = 16; o > 0; o >>= 1) s += __shfl_down_sync(0xffffffffu, s, o);
    if ((tid & 31) == 0) ws[tid >> 5] = s;
    __syncthreads();
    if (tid == 0){ float t = 0.f; for (int i = 0; i < 12; i++) t += ws[i]; ws[0] = t; }
    __syncthreads();
    float var = ws[0] * (1.0f/D_);
    float y = d * rsqrtf(var + LNEPS) * g[tid] + bt[tid];
    size_t o_ = (size_t)row*D_ + tid;
    out[o_] = add ? (out[o_] + y) : y;
}

// ---------------- rotary spatial embedding: (B,N,D[off:]) -> (B,H,N,HD) ------------
__global__ void rose_kernel(const float* __restrict__ src, int stride, int off,
                            float* __restrict__ dst, int N, int Gw, float sp0, float sp1,
                            const float* __restrict__ fr, const float* __restrict__ temp,
                            int doRot, int applyTemp){
    int idx = blockIdx.x*blockDim.x + threadIdx.x;
    int total = BH_ * N * HD_;
    if (idx >= total) return;
    int hd = idx & 31;
    int n  = (idx >> 5) % N;
    int bh = idx / (N*32);
    int h = bh % H_, b = bh / H_;
    const float* sp = src + ((size_t)b*N + n)*stride + off + h*HD_;
    float val;
    if (doRot && hd < NROT_){
        int m = hd >> 1, s = m >> 2, p = m & 3;
        float coord = (s == 0) ? (float)(n / Gw) * sp0 : (float)(n % Gw) * sp1;
        float ang = coord * fr[(h*2 + s)*4 + p];
        float cs, sn; sincosf(ang, &sn, &cs);
        float x1 = sp[2*m], x2 = sp[2*m+1];
        val = (hd & 1) ? (x1*sn + x2*cs) : (x1*cs - x2*sn);
    } else {
        val = sp[hd];
    }
    if (applyTemp) val *= temp[0];
    dst[idx] = val;
}

// ======== scores: E = exp(Q K^T) tile GEMM + fused row-sum atomics ========
__global__ void score_kernel(const float* __restrict__ q, const float* __restrict__ kmat,
                             float* __restrict__ E, float* __restrict__ rowsum){
    __shared__ float Qs[32][68];
    __shared__ float Ks[32][68];
    int tid = threadIdx.x;
    int tx = tid & 15, ty = tid >> 4;
    int kt = blockIdx.x * 64, q0 = blockIdx.y * 64, bh = blockIdx.z;
    int m  = tid & 63;
    int dg = (tid >> 6) * 8;
    {
        float4 a0 = make_float4(0.f,0.f,0.f,0.f), a1 = a0;
        if (q0 + m < NOUT){
            const float* src = q + ((size_t)bh*NOUT + q0 + m)*HD_ + dg;
            a0 = *(const float4*)src; a1 = *(const float4*)(src + 4);
        }
        Qs[dg+0][m]=a0.x; Qs[dg+1][m]=a0.y; Qs[dg+2][m]=a0.z; Qs[dg+3][m]=a0.w;
        Qs[dg+4][m]=a1.x; Qs[dg+5][m]=a1.y; Qs[dg+6][m]=a1.z; Qs[dg+7][m]=a1.w;
        const float* ks = kmat + ((size_t)bh*NIN + kt + m)*HD_ + dg;
        float4 b0 = *(const float4*)ks, b1 = *(const float4*)(ks + 4);
        Ks[dg+0][m]=b0.x; Ks[dg+1][m]=b0.y; Ks[dg+2][m]=b0.z; Ks[dg+3][m]=b0.w;
        Ks[dg+4][m]=b1.x; Ks[dg+5][m]=b1.y; Ks[dg+6][m]=b1.z; Ks[dg+7][m]=b1.w;
    }
    __syncthreads();
    float acc[4][4] = {};
    #pragma unroll
    for (int d = 0; d < 32; d++){
        float4 av = *(float4*)&Qs[d][ty*4];
        float4 bv = *(float4*)&Ks[d][tx*4];
        acc[0][0]+=av.x*bv.x; acc[0][1]+=av.x*bv.y; acc[0][2]+=av.x*bv.z; acc[0][3]+=av.x*bv.w;
        acc[1][0]+=av.y*bv.x; acc[1][1]+=av.y*bv.y; acc[1][2]+=av.y*bv.z; acc[1][3]+=av.y*bv.w;
        acc[2][0]+=av.z*bv.x; acc[2][1]+=av.z*bv.y; acc[2][2]+=av.z*bv.z; acc[2][3]+=av.z*bv.w;
        acc[3][0]+=av.w*bv.x; acc[3][1]+=av.w*bv.y; acc[3][2]+=av.w*bv.z; acc[3][3]+=av.w*bv.w;
    }
    #pragma unroll
    for (int i = 0; i < 4; i++){
        int r = q0 + ty*4 + i;
        float4 e;
        e.x = expf(acc[i][0]); e.y = expf(acc[i][1]);
        e.z = expf(acc[i][2]); e.w = expf(acc[i][3]);
        float rs = e.x + e.y + e.z + e.w;
        if (r < NOUT)
            *(float4*)(E + ((size_t)bh*NOUT + r)*NIN + kt + tx*4) = e;
        #pragma unroll
        for (int o = 8; o > 0; o >>= 1) rs += __shfl_down_sync(0xffffffffu, rs, o, 16);
        if ((tid & 15) == 0 && r < NOUT)
            atomicAdd(rowsum + bh*NOUT + r, rs);
    }
}

__global__ void rowinv_kernel(float* __restrict__ rowsum){
    int i = blockIdx.x*blockDim.x + threadIdx.x;
    if (i < BH_*NOUT) rowsum[i] = 1.f / rowsum[i];
}

__global__ void colsum_kernel(const float* __restrict__ E, const float* __restrict__ rinv,
                              float* __restrict__ colinv){
    int bh = blockIdx.y;
    int col = blockIdx.x*256 + threadIdx.x;
    const float* a = E + (size_t)bh*NOUT*NIN + col;
    const float* ri = rinv + bh*NOUT;
    float s = 0.f;
    #pragma unroll 4
    for (int qi = 0; qi < NOUT; qi++) s += a[(size_t)qi*NIN] * __ldg(ri + qi);
    colinv[bh*NIN + col] = 1.f / (s + EPSV);
}

// ======== PV GEMM: upd += (E*rowinv*colinv) @ V, split-K, atomic epilogue ========
__global__ void pv_kernel(const float* __restrict__ E, const float* __restrict__ rinv,
                          const float* __restrict__ colinv, const float* __restrict__ v,
                          float* __restrict__ out){
    __shared__ float  Es[16][132];
    __shared__ float4 Vs[16][8];
    int tid = threadIdx.x;
    int tx = tid & 7;
    int ty = tid >> 3;
    int q0 = blockIdx.x * 128, bh = blockIdx.y;
    int ks0 = blockIdx.z * 1024;
    float acc[4][4] = {};
    int la_m  = tid & 127;
    int la_kg = (tid >> 7) * 8;
    int am = q0 + la_m;
    bool mok = am < NOUT;
    float rowv = mok ? rinv[bh*NOUT + am] : 0.f;
    const float* Erow = E + ((size_t)bh*NOUT + (mok ? am : 0))*NIN;
    const float* ci   = colinv + bh*NIN;
    const float* vb   = v + (size_t)bh*NIN*HD_;
    for (int k0 = ks0; k0 < ks0 + 1024; k0 += 16){
        float4 a0 = make_float4(0.f,0.f,0.f,0.f), a1 = a0;
        if (mok){
            a0 = *(const float4*)(Erow + k0 + la_kg);
            a1 = *(const float4*)(Erow + k0 + la_kg + 4);
        }
        float4 c0 = *(const float4*)(ci + k0 + la_kg);
        float4 c1 = *(const float4*)(ci + k0 + la_kg + 4);
        Es[la_kg+0][la_m]=a0.x*rowv*c0.x; Es[la_kg+1][la_m]=a0.y*rowv*c0.y;
        Es[la_kg+2][la_m]=a0.z*rowv*c0.z; Es[la_kg+3][la_m]=a0.w*rowv*c0.w;
        Es[la_kg+4][la_m]=a1.x*rowv*c1.x; Es[la_kg+5][la_m]=a1.y*rowv*c1.y;
        Es[la_kg+6][la_m]=a1.z*rowv*c1.z; Es[la_kg+7][la_m]=a1.w*rowv*c1.w;
        if (tid < 128){
            int kk = tid >> 3, n4 = tid & 7;
            Vs[kk][n4] = *(const float4*)(vb + (size_t)(k0+kk)*HD_ + n4*4);
        }
        __syncthreads();
        #pragma unroll
        for (int kk = 0; kk < 16; kk++){
            float4 av = *(float4*)&Es[kk][ty*4];
            float4 bv = Vs[kk][tx];
            acc[0][0]+=av.x*bv.x; acc[0][1]+=av.x*bv.y; acc[0][2]+=av.x*bv.z; acc[0][3]+=av.x*bv.w;
            acc[1][0]+=av.y*bv.x; acc[1][1]+=av.y*bv.y; acc[1][2]+=av.y*bv.z; acc[1][3]+=av.y*bv.w;
            acc[2][0]+=av.z*bv.x; acc[2][1]+=av.z*bv.y; acc[2][2]+=av.z*bv.z; acc[2][3]+=av.z*bv.w;
            acc[3][0]+=av.w*bv.x; acc[3][1]+=av.w*bv.y; acc[3][2]+=av.w*bv.z; acc[3][3]+=av.w*bv.w;
        }
        __syncthreads();
    }
    int b = bh / H_, h = bh % H_;
    #pragma unroll
    for (int i = 0; i < 4; i++){
        int r = q0 + ty*4 + i;
        if (r >= NOUT) break;
        float* dst = out + ((size_t)b*NOUT + r)*D_ + h*HD_ + tx*4;
        #pragma unroll
        for (int j = 0; j < 4; j++) atomicAdd(dst + j, acc[i][j]);
    }
}

// last iter: attn_k = E*rowinv (in place), attn_q = attn_k*colinv
__global__ void final_kernel(float* __restrict__ E, const float* __restrict__ rinv,
                             const float* __restrict__ colinv, float* __restrict__ outq){
    size_t idx = ((size_t)blockIdx.x*blockDim.x + threadIdx.x) * 4;
    if (idx >= ATTN_SZ) return;
    size_t row = idx >> 12;
    int col = (int)(idx & 4095);
    int bh = (int)(row / NOUT);
    float rv = rinv[row];
    float4 e = *(float4*)(E + idx);
    float4 cv = *(const float4*)(colinv + bh*NIN + col);
    float4 ak, aq;
    ak.x = e.x*rv; ak.y = e.y*rv; ak.z = e.z*rv; ak.w = e.w*rv;
    aq.x = ak.x*cv.x; aq.y = ak.y*cv.y; aq.z = ak.z*cv.z; aq.w = ak.w*cv.w;
    *(float4*)(E + idx) = ak;
    *(float4*)(outq + idx) = aq;
}

__global__ void copy_kernel(const float* __restrict__ src, float* __restrict__ dst, int n){
    int idx = blockIdx.x*blockDim.x + threadIdx.x;
    if (idx < n) dst[idx] = src[idx];
}

// ---------------- host orchestration ----------------------------------------------
extern "C" void kernel_launch(void* const* d_in, const int* in_sizes, int n_in,
                              void* d_out, int out_size){
    const float* x      = (const float*)d_in[0];
    const float* conv_w = (const float*)d_in[1];
    const float* conv_b = (const float*)d_in[2];
    const float* kv_w   = (const float*)d_in[3];
    const float* kv_b   = (const float*)d_in[4];
    const float* q_w    = (const float*)d_in[5];
    const float* q_b    = (const float*)d_in[6];
    const float* w1     = (const float*)d_in[7];
    const float* b1m    = (const float*)d_in[8];
    const float* w2     = (const float*)d_in[9];
    const float* b2m    = (const float*)d_in[10];
    const float* g1     = (const float*)d_in[11];
    const float* b1_    = (const float*)d_in[12];
    const float* g2     = (const float*)d_in[13];
    const float* b2_    = (const float*)d_in[14];
    const float* g3     = (const float*)d_in[15];
    const float* b3_    = (const float*)d_in[16];
    const float* temp   = (const float*)d_in[17];
    const float* freqs  = (const float*)d_in[18];

    unsigned *wtp, *kvwp, *qwp, *w1p, *w2p;
    float *xo, *xout, *kv, *k, *v, *qlin, *q, *attn_s, *rowsum, *colinv, *h1;
    cudaGetSymbolAddress((void**)&wtp,    g_wtp);
    cudaGetSymbolAddress((void**)&kvwp,   g_kvwp);
    cudaGetSymbolAddress((void**)&qwp,    g_qwp);
    cudaGetSymbolAddress((void**)&w1p,    g_w1p);
    cudaGetSymbolAddress((void**)&w2p,    g_w2p);
    cudaGetSymbolAddress((void**)&xo,     g_xo);
    cudaGetSymbolAddress((void**)&xout,   g_xout);
    cudaGetSymbolAddress((void**)&kv,     g_kv);
    cudaGetSymbolAddress((void**)&k,      g_k);
    cudaGetSymbolAddress((void**)&v,      g_v);
    cudaGetSymbolAddress((void**)&qlin,   g_qlin);
    cudaGetSymbolAddress((void**)&q,      g_q);
    cudaGetSymbolAddress((void**)&attn_s, g_attn);
    cudaGetSymbolAddress((void**)&rowsum, g_rowsum);
    cudaGetSymbolAddress((void**)&colinv, g_colinv);
    cudaGetSymbolAddress((void**)&h1,     g_h1);

    float* out = (float*)d_out;
    bool full = (size_t)out_size >= (size_t)XOUT_SZ + 2*ATTN_SZ;
    float* out_attnq = full ? out + XOUT_SZ : attn_s;
    float* Ebuf      = full ? out + XOUT_SZ + ATTN_SZ : attn_s;  // attn_k slot holds E

    // ---- prologue: pack weights to bf16 hi/lo ----
    packconv_kernel<<<(49*D_*D_ + 255)/256, 256>>>(conv_w, wtp);
    packw_kernel<<<(D_*2*D_ + 255)/256, 256>>>(kv_w, kvwp, D_*2*D_);
    packw_kernel<<<(D_*D_ + 255)/256, 256>>>(q_w, qwp, D_*D_);
    packw_kernel<<<(D_*4*D_ + 255)/256, 256>>>(w1, w1p, D_*4*D_);
    packw_kernel<<<(4*D_*D_ + 255)/256, 256>>>(w2, w2p, 4*D_*D_);

    // ---- conv + first LN ----
    seed_kernel<<<(MOUT*D_ + 255)/256, 256>>>(conv_b, xo, MOUT, D_);
    mconv_kernel<<<dim3(D_/64, (MOUT+127)/128, 7), 256>>>(x, wtp, xo);
    ln_kernel<<<MOUT, D_>>>(xo, g1, b1_, xout, 0);

    // ---- kv (loop-invariant) + rose ----
    mgemm_kernel<<<dim3(2*D_/64, MIN_/128, 1), 256>>>(x, kvwp, kv_b, kv, MIN_, 2*D_, D_, D_, 0, 0);
    int totk = BH_*NIN*HD_;
    rose_kernel<<<(totk+255)/256, 256>>>(kv, 2*D_, 0,  k, NIN, GW_, 1.f, 1.f, freqs, temp, 1, 1);
    rose_kernel<<<(totk+255)/256, 256>>>(kv, 2*D_, D_, v, NIN, GW_, 1.f, 1.f, freqs, temp, 0, 0);

    int totq = BH_*NOUT*HD_;
    for (int it = 0; it < 3; it++){
        seed_kernel<<<(MOUT*D_ + 255)/256, 256>>>(q_b, qlin, MOUT, D_);
        mgemm_kernel<<<dim3(D_/64, (MOUT+127)/128, 2), 256>>>(xout, qwp, q_b, qlin, MOUT, D_, D_, D_/2, 0, 1);
        rose_kernel<<<(totq+255)/256, 256>>>(qlin, D_, 0, q, NOUT, QG, 3.f, 3.f, freqs, temp, 1, 0);

        zero2_kernel<<<(MOUT*D_ + 255)/256, 256>>>(rowsum, BH_*NOUT, xo, MOUT*D_);
        score_kernel<<<dim3(NIN/64, (NOUT+63)/64, BH_), 256>>>(q, k, Ebuf, rowsum);
        rowinv_kernel<<<(BH_*NOUT + 255)/256, 256>>>(rowsum);
        colsum_kernel<<<dim3(NIN/256, BH_), 256>>>(Ebuf, rowsum, colinv);
        pv_kernel<<<dim3((NOUT+127)/128, BH_, 4), 256>>>(Ebuf, rowsum, colinv, v, xo);
        if (it == 2 && full)
            final_kernel<<<(int)((ATTN_SZ/4 + 255)/256), 256>>>(Ebuf, rowsum, colinv, out_attnq);
        ln_kernel<<<MOUT, D_>>>(xo, g2, b2_, xout, 1);

        mgemm_kernel<<<dim3(4*D_/64, (MOUT+127)/128, 1), 256>>>(xout, w1p, b1m, h1, MOUT, 4*D_, D_, D_, 1, 0);
        seed_kernel<<<(MOUT*D_ + 255)/256, 256>>>(b2m, xo, MOUT, D_);
        mgemm_kernel<<<dim3(D_/64, (MOUT+127)/128, 2), 256>>>(h1, w2p, b2m, xo, MOUT, D_, 4*D_, 2*D_, 0, 1);
        ln_kernel<<<MOUT, D_>>>(xo, g3, b3_, xout, 1);
    }
    copy_kernel<<<(XOUT_SZ + 255)/256, 256>>>(xout, out, XOUT_SZ);
}

// round 8
// speedup vs baseline: 4.3650x; 1.1426x over previous
#include <cuda_runtime.h>
#include <cuda_bf16.h>
#include <math.h>
#include <stdint.h>

// ---------------- problem constants ----------------
#define B_    2
#define NIN   4096
#define NOUT  484
#define D_    384
#define H_    12
#define HD_   32
#define QG    22
#define GW_   64
#define MOUT  (B_*NOUT)   // 968
#define MIN_  (B_*NIN)    // 8192
#define BH_   (B_*H_)     // 24
#define NROT_ 16
#define LNEPS 1e-5f
#define EPSV  1.1920929e-07f
#define CKK   (49*D_)     // 18816 conv k-extent

#define XOUT_SZ  (MOUT*D_)                       // 371712
#define ATTN_SZ  ((size_t)BH_*NOUT*NIN)          // 47579136

// ---------------- scratch (device globals; no alloc allowed) ----------------
// weights: transposed [n][k], bf16 hi / lo
__device__ __nv_bfloat16 g_cwh[D_*CKK],  g_cwl[D_*CKK];       // conv: [co][khw*384+ci]
__device__ __nv_bfloat16 g_kvwh[2*D_*D_], g_kvwl[2*D_*D_];
__device__ __nv_bfloat16 g_qwh[D_*D_],    g_qwl[D_*D_];
__device__ __nv_bfloat16 g_w1h[4*D_*D_],  g_w1l[4*D_*D_];
__device__ __nv_bfloat16 g_w2h[D_*4*D_],  g_w2l[D_*4*D_];
// attention operands, bf16 hi/lo
__device__ __nv_bfloat16 g_kh[BH_*NIN*HD_],  g_kl[BH_*NIN*HD_];
__device__ __nv_bfloat16 g_vth[BH_*HD_*NIN], g_vtl[BH_*HD_*NIN];  // transposed [bh][d][n]
__device__ __nv_bfloat16 g_qh[BH_*NOUT*HD_], g_ql[BH_*NOUT*HD_];
// fp32 buffers
__device__ float g_xo[MOUT*D_];
__device__ float g_xout[MOUT*D_];
__device__ float g_kv[MIN_*2*D_];
__device__ float g_k[BH_*NIN*HD_];
__device__ float g_v[BH_*NIN*HD_];
__device__ float g_qlin[MOUT*D_];
__device__ float g_q[BH_*NOUT*HD_];
__device__ float g_attn[(size_t)BH_*NOUT*NIN];   // fallback if out_size is small
__device__ float g_rowsum[BH_*NOUT];
__device__ float g_colinv[BH_*NIN];
__device__ float g_h1[MOUT*4*D_];

// ---------------- helpers ----------------
__device__ __forceinline__ float gelu_f(float x){
    return 0.5f * x * (1.0f + erff(x * 0.70710678118654752f));
}
__device__ __forceinline__ void split1(float v, __nv_bfloat16& h, __nv_bfloat16& l){
    h = __float2bfloat16(v);
    l = __float2bfloat16(v - __bfloat162float(h));
}
// split float4 -> 2 packed u32 (hi) + 2 packed u32 (lo); element k in low half
__device__ __forceinline__ void split4(float4 v, unsigned& h0, unsigned& h1,
                                       unsigned& l0, unsigned& l1){
    __nv_bfloat162 hx = __floats2bfloat162_rn(v.x, v.y);
    __nv_bfloat162 hz = __floats2bfloat162_rn(v.z, v.w);
    float2 fx = __bfloat1622float2(hx);
    float2 fz = __bfloat1622float2(hz);
    __nv_bfloat162 lx = __floats2bfloat162_rn(v.x - fx.x, v.y - fx.y);
    __nv_bfloat162 lz = __floats2bfloat162_rn(v.z - fz.x, v.w - fz.y);
    h0 = *(unsigned*)&hx; h1 = *(unsigned*)&hz;
    l0 = *(unsigned*)&lx; l1 = *(unsigned*)&lz;
}
// FFMA-only exp: 2^(x*log2e) via round + degree-6 poly; no MUFU. rel err ~1.2e-7
__device__ __forceinline__ float exp_fast(float x){
    float t = x * 1.4426950408889634f;
    float r = t + 12582912.0f;
    int   n = __float_as_int(r) - 0x4B400000;
    float f = t - (r - 12582912.0f);
    float p =            1.5403530e-4f;
    p = fmaf(p, f, 1.3333558e-3f);
    p = fmaf(p, f, 9.6181291e-3f);
    p = fmaf(p, f, 5.5504109e-2f);
    p = fmaf(p, f, 2.4022651e-1f);
    p = fmaf(p, f, 6.9314718e-1f);
    p = fmaf(p, f, 1.0f);
    return __int_as_float(__float_as_int(p) + (n << 23));
}
// D += A(16x16) * B(16x8), bf16 inputs, f32 accum
__device__ __forceinline__ void mma16816(float* c, const unsigned* a, const unsigned* b){
    asm volatile("mma.sync.aligned.m16n8k16.row.col.f32.bf16.bf16.f32 "
        "{%0,%1,%2,%3},{%4,%5,%6,%7},{%8,%9},{%0,%1,%2,%3};"
        : "+f"(c[0]), "+f"(c[1]), "+f"(c[2]), "+f"(c[3])
        : "r"(a[0]), "r"(a[1]), "r"(a[2]), "r"(a[3]), "r"(b[0]), "r"(b[1]));
}

// ---------------- prologue pack kernels ----------------
// dst[n][k] (h,l) = split(src[k][n])
__global__ void packT_kernel(const float* __restrict__ src, __nv_bfloat16* __restrict__ h,
                             __nv_bfloat16* __restrict__ l, int K, int N){
    int idx = blockIdx.x*blockDim.x + threadIdx.x;
    if (idx >= K*N) return;
    int n = idx / K, k = idx % K;
    __nv_bfloat16 hh, ll; split1(src[(size_t)k*N + n], hh, ll);
    h[idx] = hh; l[idx] = ll;
}
// conv: dst[co][khw*384+ci] = split(w[co][ci][kh][kw])
__global__ void packconvT_kernel(const float* __restrict__ w, __nv_bfloat16* __restrict__ h,
                                 __nv_bfloat16* __restrict__ l){
    int idx = blockIdx.x*blockDim.x + threadIdx.x;
    if (idx >= D_*CKK) return;
    int co = idx / CKK, r = idx % CKK;
    int khw = r / D_, ci = r % D_;
    __nv_bfloat16 hh, ll; split1(w[((size_t)co*D_ + ci)*49 + khw], hh, ll);
    h[idx] = hh; l[idx] = ll;
}
__global__ void splitf_kernel(const float* __restrict__ src, __nv_bfloat16* __restrict__ h,
                              __nv_bfloat16* __restrict__ l, int n){
    int i = blockIdx.x*blockDim.x + threadIdx.x;
    if (i >= n) return;
    __nv_bfloat16 hh, ll; split1(src[i], hh, ll);
    h[i] = hh; l[i] = ll;
}
// v [bh][n][d] -> transposed split [bh][d][n]
__global__ void splitvT_kernel(const float* __restrict__ v, __nv_bfloat16* __restrict__ th,
                               __nv_bfloat16* __restrict__ tl){
    int i = blockIdx.x*blockDim.x + threadIdx.x;
    if (i >= BH_*HD_*NIN) return;
    int n  = i % NIN;
    int d  = (i / NIN) % HD_;
    int bh = i / (NIN*HD_);
    __nv_bfloat16 hh, ll; split1(v[((size_t)bh*NIN + n)*HD_ + d], hh, ll);
    th[i] = hh; tl[i] = ll;
}
__global__ void seed_kernel(const float* __restrict__ b, float* __restrict__ o, int M, int N){
    int idx = blockIdx.x*blockDim.x + threadIdx.x;
    if (idx < M*N) o[idx] = b[idx % N];
}
__global__ void zero2_kernel(float* __restrict__ a, int na, float* __restrict__ b, int nb){
    int i = blockIdx.x*blockDim.x + threadIdx.x;
    if (i < na) a[i] = 0.f;
    if (i < nb) b[i] = 0.f;
}

// ================= HMMA bf16-split dense GEMM =================
// C[M,N] = A[M,K](fp32) @ W (transposed bf16 h/l [N][K]). Tile 128x64, BK=32.
#define ASTR 40

struct Frag { unsigned ah[2][4], al[2][4], bh[4][2], bl[4][2]; };

__device__ __forceinline__ void load_frags(Frag& f, const __nv_bfloat16* Ah, const __nv_bfloat16* Al,
                                           const __nv_bfloat16* Bh, const __nv_bfloat16* Bl,
                                           int wm, int wn, int ks, int g, int c2){
    #pragma unroll
    for (int t = 0; t < 2; t++){
        int rb = (wm*32 + t*16 + g)*ASTR + ks + c2;
        f.ah[t][0] = *(const unsigned*)(Ah + rb);
        f.ah[t][1] = *(const unsigned*)(Ah + rb + 8*ASTR);
        f.ah[t][2] = *(const unsigned*)(Ah + rb + 8);
        f.ah[t][3] = *(const unsigned*)(Ah + rb + 8*ASTR + 8);
        f.al[t][0] = *(const unsigned*)(Al + rb);
        f.al[t][1] = *(const unsigned*)(Al + rb + 8*ASTR);
        f.al[t][2] = *(const unsigned*)(Al + rb + 8);
        f.al[t][3] = *(const unsigned*)(Al + rb + 8*ASTR + 8);
    }
    #pragma unroll
    for (int u = 0; u < 4; u++){
        int nb = (wn*32 + u*8 + g)*ASTR + ks + c2;
        f.bh[u][0] = *(const unsigned*)(Bh + nb);
        f.bh[u][1] = *(const unsigned*)(Bh + nb + 8);
        f.bl[u][0] = *(const unsigned*)(Bl + nb);
        f.bl[u][1] = *(const unsigned*)(Bl + nb + 8);
    }
}
__device__ __forceinline__ void do_mmas(float (*acc)[4], const Frag& f){
    #pragma unroll
    for (int t = 0; t < 2; t++)
        #pragma unroll
        for (int u = 0; u < 4; u++){
            mma16816(acc[t*4+u], f.ah[t], f.bh[u]);
            mma16816(acc[t*4+u], f.ah[t], f.bl[u]);
            mma16816(acc[t*4+u], f.al[t], f.bh[u]);
        }
}
__device__ __forceinline__ void epi(float (*acc)[4], const float* __restrict__ bias,
                                    float* __restrict__ C, int M, int N, int m0, int n0,
                                    int wm, int wn, int g, int c2, int act, int atom){
    #pragma unroll
    for (int t = 0; t < 2; t++){
        int r0 = m0 + wm*32 + t*16 + g;
        #pragma unroll
        for (int u = 0; u < 4; u++){
            int cb = n0 + wn*32 + u*8 + c2;
            float* ac = acc[t*4+u];
            if (atom){
                if (r0 < M){
                    atomicAdd(&C[(size_t)r0*N + cb],     ac[0]);
                    atomicAdd(&C[(size_t)r0*N + cb + 1], ac[1]);
                }
                if (r0 + 8 < M){
                    atomicAdd(&C[(size_t)(r0+8)*N + cb],     ac[2]);
                    atomicAdd(&C[(size_t)(r0+8)*N + cb + 1], ac[3]);
                }
            } else {
                float b0 = bias[cb], b1 = bias[cb+1];
                float o0 = ac[0]+b0, o1 = ac[1]+b1, o2 = ac[2]+b0, o3 = ac[3]+b1;
                if (act){ o0=gelu_f(o0); o1=gelu_f(o1); o2=gelu_f(o2); o3=gelu_f(o3); }
                if (r0 < M){ C[(size_t)r0*N + cb] = o0; C[(size_t)r0*N + cb + 1] = o1; }
                if (r0 + 8 < M){ C[(size_t)(r0+8)*N + cb] = o2; C[(size_t)(r0+8)*N + cb + 1] = o3; }
            }
        }
    }
}
// A-tile fill with packed split
__device__ __forceinline__ void fillA(__nv_bfloat16* Ah, __nv_bfloat16* Al,
                                      const float* __restrict__ A, int M, int K,
                                      int m0, int k0, int tid){
    #pragma unroll
    for (int i = 0; i < 4; i++){
        int e = tid + i*256;
        int row = e >> 3, kg = (e & 7)*4;
        float4 v = (m0+row < M) ? *(const float4*)(A + (size_t)(m0+row)*K + k0 + kg)
                                : make_float4(0.f,0.f,0.f,0.f);
        unsigned h0,h1,l0,l1; split4(v, h0,h1,l0,l1);
        unsigned* ph = (unsigned*)&Ah[row*ASTR + kg];
        unsigned* pl = (unsigned*)&Al[row*ASTR + kg];
        ph[0]=h0; ph[1]=h1; pl[0]=l0; pl[1]=l1;
    }
}
// B-tile fill from transposed bf16 weights (row stride Kst)
__device__ __forceinline__ void fillB(__nv_bfloat16* Bh, __nv_bfloat16* Bl,
                                      const __nv_bfloat16* __restrict__ Wh,
                                      const __nv_bfloat16* __restrict__ Wl,
                                      size_t rowbase, int Kst, int n0, int tid){
    int n  = tid >> 2;
    int kb = (tid & 3)*8;
    const unsigned* ph = (const unsigned*)Wh + ((rowbase + (size_t)(n0+n)*Kst + kb) >> 1);
    const unsigned* pl = (const unsigned*)Wl + ((rowbase + (size_t)(n0+n)*Kst + kb) >> 1);
    unsigned* sh = (unsigned*)&Bh[n*ASTR + kb];
    unsigned* sl = (unsigned*)&Bl[n*ASTR + kb];
    #pragma unroll
    for (int j = 0; j < 4; j++){ sh[j] = ph[j]; sl[j] = pl[j]; }
}

__global__ __launch_bounds__(256, 2)
void mgemm_kernel(const float* __restrict__ A, const __nv_bfloat16* __restrict__ Wh,
                  const __nv_bfloat16* __restrict__ Wl,
                  const float* __restrict__ bias, float* __restrict__ C,
                  int M, int N, int K, int kSlice, int act, int atom){
    __shared__ __align__(16) __nv_bfloat16 Ah[128*ASTR], Al[128*ASTR];
    __shared__ __align__(16) __nv_bfloat16 Bh[64*ASTR],  Bl[64*ASTR];
    int tid = threadIdx.x, lane = tid & 31, wid = tid >> 5;
    int wm = wid >> 1, wn = wid & 1;
    int g = lane >> 2, c2 = (lane & 3)*2;
    int m0 = blockIdx.y*128, n0 = blockIdx.x*64;
    int kb0 = blockIdx.z*kSlice, kend = kb0 + kSlice;
    float acc[8][4] = {};
    for (int k0 = kb0; k0 < kend; k0 += 32){
        fillA(Ah, Al, A, M, K, m0, k0, tid);
        fillB(Bh, Bl, Wh, Wl, (size_t)k0, K, n0, tid);
        __syncthreads();
        #pragma unroll
        for (int ks = 0; ks < 32; ks += 16){
            Frag f;
            load_frags(f, Ah, Al, Bh, Bl, wm, wn, ks, g, c2);
            do_mmas(acc, f);
        }
        __syncthreads();
    }
    epi(acc, bias, C, M, N, m0, n0, wm, wn, g, c2, act, atom);
}

// conv as implicit GEMM: K split over kh (grid.z = 7), atomic epilogue
__global__ __launch_bounds__(256, 2)
void mconv_kernel(const float* __restrict__ x, const __nv_bfloat16* __restrict__ Wh,
                  const __nv_bfloat16* __restrict__ Wl, float* __restrict__ C){
    __shared__ __align__(16) __nv_bfloat16 Ah[128*ASTR], Al[128*ASTR];
    __shared__ __align__(16) __nv_bfloat16 Bh[64*ASTR],  Bl[64*ASTR];
    int tid = threadIdx.x, lane = tid & 31, wid = tid >> 5;
    int wm = wid >> 1, wn = wid & 1;
    int g = lane >> 2, c2 = (lane & 3)*2;
    int m0 = blockIdx.y*128, n0 = blockIdx.x*64;
    int slice = blockIdx.z;
    float acc[8][4] = {};
    for (int kc = 0; kc < 7*D_; kc += 32){
        int khw = slice*7 + kc/D_;
        int cib = kc % D_;
        int kh = khw/7, kw = khw%7;
        #pragma unroll
        for (int i = 0; i < 4; i++){
            int e = tid + i*256;
            int row = e >> 3, kg = (e & 7)*4;
            int m = m0 + row;
            float4 v = make_float4(0.f,0.f,0.f,0.f);
            if (m < MOUT){
                int bb = m / NOUT, rr = m % NOUT;
                int oh = rr / QG, ow = rr % QG;
                int ih = oh*3 - 3 + kh, iw = ow*3 - 3 + kw;
                if ((unsigned)ih < 64u && (unsigned)iw < 64u)
                    v = *(const float4*)(x + ((size_t)(bb*NIN + ih*GW_ + iw))*D_ + cib + kg);
            }
            unsigned h0,h1,l0,l1; split4(v, h0,h1,l0,l1);
            unsigned* ph = (unsigned*)&Ah[row*ASTR + kg];
            unsigned* pl = (unsigned*)&Al[row*ASTR + kg];
            ph[0]=h0; ph[1]=h1; pl[0]=l0; pl[1]=l1;
        }
        fillB(Bh, Bl, Wh, Wl, (size_t)(khw*D_ + cib), CKK, n0, tid);
        __syncthreads();
        #pragma unroll
        for (int ks = 0; ks < 32; ks += 16){
            Frag f;
            load_frags(f, Ah, Al, Bh, Bl, wm, wn, ks, g, c2);
            do_mmas(acc, f);
        }
        __syncthreads();
    }
    epi(acc, (const float*)0, C, MOUT, D_, m0, n0, wm, wn, g, c2, 0, 1);
}

// ---------------- layernorm over D=384, optional residual-add into out -------------
__global__ void ln_kernel(const float* __restrict__ X, const float* __restrict__ g,
                          const float* __restrict__ bt, float* __restrict__ out, int add){
    int row = blockIdx.x, tid = threadIdx.x;
    float x = X[(size_t)row*D_ + tid];
    __shared__ float ws[12];
    float s = x;
    #pragma unroll
    for (int o = 16; o > 0; o >>= 1) s += __shfl_down_sync(0xffffffffu, s, o);
    if ((tid & 31) == 0) ws[tid >> 5] = s;
    __syncthreads();
    if (tid == 0){ float t = 0.f; for (int i = 0; i < 12; i++) t += ws[i]; ws[0] = t; }
    __syncthreads();
    float mu = ws[0] * (1.0f/D_);
    __syncthreads();
    float d = x - mu;
    s = d*d;
    #pragma unroll
    for (int o = 16; o > 0; o >>= 1) s += __shfl_down_sync(0xffffffffu, s, o);
    if ((tid & 31) == 0) ws[tid >> 5] = s;
    __syncthreads();
    if (tid == 0){ float t = 0.f; for (int i = 0; i < 12; i++) t += ws[i]; ws[0] = t; }
    __syncthreads();
    float var = ws[0] * (1.0f/D_);
    float y = d * rsqrtf(var + LNEPS) * g[tid] + bt[tid];
    size_t o_ = (size_t)row*D_ + tid;
    out[o_] = add ? (out[o_] + y) : y;
}

// ---------------- rotary spatial embedding ----------------
__global__ void rose_kernel(const float* __restrict__ src, int stride, int off,
                            float* __restrict__ dst, int N, int Gw, float sp0, float sp1,
                            const float* __restrict__ fr, const float* __restrict__ temp,
                            int doRot, int applyTemp){
    int idx = blockIdx.x*blockDim.x + threadIdx.x;
    int total = BH_ * N * HD_;
    if (idx >= total) return;
    int hd = idx & 31;
    int n  = (idx >> 5) % N;
    int bh = idx / (N*32);
    int h = bh % H_, b = bh / H_;
    const float* sp = src + ((size_t)b*N + n)*stride + off + h*HD_;
    float val;
    if (doRot && hd < NROT_){
        int m = hd >> 1, s = m >> 2, p = m & 3;
        float coord = (s == 0) ? (float)(n / Gw) * sp0 : (float)(n % Gw) * sp1;
        float ang = coord * fr[(h*2 + s)*4 + p];
        float cs, sn; sincosf(ang, &sn, &cs);
        float x1 = sp[2*m], x2 = sp[2*m+1];
        val = (hd & 1) ? (x1*sn + x2*cs) : (x1*cs - x2*sn);
    } else {
        val = sp[hd];
    }
    if (applyTemp) val *= temp[0];
    dst[idx] = val;
}

// ======== HMMA scores: E = exp(Q K^T), fused row-sum ========
// grid (NIN/128, 8, BH), 256 threads. 8 warps = 2(q)x4(k), warp tile 32q x 32k.
__global__ __launch_bounds__(256)
void mscore_kernel(const __nv_bfloat16* __restrict__ Qh, const __nv_bfloat16* __restrict__ Ql,
                   const __nv_bfloat16* __restrict__ Kh, const __nv_bfloat16* __restrict__ Kl,
                   float* __restrict__ E, float* __restrict__ rowsum){
    __shared__ __align__(16) __nv_bfloat16 Qhs[64*ASTR], Qls[64*ASTR];
    __shared__ __align__(16) __nv_bfloat16 Khs[128*ASTR], Kls[128*ASTR];
    __shared__ float rs[64];
    int tid = threadIdx.x, lane = tid & 31, wid = tid >> 5;
    int wq = wid >> 2, wk = wid & 3;
    int g = lane >> 2, c2 = (lane & 3)*2;
    int kt = blockIdx.x*128, q0 = blockIdx.y*64, bh = blockIdx.z;
    if (tid < 64) rs[tid] = 0.f;
    // Q fill: 64 rows x 32 d
    {
        int row = tid >> 2, kb = (tid & 3)*8;
        unsigned* sh = (unsigned*)&Qhs[row*ASTR + kb];
        unsigned* sl = (unsigned*)&Qls[row*ASTR + kb];
        if (q0 + row < NOUT){
            size_t e32 = ((size_t)(bh*NOUT + q0 + row)*HD_ + kb) >> 1;
            const unsigned* ph = (const unsigned*)Qh + e32;
            const unsigned* pl = (const unsigned*)Ql + e32;
            #pragma unroll
            for (int j = 0; j < 4; j++){ sh[j] = ph[j]; sl[j] = pl[j]; }
        } else {
            #pragma unroll
            for (int j = 0; j < 4; j++){ sh[j] = 0u; sl[j] = 0u; }
        }
    }
    // K fill: 128 rows x 32 d
    {
        int row = tid >> 1, kb = (tid & 1)*16;
        size_t e32 = ((size_t)(bh*NIN + kt + row)*HD_ + kb) >> 1;
        const unsigned* ph = (const unsigned*)Kh + e32;
        const unsigned* pl = (const unsigned*)Kl + e32;
        unsigned* sh = (unsigned*)&Khs[row*ASTR + kb];
        unsigned* sl = (unsigned*)&Kls[row*ASTR + kb];
        #pragma unroll
        for (int j = 0; j < 8; j++){ sh[j] = ph[j]; sl[j] = pl[j]; }
    }
    __syncthreads();
    float acc[2][4][4] = {};
    #pragma unroll
    for (int ks = 0; ks < 32; ks += 16){
        unsigned ah[2][4], al[2][4], bhf[4][2], blf[4][2];
        #pragma unroll
        for (int t = 0; t < 2; t++){
            int rb = (wq*32 + t*16 + g)*ASTR + ks + c2;
            ah[t][0] = *(const unsigned*)(Qhs + rb);
            ah[t][1] = *(const unsigned*)(Qhs + rb + 8*ASTR);
            ah[t][2] = *(const unsigned*)(Qhs + rb + 8);
            ah[t][3] = *(const unsigned*)(Qhs + rb + 8*ASTR + 8);
            al[t][0] = *(const unsigned*)(Qls + rb);
            al[t][1] = *(const unsigned*)(Qls + rb + 8*ASTR);
            al[t][2] = *(const unsigned*)(Qls + rb + 8);
            al[t][3] = *(const unsigned*)(Qls + rb + 8*ASTR + 8);
        }
        #pragma unroll
        for (int u = 0; u < 4; u++){
            int nb = (wk*32 + u*8 + g)*ASTR + ks + c2;
            bhf[u][0] = *(const unsigned*)(Khs + nb);
            bhf[u][1] = *(const unsigned*)(Khs + nb + 8);
            blf[u][0] = *(const unsigned*)(Kls + nb);
            blf[u][1] = *(const unsigned*)(Kls + nb + 8);
        }
        #pragma unroll
        for (int t = 0; t < 2; t++)
            #pragma unroll
            for (int u = 0; u < 4; u++){
                mma16816(acc[t][u], ah[t], bhf[u]);
                mma16816(acc[t][u], ah[t], blf[u]);
                mma16816(acc[t][u], al[t], bhf[u]);
            }
    }
    // exp + store + row-sum
    #pragma unroll
    for (int t = 0; t < 2; t++){
        int lr = wq*32 + t*16 + g;
        int r  = q0 + lr;
        float s0 = 0.f, s1 = 0.f;
        #pragma unroll
        for (int u = 0; u < 4; u++){
            int col = kt + wk*32 + u*8 + c2;
            float e0 = exp_fast(acc[t][u][0]), e1 = exp_fast(acc[t][u][1]);
            float e2 = exp_fast(acc[t][u][2]), e3 = exp_fast(acc[t][u][3]);
            if (r < NOUT){ float2 v = make_float2(e0, e1);
                *(float2*)(E + (size_t)(bh*NOUT + r)*NIN + col) = v; }
            if (r + 8 < NOUT){ float2 v = make_float2(e2, e3);
                *(float2*)(E + (size_t)(bh*NOUT + r + 8)*NIN + col) = v; }
            s0 += e0 + e1; s1 += e2 + e3;
        }
        s0 += __shfl_xor_sync(0xffffffffu, s0, 1);
        s0 += __shfl_xor_sync(0xffffffffu, s0, 2);
        s1 += __shfl_xor_sync(0xffffffffu, s1, 1);
        s1 += __shfl_xor_sync(0xffffffffu, s1, 2);
        if ((lane & 3) == 0){
            atomicAdd(&rs[lr], s0);
            atomicAdd(&rs[lr + 8], s1);
        }
    }
    __syncthreads();
    if (tid < 64 && q0 + tid < NOUT)
        atomicAdd(rowsum + bh*NOUT + q0 + tid, rs[tid]);
}

__global__ void rowinv_kernel(float* __restrict__ rowsum){
    int i = blockIdx.x*blockDim.x + threadIdx.x;
    if (i < BH_*NOUT) rowsum[i] = 1.f / rowsum[i];
}

__global__ void colsum_kernel(const float* __restrict__ E, const float* __restrict__ rinv,
                              float* __restrict__ colinv){
    int bh = blockIdx.y;
    int col = blockIdx.x*256 + threadIdx.x;
    const float* a = E + (size_t)bh*NOUT*NIN + col;
    const float* ri = rinv + bh*NOUT;
    float s = 0.f;
    #pragma unroll 4
    for (int qi = 0; qi < NOUT; qi++) s += a[(size_t)qi*NIN] * __ldg(ri + qi);
    colinv[bh*NIN + col] = 1.f / (s + EPSV);
}

// ======== HMMA PV: upd += (E*rinv*colinv) @ V, split-K=2, atomic epilogue ========
// grid (8, BH, 2), 256 threads. 8 warps = 4(q16) x 2(d16).
#define PSTR 72
__global__ __launch_bounds__(256)
void mpv_kernel(const float* __restrict__ E, const float* __restrict__ rinv,
                const float* __restrict__ colinv,
                const __nv_bfloat16* __restrict__ Vth, const __nv_bfloat16* __restrict__ Vtl,
                float* __restrict__ out){
    __shared__ __align__(16) __nv_bfloat16 Ahs[64*PSTR], Als[64*PSTR];
    __shared__ __align__(16) __nv_bfloat16 Vhs[32*PSTR], Vls[32*PSTR];
    int tid = threadIdx.x, lane = tid & 31, wid = tid >> 5;
    int wq = wid >> 1, wd = wid & 1;
    int g = lane >> 2, c2 = (lane & 3)*2;
    int q0 = blockIdx.x*64, bh = blockIdx.y;
    int ks0 = blockIdx.z*2048;
    float acc[2][4] = {};
    // preload rinv for this thread's 4 fill-rows
    int frow = tid >> 4, fcol = (tid & 15)*4;
    float rv[4];
    #pragma unroll
    for (int i = 0; i < 4; i++){
        int r = q0 + frow + i*16;
        rv[i] = (r < NOUT) ? rinv[bh*NOUT + r] : 0.f;
    }
    for (int c = 0; c < 32; c++){
        int k0 = ks0 + c*64;
        #pragma unroll
        for (int i = 0; i < 4; i++){
            int row = frow + i*16;
            int r = q0 + row;
            float4 e = (r < NOUT) ? *(const float4*)(E + (size_t)(bh*NOUT + r)*NIN + k0 + fcol)
                                  : make_float4(0.f,0.f,0.f,0.f);
            float4 cv = *(const float4*)(colinv + bh*NIN + k0 + fcol);
            float4 a;
            a.x = e.x*rv[i]*cv.x; a.y = e.y*rv[i]*cv.y;
            a.z = e.z*rv[i]*cv.z; a.w = e.w*rv[i]*cv.w;
            unsigned h0,h1,l0,l1; split4(a, h0,h1,l0,l1);
            unsigned* ph = (unsigned*)&Ahs[row*PSTR + fcol];
            unsigned* pl = (unsigned*)&Als[row*PSTR + fcol];
            ph[0]=h0; ph[1]=h1; pl[0]=l0; pl[1]=l1;
        }
        {
            int d = tid >> 3, kb = (tid & 7)*8;
            size_t e32 = ((size_t)(bh*HD_ + d)*NIN + k0 + kb) >> 1;
            const unsigned* ph = (const unsigned*)Vth + e32;
            const unsigned* pl = (const unsigned*)Vtl + e32;
            unsigned* sh = (unsigned*)&Vhs[d*PSTR + kb];
            unsigned* sl = (unsigned*)&Vls[d*PSTR + kb];
            #pragma unroll
            for (int j = 0; j < 4; j++){ sh[j] = ph[j]; sl[j] = pl[j]; }
        }
        __syncthreads();
        #pragma unroll
        for (int ks = 0; ks < 64; ks += 16){
            unsigned a_h[4], a_l[4];
            int rb = (wq*16 + g)*PSTR + ks + c2;
            a_h[0] = *(const unsigned*)(Ahs + rb);
            a_h[1] = *(const unsigned*)(Ahs + rb + 8*PSTR);
            a_h[2] = *(const unsigned*)(Ahs + rb + 8);
            a_h[3] = *(const unsigned*)(Ahs + rb + 8*PSTR + 8);
            a_l[0] = *(const unsigned*)(Als + rb);
            a_l[1] = *(const unsigned*)(Als + rb + 8*PSTR);
            a_l[2] = *(const unsigned*)(Als + rb + 8);
            a_l[3] = *(const unsigned*)(Als + rb + 8*PSTR + 8);
            #pragma unroll
            for (int u = 0; u < 2; u++){
                unsigned b_h[2], b_l[2];
                int nb = (wd*16 + u*8 + g)*PSTR + ks + c2;
                b_h[0] = *(const unsigned*)(Vhs + nb);
                b_h[1] = *(const unsigned*)(Vhs + nb + 8);
                b_l[0] = *(const unsigned*)(Vls + nb);
                b_l[1] = *(const unsigned*)(Vls + nb + 8);
                mma16816(acc[u], a_h, b_h);
                mma16816(acc[u], a_h, b_l);
                mma16816(acc[u], a_l, b_h);
            }
        }
        __syncthreads();
    }
    int b = bh / H_, h = bh % H_;
    int r0 = q0 + wq*16 + g;
    #pragma unroll
    for (int u = 0; u < 2; u++){
        int col = h*HD_ + wd*16 + u*8 + c2;
        if (r0 < NOUT){
            atomicAdd(out + (size_t)(b*NOUT + r0)*D_ + col,     acc[u][0]);
            atomicAdd(out + (size_t)(b*NOUT + r0)*D_ + col + 1, acc[u][1]);
        }
        if (r0 + 8 < NOUT){
            atomicAdd(out + (size_t)(b*NOUT + r0 + 8)*D_ + col,     acc[u][2]);
            atomicAdd(out + (size_t)(b*NOUT + r0 + 8)*D_ + col + 1, acc[u][3]);
        }
    }
}

// last iter: attn_k = E*rowinv (in place), attn_q = attn_k*colinv
__global__ void final_kernel(float* __restrict__ E, const float* __restrict__ rinv,
                             const float* __restrict__ colinv, float* __restrict__ outq){
    size_t idx = ((size_t)blockIdx.x*blockDim.x + threadIdx.x) * 4;
    if (idx >= ATTN_SZ) return;
    size_t row = idx >> 12;
    int col = (int)(idx & 4095);
    int bh = (int)(row / NOUT);
    float rvv = rinv[row];
    float4 e = *(float4*)(E + idx);
    float4 cv = *(const float4*)(colinv + bh*NIN + col);
    float4 ak, aq;
    ak.x = e.x*rvv; ak.y = e.y*rvv; ak.z = e.z*rvv; ak.w = e.w*rvv;
    aq.x = ak.x*cv.x; aq.y = ak.y*cv.y; aq.z = ak.z*cv.z; aq.w = ak.w*cv.w;
    *(float4*)(E + idx) = ak;
    *(float4*)(outq + idx) = aq;
}

__global__ void copy_kernel(const float* __restrict__ src, float* __restrict__ dst, int n){
    int idx = blockIdx.x*blockDim.x + threadIdx.x;
    if (idx < n) dst[idx] = src[idx];
}

// ---------------- host orchestration ----------------------------------------------
extern "C" void kernel_launch(void* const* d_in, const int* in_sizes, int n_in,
                              void* d_out, int out_size){
    const float* x      = (const float*)d_in[0];
    const float* conv_w = (const float*)d_in[1];
    const float* conv_b = (const float*)d_in[2];
    const float* kv_w   = (const float*)d_in[3];
    const float* kv_b   = (const float*)d_in[4];
    const float* q_w    = (const float*)d_in[5];
    const float* q_b    = (const float*)d_in[6];
    const float* w1     = (const float*)d_in[7];
    const float* b1m    = (const float*)d_in[8];
    const float* w2     = (const float*)d_in[9];
    const float* b2m    = (const float*)d_in[10];
    const float* g1     = (const float*)d_in[11];
    const float* b1_    = (const float*)d_in[12];
    const float* g2     = (const float*)d_in[13];
    const float* b2_    = (const float*)d_in[14];
    const float* g3     = (const float*)d_in[15];
    const float* b3_    = (const float*)d_in[16];
    const float* temp   = (const float*)d_in[17];
    const float* freqs  = (const float*)d_in[18];

    __nv_bfloat16 *cwh,*cwl,*kvwh,*kvwl,*qwh,*qwl,*w1h,*w1l,*w2h,*w2l;
    __nv_bfloat16 *kh,*kl,*vth,*vtl,*qh,*ql;
    float *xo,*xout,*kv,*k,*v,*qlin,*q,*attn_s,*rowsum,*colinv,*h1;
    cudaGetSymbolAddress((void**)&cwh,  g_cwh);  cudaGetSymbolAddress((void**)&cwl,  g_cwl);
    cudaGetSymbolAddress((void**)&kvwh, g_kvwh); cudaGetSymbolAddress((void**)&kvwl, g_kvwl);
    cudaGetSymbolAddress((void**)&qwh,  g_qwh);  cudaGetSymbolAddress((void**)&qwl,  g_qwl);
    cudaGetSymbolAddress((void**)&w1h,  g_w1h);  cudaGetSymbolAddress((void**)&w1l,  g_w1l);
    cudaGetSymbolAddress((void**)&w2h,  g_w2h);  cudaGetSymbolAddress((void**)&w2l,  g_w2l);
    cudaGetSymbolAddress((void**)&kh,   g_kh);   cudaGetSymbolAddress((void**)&kl,   g_kl);
    cudaGetSymbolAddress((void**)&vth,  g_vth);  cudaGetSymbolAddress((void**)&vtl,  g_vtl);
    cudaGetSymbolAddress((void**)&qh,   g_qh);   cudaGetSymbolAddress((void**)&ql,   g_ql);
    cudaGetSymbolAddress((void**)&xo,     g_xo);
    cudaGetSymbolAddress((void**)&xout,   g_xout);
    cudaGetSymbolAddress((void**)&kv,     g_kv);
    cudaGetSymbolAddress((void**)&k,      g_k);
    cudaGetSymbolAddress((void**)&v,      g_v);
    cudaGetSymbolAddress((void**)&qlin,   g_qlin);
    cudaGetSymbolAddress((void**)&q,      g_q);
    cudaGetSymbolAddress((void**)&attn_s, g_attn);
    cudaGetSymbolAddress((void**)&rowsum, g_rowsum);
    cudaGetSymbolAddress((void**)&colinv, g_colinv);
    cudaGetSymbolAddress((void**)&h1,     g_h1);

    float* out = (float*)d_out;
    bool full = (size_t)out_size >= (size_t)XOUT_SZ + 2*ATTN_SZ;
    float* out_attnq = full ? out + XOUT_SZ : attn_s;
    float* Ebuf      = full ? out + XOUT_SZ + ATTN_SZ : attn_s;  // attn_k slot holds E

    // ---- prologue: pack weights (transposed bf16 hi/lo) ----
    packconvT_kernel<<<(D_*CKK + 255)/256, 256>>>(conv_w, cwh, cwl);
    packT_kernel<<<(D_*2*D_ + 255)/256, 256>>>(kv_w, kvwh, kvwl, D_, 2*D_);
    packT_kernel<<<(D_*D_ + 255)/256, 256>>>(q_w, qwh, qwl, D_, D_);
    packT_kernel<<<(D_*4*D_ + 255)/256, 256>>>(w1, w1h, w1l, D_, 4*D_);
    packT_kernel<<<(4*D_*D_ + 255)/256, 256>>>(w2, w2h, w2l, 4*D_, D_);

    // ---- conv + first LN ----
    seed_kernel<<<(MOUT*D_ + 255)/256, 256>>>(conv_b, xo, MOUT, D_);
    mconv_kernel<<<dim3(D_/64, (MOUT+127)/128, 7), 256>>>(x, cwh, cwl, xo);
    ln_kernel<<<MOUT, D_>>>(xo, g1, b1_, xout, 0);

    // ---- kv (loop-invariant) + rose + split ----
    mgemm_kernel<<<dim3(2*D_/64, MIN_/128, 1), 256>>>(x, kvwh, kvwl, kv_b, kv, MIN_, 2*D_, D_, D_, 0, 0);
    int totk = BH_*NIN*HD_;
    rose_kernel<<<(totk+255)/256, 256>>>(kv, 2*D_, 0,  k, NIN, GW_, 1.f, 1.f, freqs, temp, 1, 1);
    rose_kernel<<<(totk+255)/256, 256>>>(kv, 2*D_, D_, v, NIN, GW_, 1.f, 1.f, freqs, temp, 0, 0);
    splitf_kernel<<<(totk+255)/256, 256>>>(k, kh, kl, totk);
    splitvT_kernel<<<(totk+255)/256, 256>>>(v, vth, vtl);

    int totq = BH_*NOUT*HD_;
    for (int it = 0; it < 3; it++){
        seed_kernel<<<(MOUT*D_ + 255)/256, 256>>>(q_b, qlin, MOUT, D_);
        mgemm_kernel<<<dim3(D_/64, (MOUT+127)/128, 2), 256>>>(xout, qwh, qwl, q_b, qlin, MOUT, D_, D_, D_/2, 0, 1);
        rose_kernel<<<(totq+255)/256, 256>>>(qlin, D_, 0, q, NOUT, QG, 3.f, 3.f, freqs, temp, 1, 0);
        splitf_kernel<<<(totq+255)/256, 256>>>(q, qh, ql, totq);

        zero2_kernel<<<(MOUT*D_ + 255)/256, 256>>>(rowsum, BH_*NOUT, xo, MOUT*D_);
        mscore_kernel<<<dim3(NIN/128, (NOUT+63)/64, BH_), 256>>>(qh, ql, kh, kl, Ebuf, rowsum);
        rowinv_kernel<<<(BH_*NOUT + 255)/256, 256>>>(rowsum);
        colsum_kernel<<<dim3(NIN/256, BH_), 256>>>(Ebuf, rowsum, colinv);
        mpv_kernel<<<dim3((NOUT+63)/64, BH_, 2), 256>>>(Ebuf, rowsum, colinv, vth, vtl, xo);
        if (it == 2 && full)
            final_kernel<<<(int)((ATTN_SZ/4 + 255)/256), 256>>>(Ebuf, rowsum, colinv, out_attnq);
        ln_kernel<<<MOUT, D_>>>(xo, g2, b2_, xout, 1);

        mgemm_kernel<<<dim3(4*D_/64, (MOUT+127)/128, 1), 256>>>(xout, w1h, w1l, b1m, h1, MOUT, 4*D_, D_, D_, 1, 0);
        seed_kernel<<<(MOUT*D_ + 255)/256, 256>>>(b2m, xo, MOUT, D_);
        mgemm_kernel<<<dim3(D_/64, (MOUT+127)/128, 2), 256>>>(h1, w2h, w2l, b2m, xo, MOUT, D_, 4*D_, 2*D_, 0, 1);
        ln_kernel<<<MOUT, D_>>>(xo, g3, b3_, xout, 1);
    }
    copy_kernel<<<(XOUT_SZ + 255)/256, 256>>>(xout, out, XOUT_SZ);
}

// round 9
// speedup vs baseline: 4.8533x; 1.1119x over previous
#include <cuda_runtime.h>
#include <cuda_bf16.h>
#include <math.h>
#include <stdint.h>

// ---------------- problem constants ----------------
#define B_    2
#define NIN   4096
#define NOUT  484
#define D_    384
#define H_    12
#define HD_   32
#define QG    22
#define GW_   64
#define MOUT  (B_*NOUT)   // 968
#define MIN_  (B_*NIN)    // 8192
#define BH_   (B_*H_)     // 24
#define NROT_ 16
#define LNEPS 1e-5f
#define EPSV  1.1920929e-07f
#define CKK   (49*D_)     // 18816 conv k-extent

#define XOUT_SZ  (MOUT*D_)                       // 371712
#define ATTN_SZ  ((size_t)BH_*NOUT*NIN)          // 47579136

// ---------------- scratch (device globals; no alloc allowed) ----------------
__device__ __nv_bfloat16 g_cwh[D_*CKK],  g_cwl[D_*CKK];       // conv w: [co][khw*384+ci]
__device__ __nv_bfloat16 g_kvwh[2*D_*D_], g_kvwl[2*D_*D_];
__device__ __nv_bfloat16 g_qwh[D_*D_],    g_qwl[D_*D_];
__device__ __nv_bfloat16 g_w1h[4*D_*D_],  g_w1l[4*D_*D_];
__device__ __nv_bfloat16 g_w2h[D_*4*D_],  g_w2l[D_*4*D_];
__device__ __nv_bfloat16 g_xh[MIN_*D_],   g_xl[MIN_*D_];       // pre-split input x
__device__ __nv_bfloat16 g_kh[BH_*NIN*HD_],  g_kl[BH_*NIN*HD_];
__device__ __nv_bfloat16 g_vth[BH_*HD_*NIN], g_vtl[BH_*HD_*NIN];  // [bh][d][n]
__device__ __nv_bfloat16 g_qh[BH_*NOUT*HD_], g_ql[BH_*NOUT*HD_];
__device__ float g_xo[MOUT*D_];
__device__ float g_xout[MOUT*D_];                 // fallback only
__device__ float g_kv[MIN_*2*D_];
__device__ float g_qlin[MOUT*D_];
__device__ float g_attn[(size_t)BH_*NOUT*NIN];    // bf16 E (iters 0,1) + fp32 fallback
__device__ float g_rowsum[BH_*NOUT];
__device__ float g_colinv[BH_*NIN];
__device__ float g_h1[MOUT*4*D_];

// ---------------- helpers ----------------
__device__ __forceinline__ float gelu_f(float x){
    return 0.5f * x * (1.0f + erff(x * 0.70710678118654752f));
}
__device__ __forceinline__ void split1(float v, __nv_bfloat16& h, __nv_bfloat16& l){
    h = __float2bfloat16(v);
    l = __float2bfloat16(v - __bfloat162float(h));
}
__device__ __forceinline__ void split4(float4 v, unsigned& h0, unsigned& h1,
                                       unsigned& l0, unsigned& l1){
    __nv_bfloat162 hx = __floats2bfloat162_rn(v.x, v.y);
    __nv_bfloat162 hz = __floats2bfloat162_rn(v.z, v.w);
    float2 fx = __bfloat1622float2(hx);
    float2 fz = __bfloat1622float2(hz);
    __nv_bfloat162 lx = __floats2bfloat162_rn(v.x - fx.x, v.y - fx.y);
    __nv_bfloat162 lz = __floats2bfloat162_rn(v.z - fz.x, v.w - fz.y);
    h0 = *(unsigned*)&hx; h1 = *(unsigned*)&hz;
    l0 = *(unsigned*)&lx; l1 = *(unsigned*)&lz;
}
// FFMA-only exp (no MUFU), rel err ~1.2e-7
__device__ __forceinline__ float exp_fast(float x){
    float t = x * 1.4426950408889634f;
    float r = t + 12582912.0f;
    int   n = __float_as_int(r) - 0x4B400000;
    float f = t - (r - 12582912.0f);
    float p =            1.5403530e-4f;
    p = fmaf(p, f, 1.3333558e-3f);
    p = fmaf(p, f, 9.6181291e-3f);
    p = fmaf(p, f, 5.5504109e-2f);
    p = fmaf(p, f, 2.4022651e-1f);
    p = fmaf(p, f, 6.9314718e-1f);
    p = fmaf(p, f, 1.0f);
    return __int_as_float(__float_as_int(p) + (n << 23));
}
__device__ __forceinline__ void mma16816(float* c, const unsigned* a, const unsigned* b){
    asm volatile("mma.sync.aligned.m16n8k16.row.col.f32.bf16.bf16.f32 "
        "{%0,%1,%2,%3},{%4,%5,%6,%7},{%8,%9},{%0,%1,%2,%3};"
        : "+f"(c[0]), "+f"(c[1]), "+f"(c[2]), "+f"(c[3])
        : "r"(a[0]), "r"(a[1]), "r"(a[2]), "r"(a[3]), "r"(b[0]), "r"(b[1]));
}

// ---------------- prologue pack kernels ----------------
__global__ void packT_kernel(const float* __restrict__ src, __nv_bfloat16* __restrict__ h,
                             __nv_bfloat16* __restrict__ l, int K, int N){
    int idx = blockIdx.x*blockDim.x + threadIdx.x;
    if (idx >= K*N) return;
    int n = idx / K, k = idx % K;
    __nv_bfloat16 hh, ll; split1(src[(size_t)k*N + n], hh, ll);
    h[idx] = hh; l[idx] = ll;
}
__global__ void packconvT_kernel(const float* __restrict__ w, __nv_bfloat16* __restrict__ h,
                                 __nv_bfloat16* __restrict__ l){
    int idx = blockIdx.x*blockDim.x + threadIdx.x;
    if (idx >= D_*CKK) return;
    int co = idx / CKK, r = idx % CKK;
    int khw = r / D_, ci = r % D_;
    __nv_bfloat16 hh, ll; split1(w[((size_t)co*D_ + ci)*49 + khw], hh, ll);
    h[idx] = hh; l[idx] = ll;
}
__global__ void splitf_kernel(const float* __restrict__ src, __nv_bfloat16* __restrict__ h,
                              __nv_bfloat16* __restrict__ l, int n){
    int i = blockIdx.x*blockDim.x + threadIdx.x;
    if (i >= n) return;
    __nv_bfloat16 hh, ll; split1(src[i], hh, ll);
    h[i] = hh; l[i] = ll;
}
__global__ void seed_kernel(const float* __restrict__ b, float* __restrict__ o, int M, int N){
    int idx = blockIdx.x*blockDim.x + threadIdx.x;
    if (idx < M*N) o[idx] = b[idx % N];
}
// per-iter prep: xo=0, qlin=q_b, rowsum=0
__global__ void prep_kernel(const float* __restrict__ qb, float* __restrict__ qlin,
                            float* __restrict__ xo, float* __restrict__ rowsum){
    int i = blockIdx.x*blockDim.x + threadIdx.x;
    if (i < MOUT*D_){ xo[i] = 0.f; qlin[i] = qb[i % D_]; }
    if (i < BH_*NOUT) rowsum[i] = 0.f;
}

// ---------------- rose (rotary) producing bf16 hi/lo directly ----------------
// k / q path: dst [bh][n][hd] split
__global__ void rose_hl_kernel(const float* __restrict__ src, int stride, int off,
                               __nv_bfloat16* __restrict__ dh, __nv_bfloat16* __restrict__ dl,
                               int N, int Gw, float sp0, float sp1,
                               const float* __restrict__ fr, const float* __restrict__ temp,
                               int applyTemp){
    int idx = blockIdx.x*blockDim.x + threadIdx.x;
    int total = BH_ * N * HD_;
    if (idx >= total) return;
    int hd = idx & 31;
    int n  = (idx >> 5) % N;
    int bh = idx / (N*32);
    int h = bh % H_, b = bh / H_;
    const float* sp = src + ((size_t)b*N + n)*stride + off + h*HD_;
    float val;
    if (hd < NROT_){
        int m = hd >> 1, s = m >> 2, p = m & 3;
        float coord = (s == 0) ? (float)(n / Gw) * sp0 : (float)(n % Gw) * sp1;
        float ang = coord * fr[(h*2 + s)*4 + p];
        float cs, sn; sincosf(ang, &sn, &cs);
        float x1 = sp[2*m], x2 = sp[2*m+1];
        val = (hd & 1) ? (x1*sn + x2*cs) : (x1*cs - x2*sn);
    } else {
        val = sp[hd];
    }
    if (applyTemp) val *= temp[0];
    __nv_bfloat16 hh, ll; split1(val, hh, ll);
    dh[idx] = hh; dl[idx] = ll;
}
// v path: no rotation, transposed dst [bh][d][n]
__global__ void vT_hl_kernel(const float* __restrict__ kv, __nv_bfloat16* __restrict__ th,
                             __nv_bfloat16* __restrict__ tl){
    int i = blockIdx.x*blockDim.x + threadIdx.x;
    if (i >= BH_*HD_*NIN) return;
    int n  = i % NIN;
    int d  = (i / NIN) % HD_;
    int bh = i / (NIN*HD_);
    int h = bh % H_, b = bh / H_;
    float v = kv[((size_t)b*NIN + n)*(2*D_) + D_ + h*HD_ + d];
    __nv_bfloat16 hh, ll; split1(v, hh, ll);
    th[i] = hh; tl[i] = ll;
}

// ================= HMMA bf16-split dense GEMM =================
#define ASTR 40

struct Frag { unsigned ah[2][4], al[2][4], bh[4][2], bl[4][2]; };

__device__ __forceinline__ void load_frags(Frag& f, const __nv_bfloat16* Ah, const __nv_bfloat16* Al,
                                           const __nv_bfloat16* Bh, const __nv_bfloat16* Bl,
                                           int wm, int wn, int ks, int g, int c2){
    #pragma unroll
    for (int t = 0; t < 2; t++){
        int rb = (wm*32 + t*16 + g)*ASTR + ks + c2;
        f.ah[t][0] = *(const unsigned*)(Ah + rb);
        f.ah[t][1] = *(const unsigned*)(Ah + rb + 8*ASTR);
        f.ah[t][2] = *(const unsigned*)(Ah + rb + 8);
        f.ah[t][3] = *(const unsigned*)(Ah + rb + 8*ASTR + 8);
        f.al[t][0] = *(const unsigned*)(Al + rb);
        f.al[t][1] = *(const unsigned*)(Al + rb + 8*ASTR);
        f.al[t][2] = *(const unsigned*)(Al + rb + 8);
        f.al[t][3] = *(const unsigned*)(Al + rb + 8*ASTR + 8);
    }
    #pragma unroll
    for (int u = 0; u < 4; u++){
        int nb = (wn*32 + u*8 + g)*ASTR + ks + c2;
        f.bh[u][0] = *(const unsigned*)(Bh + nb);
        f.bh[u][1] = *(const unsigned*)(Bh + nb + 8);
        f.bl[u][0] = *(const unsigned*)(Bl + nb);
        f.bl[u][1] = *(const unsigned*)(Bl + nb + 8);
    }
}
__device__ __forceinline__ void do_mmas(float (*acc)[4], const Frag& f){
    #pragma unroll
    for (int t = 0; t < 2; t++)
        #pragma unroll
        for (int u = 0; u < 4; u++){
            mma16816(acc[t*4+u], f.ah[t], f.bh[u]);
            mma16816(acc[t*4+u], f.ah[t], f.bl[u]);
            mma16816(acc[t*4+u], f.al[t], f.bh[u]);
        }
}
__device__ __forceinline__ void epi(float (*acc)[4], const float* __restrict__ bias,
                                    float* __restrict__ C, int M, int N, int m0, int n0,
                                    int wm, int wn, int g, int c2, int act, int atom){
    #pragma unroll
    for (int t = 0; t < 2; t++){
        int r0 = m0 + wm*32 + t*16 + g;
        #pragma unroll
        for (int u = 0; u < 4; u++){
            int cb = n0 + wn*32 + u*8 + c2;
            float* ac = acc[t*4+u];
            if (atom){
                if (r0 < M){
                    atomicAdd(&C[(size_t)r0*N + cb],     ac[0]);
                    atomicAdd(&C[(size_t)r0*N + cb + 1], ac[1]);
                }
                if (r0 + 8 < M){
                    atomicAdd(&C[(size_t)(r0+8)*N + cb],     ac[2]);
                    atomicAdd(&C[(size_t)(r0+8)*N + cb + 1], ac[3]);
                }
            } else {
                float b0 = bias[cb], b1 = bias[cb+1];
                float o0 = ac[0]+b0, o1 = ac[1]+b1, o2 = ac[2]+b0, o3 = ac[3]+b1;
                if (act){ o0=gelu_f(o0); o1=gelu_f(o1); o2=gelu_f(o2); o3=gelu_f(o3); }
                if (r0 < M){ C[(size_t)r0*N + cb] = o0; C[(size_t)r0*N + cb + 1] = o1; }
                if (r0 + 8 < M){ C[(size_t)(r0+8)*N + cb] = o2; C[(size_t)(r0+8)*N + cb + 1] = o3; }
            }
        }
    }
}
__device__ __forceinline__ void fillA(__nv_bfloat16* Ah, __nv_bfloat16* Al,
                                      const float* __restrict__ A, int M, int K,
                                      int m0, int k0, int tid){
    #pragma unroll
    for (int i = 0; i < 4; i++){
        int e = tid + i*256;
        int row = e >> 3, kg = (e & 7)*4;
        float4 v = (m0+row < M) ? *(const float4*)(A + (size_t)(m0+row)*K + k0 + kg)
                                : make_float4(0.f,0.f,0.f,0.f);
        unsigned h0,h1,l0,l1; split4(v, h0,h1,l0,l1);
        unsigned* ph = (unsigned*)&Ah[row*ASTR + kg];
        unsigned* pl = (unsigned*)&Al[row*ASTR + kg];
        ph[0]=h0; ph[1]=h1; pl[0]=l0; pl[1]=l1;
    }
}
__device__ __forceinline__ void fillB(__nv_bfloat16* Bh, __nv_bfloat16* Bl,
                                      const __nv_bfloat16* __restrict__ Wh,
                                      const __nv_bfloat16* __restrict__ Wl,
                                      size_t rowbase, int Kst, int n0, int tid){
    int n  = tid >> 2;
    int kb = (tid & 3)*8;
    const unsigned* ph = (const unsigned*)Wh + ((rowbase + (size_t)(n0+n)*Kst + kb) >> 1);
    const unsigned* pl = (const unsigned*)Wl + ((rowbase + (size_t)(n0+n)*Kst + kb) >> 1);
    unsigned* sh = (unsigned*)&Bh[n*ASTR + kb];
    unsigned* sl = (unsigned*)&Bl[n*ASTR + kb];
    #pragma unroll
    for (int j = 0; j < 4; j++){ sh[j] = ph[j]; sl[j] = pl[j]; }
}

__global__ __launch_bounds__(256, 2)
void mgemm_kernel(const float* __restrict__ A, const __nv_bfloat16* __restrict__ Wh,
                  const __nv_bfloat16* __restrict__ Wl,
                  const float* __restrict__ bias, float* __restrict__ C,
                  int M, int N, int K, int kSlice, int act, int atom){
    __shared__ __align__(16) __nv_bfloat16 Ah[128*ASTR], Al[128*ASTR];
    __shared__ __align__(16) __nv_bfloat16 Bh[64*ASTR],  Bl[64*ASTR];
    int tid = threadIdx.x, lane = tid & 31, wid = tid >> 5;
    int wm = wid >> 1, wn = wid & 1;
    int g = lane >> 2, c2 = (lane & 3)*2;
    int m0 = blockIdx.y*128, n0 = blockIdx.x*64;
    int kb0 = blockIdx.z*kSlice, kend = kb0 + kSlice;
    float acc[8][4] = {};
    for (int k0 = kb0; k0 < kend; k0 += 32){
        fillA(Ah, Al, A, M, K, m0, k0, tid);
        fillB(Bh, Bl, Wh, Wl, (size_t)k0, K, n0, tid);
        __syncthreads();
        #pragma unroll
        for (int ks = 0; ks < 32; ks += 16){
            Frag f;
            load_frags(f, Ah, Al, Bh, Bl, wm, wn, ks, g, c2);
            do_mmas(acc, f);
        }
        __syncthreads();
    }
    epi(acc, bias, C, M, N, m0, n0, wm, wn, g, c2, act, atom);
}

// A pre-split variant (for kv GEMM on x)
__global__ __launch_bounds__(256, 2)
void mgemm_pre_kernel(const __nv_bfloat16* __restrict__ Xh, const __nv_bfloat16* __restrict__ Xl,
                      const __nv_bfloat16* __restrict__ Wh, const __nv_bfloat16* __restrict__ Wl,
                      const float* __restrict__ bias, float* __restrict__ C,
                      int M, int N, int K){
    __shared__ __align__(16) __nv_bfloat16 Ah[128*ASTR], Al[128*ASTR];
    __shared__ __align__(16) __nv_bfloat16 Bh[64*ASTR],  Bl[64*ASTR];
    int tid = threadIdx.x, lane = tid & 31, wid = tid >> 5;
    int wm = wid >> 1, wn = wid & 1;
    int g = lane >> 2, c2 = (lane & 3)*2;
    int m0 = blockIdx.y*128, n0 = blockIdx.x*64;
    float acc[8][4] = {};
    for (int k0 = 0; k0 < K; k0 += 32){
        #pragma unroll
        for (int i = 0; i < 4; i++){
            int e = tid + i*256;
            int row = e >> 3, kg = (e & 7)*4;
            size_t off = (size_t)(m0+row)*K + k0 + kg;
            uint2 h = make_uint2(0u,0u), l = h;
            if (m0+row < M){
                h = *(const uint2*)(Xh + off);
                l = *(const uint2*)(Xl + off);
            }
            *(uint2*)&Ah[row*ASTR + kg] = h;
            *(uint2*)&Al[row*ASTR + kg] = l;
        }
        fillB(Bh, Bl, Wh, Wl, (size_t)k0, K, n0, tid);
        __syncthreads();
        #pragma unroll
        for (int ks = 0; ks < 32; ks += 16){
            Frag f;
            load_frags(f, Ah, Al, Bh, Bl, wm, wn, ks, g, c2);
            do_mmas(acc, f);
        }
        __syncthreads();
    }
    epi(acc, bias, C, M, N, m0, n0, wm, wn, g, c2, 0, 0);
}

// conv implicit GEMM with pre-split x; grid.z = 7 kh-slices, atomic epilogue
__global__ __launch_bounds__(256, 2)
void mconv_kernel(const __nv_bfloat16* __restrict__ Xh, const __nv_bfloat16* __restrict__ Xl,
                  const __nv_bfloat16* __restrict__ Wh, const __nv_bfloat16* __restrict__ Wl,
                  float* __restrict__ C){
    __shared__ __align__(16) __nv_bfloat16 Ah[128*ASTR], Al[128*ASTR];
    __shared__ __align__(16) __nv_bfloat16 Bh[64*ASTR],  Bl[64*ASTR];
    int tid = threadIdx.x, lane = tid & 31, wid = tid >> 5;
    int wm = wid >> 1, wn = wid & 1;
    int g = lane >> 2, c2 = (lane & 3)*2;
    int m0 = blockIdx.y*128, n0 = blockIdx.x*64;
    int slice = blockIdx.z;
    float acc[8][4] = {};
    for (int kc = 0; kc < 7*D_; kc += 32){
        int khw = slice*7 + kc/D_;
        int cib = kc % D_;
        int kh = khw/7, kw = khw%7;
        #pragma unroll
        for (int i = 0; i < 4; i++){
            int e = tid + i*256;
            int row = e >> 3, kg = (e & 7)*4;
            int m = m0 + row;
            uint2 h = make_uint2(0u,0u), l = h;
            if (m < MOUT){
                int bb = m / NOUT, rr = m % NOUT;
                int oh = rr / QG, ow = rr % QG;
                int ih = oh*3 - 3 + kh, iw = ow*3 - 3 + kw;
                if ((unsigned)ih < 64u && (unsigned)iw < 64u){
                    size_t off = ((size_t)(bb*NIN + ih*GW_ + iw))*D_ + cib + kg;
                    h = *(const uint2*)(Xh + off);
                    l = *(const uint2*)(Xl + off);
                }
            }
            *(uint2*)&Ah[row*ASTR + kg] = h;
            *(uint2*)&Al[row*ASTR + kg] = l;
        }
        fillB(Bh, Bl, Wh, Wl, (size_t)(khw*D_ + cib), CKK, n0, tid);
        __syncthreads();
        #pragma unroll
        for (int ks = 0; ks < 32; ks += 16){
            Frag f;
            load_frags(f, Ah, Al, Bh, Bl, wm, wn, ks, g, c2);
            do_mmas(acc, f);
        }
        __syncthreads();
    }
    epi(acc, (const float*)0, C, MOUT, D_, m0, n0, wm, wn, g, c2, 0, 1);
}

// ---------------- one-pass layernorm over D=384, optional residual-add -------------
__global__ void ln_kernel(const float* __restrict__ X, const float* __restrict__ g,
                          const float* __restrict__ bt, float* __restrict__ out, int add){
    int row = blockIdx.x, tid = threadIdx.x;
    float x = X[(size_t)row*D_ + tid];
    __shared__ float w1s[12], w2s[12];
    float s1 = x, s2 = x*x;
    #pragma unroll
    for (int o = 16; o > 0; o >>= 1){
        s1 += __shfl_down_sync(0xffffffffu, s1, o);
        s2 += __shfl_down_sync(0xffffffffu, s2, o);
    }
    if ((tid & 31) == 0){ w1s[tid >> 5] = s1; w2s[tid >> 5] = s2; }
    __syncthreads();
    if (tid == 0){
        float t1 = 0.f, t2 = 0.f;
        #pragma unroll
        for (int i = 0; i < 12; i++){ t1 += w1s[i]; t2 += w2s[i]; }
        w1s[0] = t1; w2s[0] = t2;
    }
    __syncthreads();
    float mu  = w1s[0] * (1.0f/D_);
    float var = w2s[0] * (1.0f/D_) - mu*mu;
    float y = (x - mu) * rsqrtf(var + LNEPS) * g[tid] + bt[tid];
    size_t o_ = (size_t)row*D_ + tid;
    out[o_] = add ? (out[o_] + y) : y;
}

// ======== HMMA scores: E = exp(Q K^T), fused row-sum; bf16 or fp32 E store ========
__global__ __launch_bounds__(256)
void mscore_kernel(const __nv_bfloat16* __restrict__ Qh, const __nv_bfloat16* __restrict__ Ql,
                   const __nv_bfloat16* __restrict__ Kh, const __nv_bfloat16* __restrict__ Kl,
                   float* __restrict__ Ef, __nv_bfloat16* __restrict__ Eb, int usebf,
                   float* __restrict__ rowsum){
    __shared__ __align__(16) __nv_bfloat16 Qhs[64*ASTR], Qls[64*ASTR];
    __shared__ __align__(16) __nv_bfloat16 Khs[128*ASTR], Kls[128*ASTR];
    __shared__ float rs[64];
    int tid = threadIdx.x, lane = tid & 31, wid = tid >> 5;
    int wq = wid >> 2, wk = wid & 3;
    int g = lane >> 2, c2 = (lane & 3)*2;
    int kt = blockIdx.x*128, q0 = blockIdx.y*64, bh = blockIdx.z;
    if (tid < 64) rs[tid] = 0.f;
    {
        int row = tid >> 2, kb = (tid & 3)*8;
        unsigned* sh = (unsigned*)&Qhs[row*ASTR + kb];
        unsigned* sl = (unsigned*)&Qls[row*ASTR + kb];
        if (q0 + row < NOUT){
            size_t e32 = ((size_t)(bh*NOUT + q0 + row)*HD_ + kb) >> 1;
            const unsigned* ph = (const unsigned*)Qh + e32;
            const unsigned* pl = (const unsigned*)Ql + e32;
            #pragma unroll
            for (int j = 0; j < 4; j++){ sh[j] = ph[j]; sl[j] = pl[j]; }
        } else {
            #pragma unroll
            for (int j = 0; j < 4; j++){ sh[j] = 0u; sl[j] = 0u; }
        }
    }
    {
        int row = tid >> 1, kb = (tid & 1)*16;
        size_t e32 = ((size_t)(bh*NIN + kt + row)*HD_ + kb) >> 1;
        const unsigned* ph = (const unsigned*)Kh + e32;
        const unsigned* pl = (const unsigned*)Kl + e32;
        unsigned* sh = (unsigned*)&Khs[row*ASTR + kb];
        unsigned* sl = (unsigned*)&Kls[row*ASTR + kb];
        #pragma unroll
        for (int j = 0; j < 8; j++){ sh[j] = ph[j]; sl[j] = pl[j]; }
    }
    __syncthreads();
    float acc[2][4][4] = {};
    #pragma unroll
    for (int ks = 0; ks < 32; ks += 16){
        unsigned ah[2][4], al[2][4], bhf[4][2], blf[4][2];
        #pragma unroll
        for (int t = 0; t < 2; t++){
            int rb = (wq*32 + t*16 + g)*ASTR + ks + c2;
            ah[t][0] = *(const unsigned*)(Qhs + rb);
            ah[t][1] = *(const unsigned*)(Qhs + rb + 8*ASTR);
            ah[t][2] = *(const unsigned*)(Qhs + rb + 8);
            ah[t][3] = *(const unsigned*)(Qhs + rb + 8*ASTR + 8);
            al[t][0] = *(const unsigned*)(Qls + rb);
            al[t][1] = *(const unsigned*)(Qls + rb + 8*ASTR);
            al[t][2] = *(const unsigned*)(Qls + rb + 8);
            al[t][3] = *(const unsigned*)(Qls + rb + 8*ASTR + 8);
        }
        #pragma unroll
        for (int u = 0; u < 4; u++){
            int nb = (wk*32 + u*8 + g)*ASTR + ks + c2;
            bhf[u][0] = *(const unsigned*)(Khs + nb);
            bhf[u][1] = *(const unsigned*)(Khs + nb + 8);
            blf[u][0] = *(const unsigned*)(Kls + nb);
            blf[u][1] = *(const unsigned*)(Kls + nb + 8);
        }
        #pragma unroll
        for (int t = 0; t < 2; t++)
            #pragma unroll
            for (int u = 0; u < 4; u++){
                mma16816(acc[t][u], ah[t], bhf[u]);
                mma16816(acc[t][u], ah[t], blf[u]);
                mma16816(acc[t][u], al[t], bhf[u]);
            }
    }
    #pragma unroll
    for (int t = 0; t < 2; t++){
        int lr = wq*32 + t*16 + g;
        int r  = q0 + lr;
        float s0 = 0.f, s1 = 0.f;
        #pragma unroll
        for (int u = 0; u < 4; u++){
            int col = kt + wk*32 + u*8 + c2;
            float e0 = exp_fast(acc[t][u][0]), e1 = exp_fast(acc[t][u][1]);
            float e2 = exp_fast(acc[t][u][2]), e3 = exp_fast(acc[t][u][3]);
            if (usebf){
                __nv_bfloat162 v0 = __floats2bfloat162_rn(e0, e1);
                __nv_bfloat162 v1 = __floats2bfloat162_rn(e2, e3);
                if (r < NOUT)
                    *(__nv_bfloat162*)(Eb + (size_t)(bh*NOUT + r)*NIN + col) = v0;
                if (r + 8 < NOUT)
                    *(__nv_bfloat162*)(Eb + (size_t)(bh*NOUT + r + 8)*NIN + col) = v1;
            } else {
                if (r < NOUT)
                    *(float2*)(Ef + (size_t)(bh*NOUT + r)*NIN + col) = make_float2(e0, e1);
                if (r + 8 < NOUT)
                    *(float2*)(Ef + (size_t)(bh*NOUT + r + 8)*NIN + col) = make_float2(e2, e3);
            }
            s0 += e0 + e1; s1 += e2 + e3;
        }
        s0 += __shfl_xor_sync(0xffffffffu, s0, 1);
        s0 += __shfl_xor_sync(0xffffffffu, s0, 2);
        s1 += __shfl_xor_sync(0xffffffffu, s1, 1);
        s1 += __shfl_xor_sync(0xffffffffu, s1, 2);
        if ((lane & 3) == 0){
            atomicAdd(&rs[lr], s0);
            atomicAdd(&rs[lr + 8], s1);
        }
    }
    __syncthreads();
    if (tid < 64 && q0 + tid < NOUT)
        atomicAdd(rowsum + bh*NOUT + q0 + tid, rs[tid]);
}

__global__ void rowinv_kernel(float* __restrict__ rowsum){
    int i = blockIdx.x*blockDim.x + threadIdx.x;
    if (i < BH_*NOUT) rowsum[i] = 1.f / rowsum[i];
}

__global__ void colsum_kernel(const float* __restrict__ Ef, const __nv_bfloat16* __restrict__ Eb,
                              int usebf, const float* __restrict__ rinv,
                              float* __restrict__ colinv){
    int bh = blockIdx.y;
    int col = blockIdx.x*256 + threadIdx.x;
    const float* ri = rinv + bh*NOUT;
    float s = 0.f;
    if (usebf){
        const __nv_bfloat16* a = Eb + (size_t)bh*NOUT*NIN + col;
        #pragma unroll 4
        for (int qi = 0; qi < NOUT; qi++)
            s += __bfloat162float(a[(size_t)qi*NIN]) * __ldg(ri + qi);
    } else {
        const float* a = Ef + (size_t)bh*NOUT*NIN + col;
        #pragma unroll 4
        for (int qi = 0; qi < NOUT; qi++)
            s += a[(size_t)qi*NIN] * __ldg(ri + qi);
    }
    colinv[bh*NIN + col] = 1.f / (s + EPSV);
}

// ======== HMMA PV: upd += (E*rinv*colinv) @ V, split-K=4, atomic epilogue ========
#define PSTR 72
__global__ __launch_bounds__(256)
void mpv_kernel(const float* __restrict__ Ef, const __nv_bfloat16* __restrict__ Eb, int usebf,
                const float* __restrict__ rinv, const float* __restrict__ colinv,
                const __nv_bfloat16* __restrict__ Vth, const __nv_bfloat16* __restrict__ Vtl,
                float* __restrict__ out){
    __shared__ __align__(16) __nv_bfloat16 Ahs[64*PSTR], Als[64*PSTR];
    __shared__ __align__(16) __nv_bfloat16 Vhs[32*PSTR], Vls[32*PSTR];
    int tid = threadIdx.x, lane = tid & 31, wid = tid >> 5;
    int wq = wid >> 1, wd = wid & 1;
    int g = lane >> 2, c2 = (lane & 3)*2;
    int q0 = blockIdx.x*64, bh = blockIdx.y;
    int ks0 = blockIdx.z*1024;
    float acc[2][4] = {};
    int frow = tid >> 4, fcol = (tid & 15)*4;
    float rv[4];
    #pragma unroll
    for (int i = 0; i < 4; i++){
        int r = q0 + frow + i*16;
        rv[i] = (r < NOUT) ? rinv[bh*NOUT + r] : 0.f;
    }
    for (int c = 0; c < 16; c++){
        int k0 = ks0 + c*64;
        #pragma unroll
        for (int i = 0; i < 4; i++){
            int row = frow + i*16;
            int r = q0 + row;
            float4 e = make_float4(0.f,0.f,0.f,0.f);
            if (r < NOUT){
                size_t base = (size_t)(bh*NOUT + r)*NIN + k0 + fcol;
                if (usebf){
                    uint2 u = *(const uint2*)(Eb + base);
                    float2 f0 = __bfloat1622float2(*(__nv_bfloat162*)&u.x);
                    float2 f1 = __bfloat1622float2(*(__nv_bfloat162*)&u.y);
                    e = make_float4(f0.x, f0.y, f1.x, f1.y);
                } else {
                    e = *(const float4*)(Ef + base);
                }
            }
            float4 cv = *(const float4*)(colinv + bh*NIN + k0 + fcol);
            float4 a;
            a.x = e.x*rv[i]*cv.x; a.y = e.y*rv[i]*cv.y;
            a.z = e.z*rv[i]*cv.z; a.w = e.w*rv[i]*cv.w;
            unsigned h0,h1,l0,l1; split4(a, h0,h1,l0,l1);
            unsigned* ph = (unsigned*)&Ahs[row*PSTR + fcol];
            unsigned* pl = (unsigned*)&Als[row*PSTR + fcol];
            ph[0]=h0; ph[1]=h1; pl[0]=l0; pl[1]=l1;
        }
        {
            int d = tid >> 3, kb = (tid & 7)*8;
            size_t e32 = ((size_t)(bh*HD_ + d)*NIN + k0 + kb) >> 1;
            const unsigned* ph = (const unsigned*)Vth + e32;
            const unsigned* pl = (const unsigned*)Vtl + e32;
            unsigned* sh = (unsigned*)&Vhs[d*PSTR + kb];
            unsigned* sl = (unsigned*)&Vls[d*PSTR + kb];
            #pragma unroll
            for (int j = 0; j < 4; j++){ sh[j] = ph[j]; sl[j] = pl[j]; }
        }
        __syncthreads();
        #pragma unroll
        for (int ks = 0; ks < 64; ks += 16){
            unsigned a_h[4], a_l[4];
            int rb = (wq*16 + g)*PSTR + ks + c2;
            a_h[0] = *(const unsigned*)(Ahs + rb);
            a_h[1] = *(const unsigned*)(Ahs + rb + 8*PSTR);
            a_h[2] = *(const unsigned*)(Ahs + rb + 8);
            a_h[3] = *(const unsigned*)(Ahs + rb + 8*PSTR + 8);
            a_l[0] = *(const unsigned*)(Als + rb);
            a_l[1] = *(const unsigned*)(Als + rb + 8*PSTR);
            a_l[2] = *(const unsigned*)(Als + rb + 8);
            a_l[3] = *(const unsigned*)(Als + rb + 8*PSTR + 8);
            #pragma unroll
            for (int u = 0; u < 2; u++){
                unsigned b_h[2], b_l[2];
                int nb = (wd*16 + u*8 + g)*PSTR + ks + c2;
                b_h[0] = *(const unsigned*)(Vhs + nb);
                b_h[1] = *(const unsigned*)(Vhs + nb + 8);
                b_l[0] = *(const unsigned*)(Vls + nb);
                b_l[1] = *(const unsigned*)(Vls + nb + 8);
                mma16816(acc[u], a_h, b_h);
                mma16816(acc[u], a_h, b_l);
                mma16816(acc[u], a_l, b_h);
            }
        }
        __syncthreads();
    }
    int b = bh / H_, h = bh % H_;
    int r0 = q0 + wq*16 + g;
    #pragma unroll
    for (int u = 0; u < 2; u++){
        int col = h*HD_ + wd*16 + u*8 + c2;
        if (r0 < NOUT){
            atomicAdd(out + (size_t)(b*NOUT + r0)*D_ + col,     acc[u][0]);
            atomicAdd(out + (size_t)(b*NOUT + r0)*D_ + col + 1, acc[u][1]);
        }
        if (r0 + 8 < NOUT){
            atomicAdd(out + (size_t)(b*NOUT + r0 + 8)*D_ + col,     acc[u][2]);
            atomicAdd(out + (size_t)(b*NOUT + r0 + 8)*D_ + col + 1, acc[u][3]);
        }
    }
}

// last iter: attn_k = E*rowinv (in place), attn_q = attn_k*colinv
__global__ void final_kernel(float* __restrict__ E, const float* __restrict__ rinv,
                             const float* __restrict__ colinv, float* __restrict__ outq){
    size_t idx = ((size_t)blockIdx.x*blockDim.x + threadIdx.x) * 4;
    if (idx >= ATTN_SZ) return;
    size_t row = idx >> 12;
    int col = (int)(idx & 4095);
    int bh = (int)(row / NOUT);
    float rvv = rinv[row];
    float4 e = *(float4*)(E + idx);
    float4 cv = *(const float4*)(colinv + bh*NIN + col);
    float4 ak, aq;
    ak.x = e.x*rvv; ak.y = e.y*rvv; ak.z = e.z*rvv; ak.w = e.w*rvv;
    aq.x = ak.x*cv.x; aq.y = ak.y*cv.y; aq.z = ak.z*cv.z; aq.w = ak.w*cv.w;
    *(float4*)(E + idx) = ak;
    *(float4*)(outq + idx) = aq;
}

// ---------------- host orchestration ----------------------------------------------
extern "C" void kernel_launch(void* const* d_in, const int* in_sizes, int n_in,
                              void* d_out, int out_size){
    const float* x      = (const float*)d_in[0];
    const float* conv_w = (const float*)d_in[1];
    const float* conv_b = (const float*)d_in[2];
    const float* kv_w   = (const float*)d_in[3];
    const float* kv_b   = (const float*)d_in[4];
    const float* q_w    = (const float*)d_in[5];
    const float* q_b    = (const float*)d_in[6];
    const float* w1     = (const float*)d_in[7];
    const float* b1m    = (const float*)d_in[8];
    const float* w2     = (const float*)d_in[9];
    const float* b2m    = (const float*)d_in[10];
    const float* g1     = (const float*)d_in[11];
    const float* b1_    = (const float*)d_in[12];
    const float* g2     = (const float*)d_in[13];
    const float* b2_    = (const float*)d_in[14];
    const float* g3     = (const float*)d_in[15];
    const float* b3_    = (const float*)d_in[16];
    const float* temp   = (const float*)d_in[17];
    const float* freqs  = (const float*)d_in[18];

    __nv_bfloat16 *cwh,*cwl,*kvwh,*kvwl,*qwh,*qwl,*w1h,*w1l,*w2h,*w2l;
    __nv_bfloat16 *xh,*xl,*kh,*kl,*vth,*vtl,*qh,*ql;
    float *xo,*xoutg,*kv,*qlin,*attn_s,*rowsum,*colinv,*h1;
    cudaGetSymbolAddress((void**)&cwh,  g_cwh);  cudaGetSymbolAddress((void**)&cwl,  g_cwl);
    cudaGetSymbolAddress((void**)&kvwh, g_kvwh); cudaGetSymbolAddress((void**)&kvwl, g_kvwl);
    cudaGetSymbolAddress((void**)&qwh,  g_qwh);  cudaGetSymbolAddress((void**)&qwl,  g_qwl);
    cudaGetSymbolAddress((void**)&w1h,  g_w1h);  cudaGetSymbolAddress((void**)&w1l,  g_w1l);
    cudaGetSymbolAddress((void**)&w2h,  g_w2h);  cudaGetSymbolAddress((void**)&w2l,  g_w2l);
    cudaGetSymbolAddress((void**)&xh,   g_xh);   cudaGetSymbolAddress((void**)&xl,   g_xl);
    cudaGetSymbolAddress((void**)&kh,   g_kh);   cudaGetSymbolAddress((void**)&kl,   g_kl);
    cudaGetSymbolAddress((void**)&vth,  g_vth);  cudaGetSymbolAddress((void**)&vtl,  g_vtl);
    cudaGetSymbolAddress((void**)&qh,   g_qh);   cudaGetSymbolAddress((void**)&ql,   g_ql);
    cudaGetSymbolAddress((void**)&xo,     g_xo);
    cudaGetSymbolAddress((void**)&xoutg,  g_xout);
    cudaGetSymbolAddress((void**)&kv,     g_kv);
    cudaGetSymbolAddress((void**)&qlin,   g_qlin);
    cudaGetSymbolAddress((void**)&attn_s, g_attn);
    cudaGetSymbolAddress((void**)&rowsum, g_rowsum);
    cudaGetSymbolAddress((void**)&colinv, g_colinv);
    cudaGetSymbolAddress((void**)&h1,     g_h1);

    float* out = (float*)d_out;
    bool full = (size_t)out_size >= (size_t)XOUT_SZ + 2*ATTN_SZ;
    float* xout      = full ? out : xoutg;            // x_out written in place
    float* out_attnq = full ? out + XOUT_SZ : attn_s;
    float* Ef        = full ? out + XOUT_SZ + ATTN_SZ : attn_s;  // fp32 E (iter 2)
    __nv_bfloat16* Eb = (__nv_bfloat16*)attn_s;                  // bf16 E (iters 0,1)

    // ---- prologue: pack weights + pre-split x ----
    packconvT_kernel<<<(D_*CKK + 255)/256, 256>>>(conv_w, cwh, cwl);
    packT_kernel<<<(D_*2*D_ + 255)/256, 256>>>(kv_w, kvwh, kvwl, D_, 2*D_);
    packT_kernel<<<(D_*D_ + 255)/256, 256>>>(q_w, qwh, qwl, D_, D_);
    packT_kernel<<<(D_*4*D_ + 255)/256, 256>>>(w1, w1h, w1l, D_, 4*D_);
    packT_kernel<<<(4*D_*D_ + 255)/256, 256>>>(w2, w2h, w2l, 4*D_, D_);
    splitf_kernel<<<(MIN_*D_ + 255)/256, 256>>>(x, xh, xl, MIN_*D_);

    // ---- conv + first LN ----
    seed_kernel<<<(MOUT*D_ + 255)/256, 256>>>(conv_b, xo, MOUT, D_);
    mconv_kernel<<<dim3(D_/64, (MOUT+127)/128, 7), 256>>>(xh, xl, cwh, cwl, xo);
    ln_kernel<<<MOUT, D_>>>(xo, g1, b1_, xout, 0);

    // ---- kv (loop-invariant) + rose-split ----
    mgemm_pre_kernel<<<dim3(2*D_/64, MIN_/128), 256>>>(xh, xl, kvwh, kvwl, kv_b, kv, MIN_, 2*D_, D_);
    int totk = BH_*NIN*HD_;
    rose_hl_kernel<<<(totk+255)/256, 256>>>(kv, 2*D_, 0, kh, kl, NIN, GW_, 1.f, 1.f, freqs, temp, 1);
    vT_hl_kernel<<<(totk+255)/256, 256>>>(kv, vth, vtl);

    int totq = BH_*NOUT*HD_;
    for (int it = 0; it < 3; it++){
        int usebf = (it < 2) ? 1 : 0;
        float* Ecur = usebf ? (float*)0 : Ef;
        prep_kernel<<<(MOUT*D_ + 255)/256, 256>>>(q_b, qlin, xo, rowsum);
        mgemm_kernel<<<dim3(D_/64, (MOUT+127)/128, 2), 256>>>(xout, qwh, qwl, q_b, qlin, MOUT, D_, D_, D_/2, 0, 1);
        rose_hl_kernel<<<(totq+255)/256, 256>>>(qlin, D_, 0, qh, ql, NOUT, QG, 3.f, 3.f, freqs, temp, 0);

        mscore_kernel<<<dim3(NIN/128, (NOUT+63)/64, BH_), 256>>>(qh, ql, kh, kl, Ecur, Eb, usebf, rowsum);
        rowinv_kernel<<<(BH_*NOUT + 255)/256, 256>>>(rowsum);
        colsum_kernel<<<dim3(NIN/256, BH_), 256>>>(Ecur, Eb, usebf, rowsum, colinv);
        mpv_kernel<<<dim3((NOUT+63)/64, BH_, 4), 256>>>(Ecur, Eb, usebf, rowsum, colinv, vth, vtl, xo);
        if (it == 2 && full)
            final_kernel<<<(int)((ATTN_SZ/4 + 255)/256), 256>>>(Ef, rowsum, colinv, out_attnq);
        ln_kernel<<<MOUT, D_>>>(xo, g2, b2_, xout, 1);

        mgemm_kernel<<<dim3(4*D_/64, (MOUT+127)/128, 1), 256>>>(xout, w1h, w1l, b1m, h1, MOUT, 4*D_, D_, D_, 1, 0);
        seed_kernel<<<(MOUT*D_ + 255)/256, 256>>>(b2m, xo, MOUT, D_);
        mgemm_kernel<<<dim3(D_/64, (MOUT+127)/128, 2), 256>>>(h1, w2h, w2l, b2m, xo, MOUT, D_, 4*D_, 2*D_, 0, 1);
        ln_kernel<<<MOUT, D_>>>(xo, g3, b3_, xout, 1);
    }
}

// round 10
// speedup vs baseline: 4.9383x; 1.0175x over previous
#include <cuda_runtime.h>
#include <cuda_bf16.h>
#include <cuda_fp16.h>
#include <math.h>
#include <stdint.h>

// ---------------- problem constants ----------------
#define B_    2
#define NIN   4096
#define NOUT  484
#define D_    384
#define H_    12
#define HD_   32
#define QG    22
#define GW_   64
#define MOUT  (B_*NOUT)   // 968
#define MIN_  (B_*NIN)    // 8192
#define BH_   (B_*H_)     // 24
#define NROT_ 16
#define LNEPS 1e-5f
#define EPSV  1.1920929e-07f
#define CKK   (49*D_)     // 18816 conv k-extent

#define XOUT_SZ  (MOUT*D_)                       // 371712
#define ATTN_SZ  ((size_t)BH_*NOUT*NIN)          // 47579136

// ---------------- scratch (device globals; no alloc allowed) ----------------
__device__ __nv_bfloat16 g_cwh[D_*CKK],  g_cwl[D_*CKK];       // conv w: [co][khw*384+ci]
__device__ __nv_bfloat16 g_kvwh[2*D_*D_], g_kvwl[2*D_*D_];
__device__ __nv_bfloat16 g_qwh[D_*D_],    g_qwl[D_*D_];
__device__ __nv_bfloat16 g_w1h[4*D_*D_],  g_w1l[4*D_*D_];
__device__ __nv_bfloat16 g_w2h[D_*4*D_],  g_w2l[D_*4*D_];
__device__ __nv_bfloat16 g_xh[MIN_*D_],   g_xl[MIN_*D_];       // pre-split input x
__device__ __nv_bfloat16 g_kh[BH_*NIN*HD_],  g_kl[BH_*NIN*HD_];
__device__ __nv_bfloat16 g_vth[BH_*HD_*NIN], g_vtl[BH_*HD_*NIN];  // [bh][d][n]
__device__ __nv_bfloat16 g_qh[BH_*NOUT*HD_], g_ql[BH_*NOUT*HD_];
__device__ float g_xo[MOUT*D_];
__device__ float g_xout[MOUT*D_];                 // fallback only
__device__ float g_kv[MIN_*2*D_];
__device__ float g_qlin[MOUT*D_];
__device__ float g_attn[(size_t)BH_*NOUT*NIN];    // fp16 (E-1) store + fallback region
__device__ float g_rowsum[BH_*NOUT];
__device__ float g_colinv[BH_*NIN];
__device__ float g_h1[MOUT*4*D_];

// ---------------- helpers ----------------
__device__ __forceinline__ float gelu_f(float x){
    return 0.5f * x * (1.0f + erff(x * 0.70710678118654752f));
}
__device__ __forceinline__ void split1(float v, __nv_bfloat16& h, __nv_bfloat16& l){
    h = __float2bfloat16(v);
    l = __float2bfloat16(v - __bfloat162float(h));
}
__device__ __forceinline__ void split4(float4 v, unsigned& h0, unsigned& h1,
                                       unsigned& l0, unsigned& l1){
    __nv_bfloat162 hx = __floats2bfloat162_rn(v.x, v.y);
    __nv_bfloat162 hz = __floats2bfloat162_rn(v.z, v.w);
    float2 fx = __bfloat1622float2(hx);
    float2 fz = __bfloat1622float2(hz);
    __nv_bfloat162 lx = __floats2bfloat162_rn(v.x - fx.x, v.y - fx.y);
    __nv_bfloat162 lz = __floats2bfloat162_rn(v.z - fz.x, v.w - fz.y);
    h0 = *(unsigned*)&hx; h1 = *(unsigned*)&hz;
    l0 = *(unsigned*)&lx; l1 = *(unsigned*)&lz;
}
// FFMA-only exp (no MUFU), rel err ~1.2e-7
__device__ __forceinline__ float exp_fast(float x){
    float t = x * 1.4426950408889634f;
    float r = t + 12582912.0f;
    int   n = __float_as_int(r) - 0x4B400000;
    float f = t - (r - 12582912.0f);
    float p =            1.5403530e-4f;
    p = fmaf(p, f, 1.3333558e-3f);
    p = fmaf(p, f, 9.6181291e-3f);
    p = fmaf(p, f, 5.5504109e-2f);
    p = fmaf(p, f, 2.4022651e-1f);
    p = fmaf(p, f, 6.9314718e-1f);
    p = fmaf(p, f, 1.0f);
    return __int_as_float(__float_as_int(p) + (n << 23));
}
__device__ __forceinline__ void mma16816(float* c, const unsigned* a, const unsigned* b){
    asm volatile("mma.sync.aligned.m16n8k16.row.col.f32.bf16.bf16.f32 "
        "{%0,%1,%2,%3},{%4,%5,%6,%7},{%8,%9},{%0,%1,%2,%3};"
        : "+f"(c[0]), "+f"(c[1]), "+f"(c[2]), "+f"(c[3])
        : "r"(a[0]), "r"(a[1]), "r"(a[2]), "r"(a[3]), "r"(b[0]), "r"(b[1]));
}

// ---------------- prologue pack kernels ----------------
__global__ void packT_kernel(const float* __restrict__ src, __nv_bfloat16* __restrict__ h,
                             __nv_bfloat16* __restrict__ l, int K, int N){
    int idx = blockIdx.x*blockDim.x + threadIdx.x;
    if (idx >= K*N) return;
    int n = idx / K, k = idx % K;
    __nv_bfloat16 hh, ll; split1(src[(size_t)k*N + n], hh, ll);
    h[idx] = hh; l[idx] = ll;
}
__global__ void packconvT_kernel(const float* __restrict__ w, __nv_bfloat16* __restrict__ h,
                                 __nv_bfloat16* __restrict__ l){
    int idx = blockIdx.x*blockDim.x + threadIdx.x;
    if (idx >= D_*CKK) return;
    int co = idx / CKK, r = idx % CKK;
    int khw = r / D_, ci = r % D_;
    __nv_bfloat16 hh, ll; split1(w[((size_t)co*D_ + ci)*49 + khw], hh, ll);
    h[idx] = hh; l[idx] = ll;
}
__global__ void splitf_kernel(const float* __restrict__ src, __nv_bfloat16* __restrict__ h,
                              __nv_bfloat16* __restrict__ l, int n){
    int i = blockIdx.x*blockDim.x + threadIdx.x;
    if (i >= n) return;
    __nv_bfloat16 hh, ll; split1(src[i], hh, ll);
    h[i] = hh; l[i] = ll;
}
__global__ void seed_kernel(const float* __restrict__ b, float* __restrict__ o, int M, int N){
    int idx = blockIdx.x*blockDim.x + threadIdx.x;
    if (idx < M*N) o[idx] = b[idx % N];
}
// per-iter prep: xo=0, qlin=q_b, rowsum=0
__global__ void prep_kernel(const float* __restrict__ qb, float* __restrict__ qlin,
                            float* __restrict__ xo, float* __restrict__ rowsum){
    int i = blockIdx.x*blockDim.x + threadIdx.x;
    if (i < MOUT*D_){ xo[i] = 0.f; qlin[i] = qb[i % D_]; }
    if (i < BH_*NOUT) rowsum[i] = 0.f;
}

// ---------------- rose (rotary) producing bf16 hi/lo directly ----------------
__global__ void rose_hl_kernel(const float* __restrict__ src, int stride, int off,
                               __nv_bfloat16* __restrict__ dh, __nv_bfloat16* __restrict__ dl,
                               int N, int Gw, float sp0, float sp1,
                               const float* __restrict__ fr, const float* __restrict__ temp,
                               int applyTemp){
    int idx = blockIdx.x*blockDim.x + threadIdx.x;
    int total = BH_ * N * HD_;
    if (idx >= total) return;
    int hd = idx & 31;
    int n  = (idx >> 5) % N;
    int bh = idx / (N*32);
    int h = bh % H_, b = bh / H_;
    const float* sp = src + ((size_t)b*N + n)*stride + off + h*HD_;
    float val;
    if (hd < NROT_){
        int m = hd >> 1, s = m >> 2, p = m & 3;
        float coord = (s == 0) ? (float)(n / Gw) * sp0 : (float)(n % Gw) * sp1;
        float ang = coord * fr[(h*2 + s)*4 + p];
        float cs, sn; sincosf(ang, &sn, &cs);
        float x1 = sp[2*m], x2 = sp[2*m+1];
        val = (hd & 1) ? (x1*sn + x2*cs) : (x1*cs - x2*sn);
    } else {
        val = sp[hd];
    }
    if (applyTemp) val *= temp[0];
    __nv_bfloat16 hh, ll; split1(val, hh, ll);
    dh[idx] = hh; dl[idx] = ll;
}
__global__ void vT_hl_kernel(const float* __restrict__ kv, __nv_bfloat16* __restrict__ th,
                             __nv_bfloat16* __restrict__ tl){
    int i = blockIdx.x*blockDim.x + threadIdx.x;
    if (i >= BH_*HD_*NIN) return;
    int n  = i % NIN;
    int d  = (i / NIN) % HD_;
    int bh = i / (NIN*HD_);
    int h = bh % H_, b = bh / H_;
    float v = kv[((size_t)b*NIN + n)*(2*D_) + D_ + h*HD_ + d];
    __nv_bfloat16 hh, ll; split1(v, hh, ll);
    th[i] = hh; tl[i] = ll;
}

// ================= HMMA bf16-split dense GEMM =================
#define ASTR 40

struct Frag { unsigned ah[2][4], al[2][4], bh[4][2], bl[4][2]; };

__device__ __forceinline__ void load_frags(Frag& f, const __nv_bfloat16* Ah, const __nv_bfloat16* Al,
                                           const __nv_bfloat16* Bh, const __nv_bfloat16* Bl,
                                           int wm, int wn, int ks, int g, int c2){
    #pragma unroll
    for (int t = 0; t < 2; t++){
        int rb = (wm*32 + t*16 + g)*ASTR + ks + c2;
        f.ah[t][0] = *(const unsigned*)(Ah + rb);
        f.ah[t][1] = *(const unsigned*)(Ah + rb + 8*ASTR);
        f.ah[t][2] = *(const unsigned*)(Ah + rb + 8);
        f.ah[t][3] = *(const unsigned*)(Ah + rb + 8*ASTR + 8);
        f.al[t][0] = *(const unsigned*)(Al + rb);
        f.al[t][1] = *(const unsigned*)(Al + rb + 8*ASTR);
        f.al[t][2] = *(const unsigned*)(Al + rb + 8);
        f.al[t][3] = *(const unsigned*)(Al + rb + 8*ASTR + 8);
    }
    #pragma unroll
    for (int u = 0; u < 4; u++){
        int nb = (wn*32 + u*8 + g)*ASTR + ks + c2;
        f.bh[u][0] = *(const unsigned*)(Bh + nb);
        f.bh[u][1] = *(const unsigned*)(Bh + nb + 8);
        f.bl[u][0] = *(const unsigned*)(Bl + nb);
        f.bl[u][1] = *(const unsigned*)(Bl + nb + 8);
    }
}
__device__ __forceinline__ void do_mmas(float (*acc)[4], const Frag& f){
    #pragma unroll
    for (int t = 0; t < 2; t++)
        #pragma unroll
        for (int u = 0; u < 4; u++){
            mma16816(acc[t*4+u], f.ah[t], f.bh[u]);
            mma16816(acc[t*4+u], f.ah[t], f.bl[u]);
            mma16816(acc[t*4+u], f.al[t], f.bh[u]);
        }
}
__device__ __forceinline__ void epi(float (*acc)[4], const float* __restrict__ bias,
                                    float* __restrict__ C, int M, int N, int m0, int n0,
                                    int wm, int wn, int g, int c2, int act, int atom){
    #pragma unroll
    for (int t = 0; t < 2; t++){
        int r0 = m0 + wm*32 + t*16 + g;
        #pragma unroll
        for (int u = 0; u < 4; u++){
            int cb = n0 + wn*32 + u*8 + c2;
            float* ac = acc[t*4+u];
            if (atom){
                if (r0 < M){
                    atomicAdd(&C[(size_t)r0*N + cb],     ac[0]);
                    atomicAdd(&C[(size_t)r0*N + cb + 1], ac[1]);
                }
                if (r0 + 8 < M){
                    atomicAdd(&C[(size_t)(r0+8)*N + cb],     ac[2]);
                    atomicAdd(&C[(size_t)(r0+8)*N + cb + 1], ac[3]);
                }
            } else {
                float b0 = bias[cb], b1 = bias[cb+1];
                float o0 = ac[0]+b0, o1 = ac[1]+b1, o2 = ac[2]+b0, o3 = ac[3]+b1;
                if (act){ o0=gelu_f(o0); o1=gelu_f(o1); o2=gelu_f(o2); o3=gelu_f(o3); }
                if (r0 < M){ C[(size_t)r0*N + cb] = o0; C[(size_t)r0*N + cb + 1] = o1; }
                if (r0 + 8 < M){ C[(size_t)(r0+8)*N + cb] = o2; C[(size_t)(r0+8)*N + cb + 1] = o3; }
            }
        }
    }
}
__device__ __forceinline__ void fillA(__nv_bfloat16* Ah, __nv_bfloat16* Al,
                                      const float* __restrict__ A, int M, int K,
                                      int m0, int k0, int tid){
    #pragma unroll
    for (int i = 0; i < 4; i++){
        int e = tid + i*256;
        int row = e >> 3, kg = (e & 7)*4;
        float4 v = (m0+row < M) ? *(const float4*)(A + (size_t)(m0+row)*K + k0 + kg)
                                : make_float4(0.f,0.f,0.f,0.f);
        unsigned h0,h1,l0,l1; split4(v, h0,h1,l0,l1);
        unsigned* ph = (unsigned*)&Ah[row*ASTR + kg];
        unsigned* pl = (unsigned*)&Al[row*ASTR + kg];
        ph[0]=h0; ph[1]=h1; pl[0]=l0; pl[1]=l1;
    }
}
__device__ __forceinline__ void fillB(__nv_bfloat16* Bh, __nv_bfloat16* Bl,
                                      const __nv_bfloat16* __restrict__ Wh,
                                      const __nv_bfloat16* __restrict__ Wl,
                                      size_t rowbase, int Kst, int n0, int tid){
    int n  = tid >> 2;
    int kb = (tid & 3)*8;
    const unsigned* ph = (const unsigned*)Wh + ((rowbase + (size_t)(n0+n)*Kst + kb) >> 1);
    const unsigned* pl = (const unsigned*)Wl + ((rowbase + (size_t)(n0+n)*Kst + kb) >> 1);
    unsigned* sh = (unsigned*)&Bh[n*ASTR + kb];
    unsigned* sl = (unsigned*)&Bl[n*ASTR + kb];
    #pragma unroll
    for (int j = 0; j < 4; j++){ sh[j] = ph[j]; sl[j] = pl[j]; }
}

__global__ __launch_bounds__(256, 2)
void mgemm_kernel(const float* __restrict__ A, const __nv_bfloat16* __restrict__ Wh,
                  const __nv_bfloat16* __restrict__ Wl,
                  const float* __restrict__ bias, float* __restrict__ C,
                  int M, int N, int K, int kSlice, int act, int atom){
    __shared__ __align__(16) __nv_bfloat16 Ah[128*ASTR], Al[128*ASTR];
    __shared__ __align__(16) __nv_bfloat16 Bh[64*ASTR],  Bl[64*ASTR];
    int tid = threadIdx.x, lane = tid & 31, wid = tid >> 5;
    int wm = wid >> 1, wn = wid & 1;
    int g = lane >> 2, c2 = (lane & 3)*2;
    int m0 = blockIdx.y*128, n0 = blockIdx.x*64;
    int kb0 = blockIdx.z*kSlice, kend = kb0 + kSlice;
    float acc[8][4] = {};
    for (int k0 = kb0; k0 < kend; k0 += 32){
        fillA(Ah, Al, A, M, K, m0, k0, tid);
        fillB(Bh, Bl, Wh, Wl, (size_t)k0, K, n0, tid);
        __syncthreads();
        #pragma unroll
        for (int ks = 0; ks < 32; ks += 16){
            Frag f;
            load_frags(f, Ah, Al, Bh, Bl, wm, wn, ks, g, c2);
            do_mmas(acc, f);
        }
        __syncthreads();
    }
    epi(acc, bias, C, M, N, m0, n0, wm, wn, g, c2, act, atom);
}

// A pre-split variant (for kv GEMM on x)
__global__ __launch_bounds__(256, 2)
void mgemm_pre_kernel(const __nv_bfloat16* __restrict__ Xh, const __nv_bfloat16* __restrict__ Xl,
                      const __nv_bfloat16* __restrict__ Wh, const __nv_bfloat16* __restrict__ Wl,
                      const float* __restrict__ bias, float* __restrict__ C,
                      int M, int N, int K){
    __shared__ __align__(16) __nv_bfloat16 Ah[128*ASTR], Al[128*ASTR];
    __shared__ __align__(16) __nv_bfloat16 Bh[64*ASTR],  Bl[64*ASTR];
    int tid = threadIdx.x, lane = tid & 31, wid = tid >> 5;
    int wm = wid >> 1, wn = wid & 1;
    int g = lane >> 2, c2 = (lane & 3)*2;
    int m0 = blockIdx.y*128, n0 = blockIdx.x*64;
    float acc[8][4] = {};
    for (int k0 = 0; k0 < K; k0 += 32){
        #pragma unroll
        for (int i = 0; i < 4; i++){
            int e = tid + i*256;
            int row = e >> 3, kg = (e & 7)*4;
            size_t off = (size_t)(m0+row)*K + k0 + kg;
            uint2 h = make_uint2(0u,0u), l = h;
            if (m0+row < M){
                h = *(const uint2*)(Xh + off);
                l = *(const uint2*)(Xl + off);
            }
            *(uint2*)&Ah[row*ASTR + kg] = h;
            *(uint2*)&Al[row*ASTR + kg] = l;
        }
        fillB(Bh, Bl, Wh, Wl, (size_t)k0, K, n0, tid);
        __syncthreads();
        #pragma unroll
        for (int ks = 0; ks < 32; ks += 16){
            Frag f;
            load_frags(f, Ah, Al, Bh, Bl, wm, wn, ks, g, c2);
            do_mmas(acc, f);
        }
        __syncthreads();
    }
    epi(acc, bias, C, M, N, m0, n0, wm, wn, g, c2, 0, 0);
}

// conv implicit GEMM with pre-split x; grid.z = 7 kh-slices, atomic epilogue
__global__ __launch_bounds__(256, 2)
void mconv_kernel(const __nv_bfloat16* __restrict__ Xh, const __nv_bfloat16* __restrict__ Xl,
                  const __nv_bfloat16* __restrict__ Wh, const __nv_bfloat16* __restrict__ Wl,
                  float* __restrict__ C){
    __shared__ __align__(16) __nv_bfloat16 Ah[128*ASTR], Al[128*ASTR];
    __shared__ __align__(16) __nv_bfloat16 Bh[64*ASTR],  Bl[64*ASTR];
    int tid = threadIdx.x, lane = tid & 31, wid = tid >> 5;
    int wm = wid >> 1, wn = wid & 1;
    int g = lane >> 2, c2 = (lane & 3)*2;
    int m0 = blockIdx.y*128, n0 = blockIdx.x*64;
    int slice = blockIdx.z;
    float acc[8][4] = {};
    for (int kc = 0; kc < 7*D_; kc += 32){
        int khw = slice*7 + kc/D_;
        int cib = kc % D_;
        int kh = khw/7, kw = khw%7;
        #pragma unroll
        for (int i = 0; i < 4; i++){
            int e = tid + i*256;
            int row = e >> 3, kg = (e & 7)*4;
            int m = m0 + row;
            uint2 h = make_uint2(0u,0u), l = h;
            if (m < MOUT){
                int bb = m / NOUT, rr = m % NOUT;
                int oh = rr / QG, ow = rr % QG;
                int ih = oh*3 - 3 + kh, iw = ow*3 - 3 + kw;
                if ((unsigned)ih < 64u && (unsigned)iw < 64u){
                    size_t off = ((size_t)(bb*NIN + ih*GW_ + iw))*D_ + cib + kg;
                    h = *(const uint2*)(Xh + off);
                    l = *(const uint2*)(Xl + off);
                }
            }
            *(uint2*)&Ah[row*ASTR + kg] = h;
            *(uint2*)&Al[row*ASTR + kg] = l;
        }
        fillB(Bh, Bl, Wh, Wl, (size_t)(khw*D_ + cib), CKK, n0, tid);
        __syncthreads();
        #pragma unroll
        for (int ks = 0; ks < 32; ks += 16){
            Frag f;
            load_frags(f, Ah, Al, Bh, Bl, wm, wn, ks, g, c2);
            do_mmas(acc, f);
        }
        __syncthreads();
    }
    epi(acc, (const float*)0, C, MOUT, D_, m0, n0, wm, wn, g, c2, 0, 1);
}

// ---------------- one-pass layernorm over D=384, optional residual-add -------------
__global__ void ln_kernel(const float* __restrict__ X, const float* __restrict__ g,
                          const float* __restrict__ bt, float* __restrict__ out, int add){
    int row = blockIdx.x, tid = threadIdx.x;
    float x = X[(size_t)row*D_ + tid];
    __shared__ float w1s[12], w2s[12];
    float s1 = x, s2 = x*x;
    #pragma unroll
    for (int o = 16; o > 0; o >>= 1){
        s1 += __shfl_down_sync(0xffffffffu, s1, o);
        s2 += __shfl_down_sync(0xffffffffu, s2, o);
    }
    if ((tid & 31) == 0){ w1s[tid >> 5] = s1; w2s[tid >> 5] = s2; }
    __syncthreads();
    if (tid == 0){
        float t1 = 0.f, t2 = 0.f;
        #pragma unroll
        for (int i = 0; i < 12; i++){ t1 += w1s[i]; t2 += w2s[i]; }
        w1s[0] = t1; w2s[0] = t2;
    }
    __syncthreads();
    float mu  = w1s[0] * (1.0f/D_);
    float var = w2s[0] * (1.0f/D_) - mu*mu;
    float y = (x - mu) * rsqrtf(var + LNEPS) * g[tid] + bt[tid];
    size_t o_ = (size_t)row*D_ + tid;
    out[o_] = add ? (out[o_] + y) : y;
}

// ======== HMMA scores: E = exp(Q K^T); store d = E-1 as fp16; fused row-sum ========
__global__ __launch_bounds__(256)
void mscore_kernel(const __nv_bfloat16* __restrict__ Qh, const __nv_bfloat16* __restrict__ Ql,
                   const __nv_bfloat16* __restrict__ Kh, const __nv_bfloat16* __restrict__ Kl,
                   __half* __restrict__ Eh, float* __restrict__ rowsum){
    __shared__ __align__(16) __nv_bfloat16 Qhs[64*ASTR], Qls[64*ASTR];
    __shared__ __align__(16) __nv_bfloat16 Khs[128*ASTR], Kls[128*ASTR];
    __shared__ float rs[64];
    int tid = threadIdx.x, lane = tid & 31, wid = tid >> 5;
    int wq = wid >> 2, wk = wid & 3;
    int g = lane >> 2, c2 = (lane & 3)*2;
    int kt = blockIdx.x*128, q0 = blockIdx.y*64, bh = blockIdx.z;
    if (tid < 64) rs[tid] = 0.f;
    {
        int row = tid >> 2, kb = (tid & 3)*8;
        unsigned* sh = (unsigned*)&Qhs[row*ASTR + kb];
        unsigned* sl = (unsigned*)&Qls[row*ASTR + kb];
        if (q0 + row < NOUT){
            size_t e32 = ((size_t)(bh*NOUT + q0 + row)*HD_ + kb) >> 1;
            const unsigned* ph = (const unsigned*)Qh + e32;
            const unsigned* pl = (const unsigned*)Ql + e32;
            #pragma unroll
            for (int j = 0; j < 4; j++){ sh[j] = ph[j]; sl[j] = pl[j]; }
        } else {
            #pragma unroll
            for (int j = 0; j < 4; j++){ sh[j] = 0u; sl[j] = 0u; }
        }
    }
    {
        int row = tid >> 1, kb = (tid & 1)*16;
        size_t e32 = ((size_t)(bh*NIN + kt + row)*HD_ + kb) >> 1;
        const unsigned* ph = (const unsigned*)Kh + e32;
        const unsigned* pl = (const unsigned*)Kl + e32;
        unsigned* sh = (unsigned*)&Khs[row*ASTR + kb];
        unsigned* sl = (unsigned*)&Kls[row*ASTR + kb];
        #pragma unroll
        for (int j = 0; j < 8; j++){ sh[j] = ph[j]; sl[j] = pl[j]; }
    }
    __syncthreads();
    float acc[2][4][4] = {};
    #pragma unroll
    for (int ks = 0; ks < 32; ks += 16){
        unsigned ah[2][4], al[2][4], bhf[4][2], blf[4][2];
        #pragma unroll
        for (int t = 0; t < 2; t++){
            int rb = (wq*32 + t*16 + g)*ASTR + ks + c2;
            ah[t][0] = *(const unsigned*)(Qhs + rb);
            ah[t][1] = *(const unsigned*)(Qhs + rb + 8*ASTR);
            ah[t][2] = *(const unsigned*)(Qhs + rb + 8);
            ah[t][3] = *(const unsigned*)(Qhs + rb + 8*ASTR + 8);
            al[t][0] = *(const unsigned*)(Qls + rb);
            al[t][1] = *(const unsigned*)(Qls + rb + 8*ASTR);
            al[t][2] = *(const unsigned*)(Qls + rb + 8);
            al[t][3] = *(const unsigned*)(Qls + rb + 8*ASTR + 8);
        }
        #pragma unroll
        for (int u = 0; u < 4; u++){
            int nb = (wk*32 + u*8 + g)*ASTR + ks + c2;
            bhf[u][0] = *(const unsigned*)(Khs + nb);
            bhf[u][1] = *(const unsigned*)(Khs + nb + 8);
            blf[u][0] = *(const unsigned*)(Kls + nb);
            blf[u][1] = *(const unsigned*)(Kls + nb + 8);
        }
        #pragma unroll
        for (int t = 0; t < 2; t++)
            #pragma unroll
            for (int u = 0; u < 4; u++){
                mma16816(acc[t][u], ah[t], bhf[u]);
                mma16816(acc[t][u], ah[t], blf[u]);
                mma16816(acc[t][u], al[t], bhf[u]);
            }
    }
    #pragma unroll
    for (int t = 0; t < 2; t++){
        int lr = wq*32 + t*16 + g;
        int r  = q0 + lr;
        float s0 = 0.f, s1 = 0.f;
        #pragma unroll
        for (int u = 0; u < 4; u++){
            int col = kt + wk*32 + u*8 + c2;
            float e0 = exp_fast(acc[t][u][0]), e1 = exp_fast(acc[t][u][1]);
            float e2 = exp_fast(acc[t][u][2]), e3 = exp_fast(acc[t][u][3]);
            // store d = E-1 (exact near 1; fp16 gives ~1e-4 abs precision)
            __half2 v0 = __floats2half2_rn(e0 - 1.0f, e1 - 1.0f);
            __half2 v1 = __floats2half2_rn(e2 - 1.0f, e3 - 1.0f);
            if (r < NOUT)
                *(__half2*)(Eh + (size_t)(bh*NOUT + r)*NIN + col) = v0;
            if (r + 8 < NOUT)
                *(__half2*)(Eh + (size_t)(bh*NOUT + r + 8)*NIN + col) = v1;
            s0 += e0 + e1; s1 += e2 + e3;
        }
        s0 += __shfl_xor_sync(0xffffffffu, s0, 1);
        s0 += __shfl_xor_sync(0xffffffffu, s0, 2);
        s1 += __shfl_xor_sync(0xffffffffu, s1, 1);
        s1 += __shfl_xor_sync(0xffffffffu, s1, 2);
        if ((lane & 3) == 0){
            atomicAdd(&rs[lr], s0);
            atomicAdd(&rs[lr + 8], s1);
        }
    }
    __syncthreads();
    if (tid < 64 && q0 + tid < NOUT)
        atomicAdd(rowsum + bh*NOUT + q0 + tid, rs[tid]);
}

__global__ void rowinv_kernel(float* __restrict__ rowsum){
    int i = blockIdx.x*blockDim.x + threadIdx.x;
    if (i < BH_*NOUT) rowsum[i] = 1.f / rowsum[i];
}

__global__ void colsum_kernel(const __half* __restrict__ Eh, const float* __restrict__ rinv,
                              float* __restrict__ colinv){
    int bh = blockIdx.y;
    int col = blockIdx.x*256 + threadIdx.x;
    const __half* a = Eh + (size_t)bh*NOUT*NIN + col;
    const float* ri = rinv + bh*NOUT;
    float s = 0.f;
    #pragma unroll 4
    for (int qi = 0; qi < NOUT; qi++)
        s += (1.0f + __half2float(a[(size_t)qi*NIN])) * __ldg(ri + qi);
    colinv[bh*NIN + col] = 1.f / (s + EPSV);
}

// ======== HMMA PV: upd += (E*rinv*colinv) @ V, split-K=4, atomic epilogue ========
// writeout: also emit attn_k = E*rinv and attn_q = E*rinv*colinv (fp32) on last iter.
#define PSTR 72
__global__ __launch_bounds__(256)
void mpv_kernel(const __half* __restrict__ Eh,
                const float* __restrict__ rinv, const float* __restrict__ colinv,
                const __nv_bfloat16* __restrict__ Vth, const __nv_bfloat16* __restrict__ Vtl,
                float* __restrict__ out, float* __restrict__ outk, float* __restrict__ outq,
                int writeout){
    __shared__ __align__(16) __nv_bfloat16 Ahs[64*PSTR], Als[64*PSTR];
    __shared__ __align__(16) __nv_bfloat16 Vhs[32*PSTR], Vls[32*PSTR];
    int tid = threadIdx.x, lane = tid & 31, wid = tid >> 5;
    int wq = wid >> 1, wd = wid & 1;
    int g = lane >> 2, c2 = (lane & 3)*2;
    int q0 = blockIdx.x*64, bh = blockIdx.y;
    int ks0 = blockIdx.z*1024;
    float acc[2][4] = {};
    int frow = tid >> 4, fcol = (tid & 15)*4;
    float rv[4];
    #pragma unroll
    for (int i = 0; i < 4; i++){
        int r = q0 + frow + i*16;
        rv[i] = (r < NOUT) ? rinv[bh*NOUT + r] : 0.f;
    }
    for (int c = 0; c < 16; c++){
        int k0 = ks0 + c*64;
        #pragma unroll
        for (int i = 0; i < 4; i++){
            int row = frow + i*16;
            int r = q0 + row;
            float4 e = make_float4(0.f,0.f,0.f,0.f);
            size_t base = (size_t)(bh*NOUT + (r < NOUT ? r : 0))*NIN + k0 + fcol;
            if (r < NOUT){
                uint2 u = *(const uint2*)(Eh + base);
                float2 f0 = __half22float2(*(__half2*)&u.x);
                float2 f1 = __half22float2(*(__half2*)&u.y);
                e = make_float4(1.0f + f0.x, 1.0f + f0.y, 1.0f + f1.x, 1.0f + f1.y);
            }
            float4 cv = *(const float4*)(colinv + bh*NIN + k0 + fcol);
            float4 a;
            a.x = e.x*rv[i]*cv.x; a.y = e.y*rv[i]*cv.y;
            a.z = e.z*rv[i]*cv.z; a.w = e.w*rv[i]*cv.w;
            if (writeout && r < NOUT){
                float4 ak;
                ak.x = e.x*rv[i]; ak.y = e.y*rv[i];
                ak.z = e.z*rv[i]; ak.w = e.w*rv[i];
                *(float4*)(outk + base) = ak;
                *(float4*)(outq + base) = a;
            }
            unsigned h0,h1,l0,l1; split4(a, h0,h1,l0,l1);
            unsigned* ph = (unsigned*)&Ahs[row*PSTR + fcol];
            unsigned* pl = (unsigned*)&Als[row*PSTR + fcol];
            ph[0]=h0; ph[1]=h1; pl[0]=l0; pl[1]=l1;
        }
        {
            int d = tid >> 3, kb = (tid & 7)*8;
            size_t e32 = ((size_t)(bh*HD_ + d)*NIN + k0 + kb) >> 1;
            const unsigned* ph = (const unsigned*)Vth + e32;
            const unsigned* pl = (const unsigned*)Vtl + e32;
            unsigned* sh = (unsigned*)&Vhs[d*PSTR + kb];
            unsigned* sl = (unsigned*)&Vls[d*PSTR + kb];
            #pragma unroll
            for (int j = 0; j < 4; j++){ sh[j] = ph[j]; sl[j] = pl[j]; }
        }
        __syncthreads();
        #pragma unroll
        for (int ks = 0; ks < 64; ks += 16){
            unsigned a_h[4], a_l[4];
            int rb = (wq*16 + g)*PSTR + ks + c2;
            a_h[0] = *(const unsigned*)(Ahs + rb);
            a_h[1] = *(const unsigned*)(Ahs + rb + 8*PSTR);
            a_h[2] = *(const unsigned*)(Ahs + rb + 8);
            a_h[3] = *(const unsigned*)(Ahs + rb + 8*PSTR + 8);
            a_l[0] = *(const unsigned*)(Als + rb);
            a_l[1] = *(const unsigned*)(Als + rb + 8*PSTR);
            a_l[2] = *(const unsigned*)(Als + rb + 8);
            a_l[3] = *(const unsigned*)(Als + rb + 8*PSTR + 8);
            #pragma unroll
            for (int u = 0; u < 2; u++){
                unsigned b_h[2], b_l[2];
                int nb = (wd*16 + u*8 + g)*PSTR + ks + c2;
                b_h[0] = *(const unsigned*)(Vhs + nb);
                b_h[1] = *(const unsigned*)(Vhs + nb + 8);
                b_l[0] = *(const unsigned*)(Vls + nb);
                b_l[1] = *(const unsigned*)(Vls + nb + 8);
                mma16816(acc[u], a_h, b_h);
                mma16816(acc[u], a_h, b_l);
                mma16816(acc[u], a_l, b_h);
            }
        }
        __syncthreads();
    }
    int b = bh / H_, h = bh % H_;
    int r0 = q0 + wq*16 + g;
    #pragma unroll
    for (int u = 0; u < 2; u++){
        int col = h*HD_ + wd*16 + u*8 + c2;
        if (r0 < NOUT){
            atomicAdd(out + (size_t)(b*NOUT + r0)*D_ + col,     acc[u][0]);
            atomicAdd(out + (size_t)(b*NOUT + r0)*D_ + col + 1, acc[u][1]);
        }
        if (r0 + 8 < NOUT){
            atomicAdd(out + (size_t)(b*NOUT + r0 + 8)*D_ + col,     acc[u][2]);
            atomicAdd(out + (size_t)(b*NOUT + r0 + 8)*D_ + col + 1, acc[u][3]);
        }
    }
}

// ---------------- host orchestration ----------------------------------------------
extern "C" void kernel_launch(void* const* d_in, const int* in_sizes, int n_in,
                              void* d_out, int out_size){
    const float* x      = (const float*)d_in[0];
    const float* conv_w = (const float*)d_in[1];
    const float* conv_b = (const float*)d_in[2];
    const float* kv_w   = (const float*)d_in[3];
    const float* kv_b   = (const float*)d_in[4];
    const float* q_w    = (const float*)d_in[5];
    const float* q_b    = (const float*)d_in[6];
    const float* w1     = (const float*)d_in[7];
    const float* b1m    = (const float*)d_in[8];
    const float* w2     = (const float*)d_in[9];
    const float* b2m    = (const float*)d_in[10];
    const float* g1     = (const float*)d_in[11];
    const float* b1_    = (const float*)d_in[12];
    const float* g2     = (const float*)d_in[13];
    const float* b2_    = (const float*)d_in[14];
    const float* g3     = (const float*)d_in[15];
    const float* b3_    = (const float*)d_in[16];
    const float* temp   = (const float*)d_in[17];
    const float* freqs  = (const float*)d_in[18];

    __nv_bfloat16 *cwh,*cwl,*kvwh,*kvwl,*qwh,*qwl,*w1h,*w1l,*w2h,*w2l;
    __nv_bfloat16 *xh,*xl,*kh,*kl,*vth,*vtl,*qh,*ql;
    float *xo,*xoutg,*kv,*qlin,*attn_s,*rowsum,*colinv,*h1;
    cudaGetSymbolAddress((void**)&cwh,  g_cwh);  cudaGetSymbolAddress((void**)&cwl,  g_cwl);
    cudaGetSymbolAddress((void**)&kvwh, g_kvwh); cudaGetSymbolAddress((void**)&kvwl, g_kvwl);
    cudaGetSymbolAddress((void**)&qwh,  g_qwh);  cudaGetSymbolAddress((void**)&qwl,  g_qwl);
    cudaGetSymbolAddress((void**)&w1h,  g_w1h);  cudaGetSymbolAddress((void**)&w1l,  g_w1l);
    cudaGetSymbolAddress((void**)&w2h,  g_w2h);  cudaGetSymbolAddress((void**)&w2l,  g_w2l);
    cudaGetSymbolAddress((void**)&xh,   g_xh);   cudaGetSymbolAddress((void**)&xl,   g_xl);
    cudaGetSymbolAddress((void**)&kh,   g_kh);   cudaGetSymbolAddress((void**)&kl,   g_kl);
    cudaGetSymbolAddress((void**)&vth,  g_vth);  cudaGetSymbolAddress((void**)&vtl,  g_vtl);
    cudaGetSymbolAddress((void**)&qh,   g_qh);   cudaGetSymbolAddress((void**)&ql,   g_ql);
    cudaGetSymbolAddress((void**)&xo,     g_xo);
    cudaGetSymbolAddress((void**)&xoutg,  g_xout);
    cudaGetSymbolAddress((void**)&kv,     g_kv);
    cudaGetSymbolAddress((void**)&qlin,   g_qlin);
    cudaGetSymbolAddress((void**)&attn_s, g_attn);
    cudaGetSymbolAddress((void**)&rowsum, g_rowsum);
    cudaGetSymbolAddress((void**)&colinv, g_colinv);
    cudaGetSymbolAddress((void**)&h1,     g_h1);

    float* out = (float*)d_out;
    bool full = (size_t)out_size >= (size_t)XOUT_SZ + 2*ATTN_SZ;
    float* xout      = full ? out : xoutg;                       // x_out in place
    float* out_attnq = full ? out + XOUT_SZ : attn_s;
    float* out_attnk = full ? out + XOUT_SZ + ATTN_SZ : attn_s;
    __half* Eh       = (__half*)attn_s;                          // fp16 (E-1), all iters

    // ---- prologue: pack weights + pre-split x ----
    packconvT_kernel<<<(D_*CKK + 255)/256, 256>>>(conv_w, cwh, cwl);
    packT_kernel<<<(D_*2*D_ + 255)/256, 256>>>(kv_w, kvwh, kvwl, D_, 2*D_);
    packT_kernel<<<(D_*D_ + 255)/256, 256>>>(q_w, qwh, qwl, D_, D_);
    packT_kernel<<<(D_*4*D_ + 255)/256, 256>>>(w1, w1h, w1l, D_, 4*D_);
    packT_kernel<<<(4*D_*D_ + 255)/256, 256>>>(w2, w2h, w2l, 4*D_, D_);
    splitf_kernel<<<(MIN_*D_ + 255)/256, 256>>>(x, xh, xl, MIN_*D_);

    // ---- conv + first LN ----
    seed_kernel<<<(MOUT*D_ + 255)/256, 256>>>(conv_b, xo, MOUT, D_);
    mconv_kernel<<<dim3(D_/64, (MOUT+127)/128, 7), 256>>>(xh, xl, cwh, cwl, xo);
    ln_kernel<<<MOUT, D_>>>(xo, g1, b1_, xout, 0);

    // ---- kv (loop-invariant) + rose-split ----
    mgemm_pre_kernel<<<dim3(2*D_/64, MIN_/128), 256>>>(xh, xl, kvwh, kvwl, kv_b, kv, MIN_, 2*D_, D_);
    int totk = BH_*NIN*HD_;
    rose_hl_kernel<<<(totk+255)/256, 256>>>(kv, 2*D_, 0, kh, kl, NIN, GW_, 1.f, 1.f, freqs, temp, 1);
    vT_hl_kernel<<<(totk+255)/256, 256>>>(kv, vth, vtl);

    int totq = BH_*NOUT*HD_;
    for (int it = 0; it < 3; it++){
        int writeout = (it == 2 && full) ? 1 : 0;
        prep_kernel<<<(MOUT*D_ + 255)/256, 256>>>(q_b, qlin, xo, rowsum);
        mgemm_kernel<<<dim3(D_/64, (MOUT+127)/128, 2), 256>>>(xout, qwh, qwl, q_b, qlin, MOUT, D_, D_, D_/2, 0, 1);
        rose_hl_kernel<<<(totq+255)/256, 256>>>(qlin, D_, 0, qh, ql, NOUT, QG, 3.f, 3.f, freqs, temp, 0);

        mscore_kernel<<<dim3(NIN/128, (NOUT+63)/64, BH_), 256>>>(qh, ql, kh, kl, Eh, rowsum);
        rowinv_kernel<<<(BH_*NOUT + 255)/256, 256>>>(rowsum);
        colsum_kernel<<<dim3(NIN/256, BH_), 256>>>(Eh, rowsum, colinv);
        mpv_kernel<<<dim3((NOUT+63)/64, BH_, 4), 256>>>(Eh, rowsum, colinv, vth, vtl,
                                                        xo, out_attnk, out_attnq, writeout);
        ln_kernel<<<MOUT, D_>>>(xo, g2, b2_, xout, 1);

        mgemm_kernel<<<dim3(4*D_/64, (MOUT+127)/128, 1), 256>>>(xout, w1h, w1l, b1m, h1, MOUT, 4*D_, D_, D_, 1, 0);
        seed_kernel<<<(MOUT*D_ + 255)/256, 256>>>(b2m, xo, MOUT, D_);
        mgemm_kernel<<<dim3(D_/64, (MOUT+127)/128, 2), 256>>>(h1, w2h, w2l, b2m, xo, MOUT, D_, 4*D_, 2*D_, 0, 1);
        ln_kernel<<<MOUT, D_>>>(xo, g3, b3_, xout, 1);
    }
}